// round 1
// baseline (speedup 1.0000x reference)
#include <cuda_runtime.h>
#include <math.h>
#include <stdint.h>

#define B_    2
#define S_    2048
#define E_    2048
#define H_    16
#define D_    128
#define HALF_ 64
#define MTOT  (B_ * S_)          // 4096
#define N_QKV (3 * E_)           // 6144

// Scratch (allocation-free contract: __device__ globals)
__device__ float g_qkv[(size_t)B_ * S_ * 3 * E_];   // [B,S,3,H,D] = 25,165,824 floats
__device__ float g_ctx[(size_t)B_ * S_ * E_];       // [B,S,H,D]   =  8,388,608 floats

// ---------------------------------------------------------------------------
// GEMM (NT): C[M,N] = A[M,K] @ W[N,K]^T + bias[N]
// 128x128 block tile, BK=16, 256 threads, 8x8 per thread, fp32.
// M, N multiples of 128; K multiple of 16 (true for all our shapes).
// ---------------------------------------------------------------------------
__global__ void __launch_bounds__(256) gemm_nt_bias(
    const float* __restrict__ A, const float* __restrict__ W,
    const float* __restrict__ bias, float* __restrict__ C,
    int N, int K)
{
    __shared__ float As[16][128];
    __shared__ float Bs[16][128];

    const int tid = threadIdx.x;
    const int tx  = tid & 15;
    const int ty  = tid >> 4;
    const int rowBlk = blockIdx.y * 128;
    const int colBlk = blockIdx.x * 128;

    const int lr = tid >> 2;   // 0..63
    const int lk = tid & 3;    // 0..3 -> k offset lk*4

    float acc[8][8];
#pragma unroll
    for (int i = 0; i < 8; ++i)
#pragma unroll
        for (int j = 0; j < 8; ++j) acc[i][j] = 0.0f;

    for (int k0 = 0; k0 < K; k0 += 16) {
#pragma unroll
        for (int l = 0; l < 2; ++l) {
            const int r = lr + l * 64;
            const float4 va = *reinterpret_cast<const float4*>(
                A + (size_t)(rowBlk + r) * K + k0 + lk * 4);
            As[lk * 4 + 0][r] = va.x;
            As[lk * 4 + 1][r] = va.y;
            As[lk * 4 + 2][r] = va.z;
            As[lk * 4 + 3][r] = va.w;
            const float4 vw = *reinterpret_cast<const float4*>(
                W + (size_t)(colBlk + r) * K + k0 + lk * 4);
            Bs[lk * 4 + 0][r] = vw.x;
            Bs[lk * 4 + 1][r] = vw.y;
            Bs[lk * 4 + 2][r] = vw.z;
            Bs[lk * 4 + 3][r] = vw.w;
        }
        __syncthreads();

#pragma unroll
        for (int k = 0; k < 16; ++k) {
            float a[8], b[8];
            *reinterpret_cast<float4*>(&a[0]) = *reinterpret_cast<const float4*>(&As[k][ty * 8]);
            *reinterpret_cast<float4*>(&a[4]) = *reinterpret_cast<const float4*>(&As[k][ty * 8 + 4]);
            *reinterpret_cast<float4*>(&b[0]) = *reinterpret_cast<const float4*>(&Bs[k][tx * 8]);
            *reinterpret_cast<float4*>(&b[4]) = *reinterpret_cast<const float4*>(&Bs[k][tx * 8 + 4]);
#pragma unroll
            for (int i = 0; i < 8; ++i)
#pragma unroll
                for (int j = 0; j < 8; ++j)
                    acc[i][j] += a[i] * b[j];
        }
        __syncthreads();
    }

#pragma unroll
    for (int i = 0; i < 8; ++i) {
        const int row = rowBlk + ty * 8 + i;
#pragma unroll
        for (int j = 0; j < 8; j += 4) {
            const int col = colBlk + tx * 8 + j;
            float4 o;
            o.x = acc[i][j + 0] + bias[col + 0];
            o.y = acc[i][j + 1] + bias[col + 1];
            o.z = acc[i][j + 2] + bias[col + 2];
            o.w = acc[i][j + 3] + bias[col + 3];
            *reinterpret_cast<float4*>(C + (size_t)row * N + col) = o;
        }
    }
}

// ---------------------------------------------------------------------------
// Rotary: in-place on qkv [B,S,3,H,D] for components q(0), k(1).
// One thread per (b,s,h,dhalf).
// ---------------------------------------------------------------------------
__global__ void __launch_bounds__(256) rotary_kernel(float* __restrict__ qkv)
{
    const int idx = blockIdx.x * blockDim.x + threadIdx.x;
    const int total = B_ * S_ * H_ * HALF_;
    if (idx >= total) return;

    const int dh = idx & (HALF_ - 1);
    const int h  = (idx >> 6) & (H_ - 1);
    const int s  = (idx >> 10) & (S_ - 1);
    const int b  = idx >> 21;

    // phase in fp64, trig in fp32 (sincosf is accurate w/ range reduction)
    const double inv = exp(-(double)dh * (log(10000.0) / 64.0));
    const float  f   = (float)((double)s * inv);
    float c, sn;
    sincosf(f, &sn, &c);

#pragma unroll
    for (int comp = 0; comp < 2; ++comp) {
        const size_t base = (((size_t)(b * S_ + s) * 3 + comp) * H_ + h) * (size_t)D_;
        const float x1 = qkv[base + dh];
        const float x2 = qkv[base + dh + HALF_];
        qkv[base + dh]         = x1 * c - x2 * sn;
        qkv[base + dh + HALF_] = x2 * c + x1 * sn;
    }
}

// ---------------------------------------------------------------------------
// Flash attention (fp32, causal): block = (q-tile 64 rows, one b*h).
// 256 threads = 16x16. Each thread: 4 score rows, score cols tx+16j,
// output cols tx+16j (j<8). Online softmax. Causal tiles skipped.
// ---------------------------------------------------------------------------
#define KS_STRIDE 132   // padded to kill LDS bank conflicts on K reads
#define PS_STRIDE 66

#define SMEM_FLOATS (64 * 128 + 64 * KS_STRIDE + 64 * 128 + 64 * PS_STRIDE)
#define SMEM_BYTES  (SMEM_FLOATS * 4)

__global__ void __launch_bounds__(256) flash_attn_kernel(
    const float* __restrict__ qkv, float* __restrict__ ctx)
{
    extern __shared__ float smem[];
    float* Qs = smem;                       // [64][128]
    float* Ks = Qs + 64 * 128;              // [64][KS_STRIDE]
    float* Vs = Ks + 64 * KS_STRIDE;        // [64][128]
    float* Ps = Vs + 64 * 128;              // [64][PS_STRIDE]

    const int qt = blockIdx.x;              // 0..31
    const int bh = blockIdx.y;              // 0..31
    const int b  = bh >> 4;
    const int h  = bh & 15;
    const int tid = threadIdx.x;
    const int tx  = tid & 15;
    const int ty  = tid >> 4;

    // Load Q tile (64x128)
#pragma unroll
    for (int l = 0; l < 8; ++l) {
        const int idx = tid + l * 256;      // over 2048 float4s
        const int r   = idx >> 5;
        const int d4  = idx & 31;
        const int sq  = (qt << 6) + r;
        const float4 v = *reinterpret_cast<const float4*>(
            qkv + ((size_t)(b * S_ + sq) * 3 + 0) * E_ + h * D_ + d4 * 4);
        *reinterpret_cast<float4*>(Qs + r * 128 + d4 * 4) = v;
    }

    float m_i[4], l_i[4], O[4][8];
#pragma unroll
    for (int i = 0; i < 4; ++i) {
        m_i[i] = -1e30f;
        l_i[i] = 0.0f;
#pragma unroll
        for (int j = 0; j < 8; ++j) O[i][j] = 0.0f;
    }

    const float scale = 0.08838834764831843f;  // 1/sqrt(128)

    for (int kt = 0; kt <= qt; ++kt) {
        __syncthreads();   // Q visible (1st iter); Ks/Vs/Ps reuse safe (later iters)

        // Load K and V tiles
#pragma unroll
        for (int l = 0; l < 8; ++l) {
            const int idx = tid + l * 256;
            const int r   = idx >> 5;
            const int d4  = idx & 31;
            const int sk  = (kt << 6) + r;
            const float4 kv4 = *reinterpret_cast<const float4*>(
                qkv + ((size_t)(b * S_ + sk) * 3 + 1) * E_ + h * D_ + d4 * 4);
            *reinterpret_cast<float4*>(Ks + r * KS_STRIDE + d4 * 4) = kv4;
            const float4 vv4 = *reinterpret_cast<const float4*>(
                qkv + ((size_t)(b * S_ + sk) * 3 + 2) * E_ + h * D_ + d4 * 4);
            *reinterpret_cast<float4*>(Vs + r * 128 + d4 * 4) = vv4;
        }
        __syncthreads();

        // S = Q K^T  (4 rows x 4 cols per thread; cols = tx + 16j)
        float sacc[4][4];
#pragma unroll
        for (int i = 0; i < 4; ++i)
#pragma unroll
            for (int j = 0; j < 4; ++j) sacc[i][j] = 0.0f;

#pragma unroll 8
        for (int k4 = 0; k4 < 32; ++k4) {
            float4 qv[4], kv[4];
#pragma unroll
            for (int i = 0; i < 4; ++i)
                qv[i] = *reinterpret_cast<const float4*>(Qs + (ty * 4 + i) * 128 + k4 * 4);
#pragma unroll
            for (int j = 0; j < 4; ++j)
                kv[j] = *reinterpret_cast<const float4*>(Ks + (tx + 16 * j) * KS_STRIDE + k4 * 4);
#pragma unroll
            for (int i = 0; i < 4; ++i)
#pragma unroll
                for (int j = 0; j < 4; ++j)
                    sacc[i][j] += qv[i].x * kv[j].x + qv[i].y * kv[j].y +
                                  qv[i].z * kv[j].z + qv[i].w * kv[j].w;
        }

        // scale + causal mask (diagonal tile only) + online softmax update
#pragma unroll
        for (int i = 0; i < 4; ++i) {
            const int qg = (qt << 6) + ty * 4 + i;
#pragma unroll
            for (int j = 0; j < 4; ++j) {
                float s = sacc[i][j] * scale;
                if (kt == qt) {
                    const int kg = (kt << 6) + tx + 16 * j;
                    if (kg > qg) s = -1e30f;
                }
                sacc[i][j] = s;
            }
            float rm = fmaxf(fmaxf(sacc[i][0], sacc[i][1]), fmaxf(sacc[i][2], sacc[i][3]));
            rm = fmaxf(rm, __shfl_xor_sync(0xffffffffu, rm, 8));
            rm = fmaxf(rm, __shfl_xor_sync(0xffffffffu, rm, 4));
            rm = fmaxf(rm, __shfl_xor_sync(0xffffffffu, rm, 2));
            rm = fmaxf(rm, __shfl_xor_sync(0xffffffffu, rm, 1));

            const float mn    = fmaxf(m_i[i], rm);
            const float alpha = __expf(m_i[i] - mn);
            float rsum = 0.0f;
#pragma unroll
            for (int j = 0; j < 4; ++j) {
                const float p = __expf(sacc[i][j] - mn);
                rsum += p;
                Ps[(ty * 4 + i) * PS_STRIDE + tx + 16 * j] = p;
            }
            rsum += __shfl_xor_sync(0xffffffffu, rsum, 8);
            rsum += __shfl_xor_sync(0xffffffffu, rsum, 4);
            rsum += __shfl_xor_sync(0xffffffffu, rsum, 2);
            rsum += __shfl_xor_sync(0xffffffffu, rsum, 1);

            l_i[i] = l_i[i] * alpha + rsum;
            m_i[i] = mn;
#pragma unroll
            for (int j = 0; j < 8; ++j) O[i][j] *= alpha;
        }
        __syncthreads();

        // O += P V   (output cols = tx + 16j)
#pragma unroll 4
        for (int kk = 0; kk < 64; ++kk) {
            float vv[8];
#pragma unroll
            for (int j = 0; j < 8; ++j) vv[j] = Vs[kk * 128 + tx + 16 * j];
#pragma unroll
            for (int i = 0; i < 4; ++i) {
                const float p = Ps[(ty * 4 + i) * PS_STRIDE + kk];
#pragma unroll
                for (int j = 0; j < 8; ++j) O[i][j] += p * vv[j];
            }
        }
    }

    // finalize + write ctx [B,S,H*D]
#pragma unroll
    for (int i = 0; i < 4; ++i) {
        const float invl = 1.0f / l_i[i];
        const int t = (qt << 6) + ty * 4 + i;
        float* dst = ctx + (size_t)(b * S_ + t) * E_ + h * D_;
#pragma unroll
        for (int j = 0; j < 8; ++j)
            dst[tx + 16 * j] = O[i][j] * invl;
    }
}

// ---------------------------------------------------------------------------
extern "C" void kernel_launch(void* const* d_in, const int* in_sizes, int n_in,
                              void* d_out, int out_size)
{
    const float* x    = (const float*)d_in[0];
    const float* wqkv = (const float*)d_in[1];
    const float* bqkv = (const float*)d_in[2];
    const float* wout = (const float*)d_in[3];
    const float* bout = (const float*)d_in[4];
    float* out = (float*)d_out;

    float *qkv, *ctx;
    cudaGetSymbolAddress((void**)&qkv, g_qkv);
    cudaGetSymbolAddress((void**)&ctx, g_ctx);

    cudaFuncSetAttribute(flash_attn_kernel,
                         cudaFuncAttributeMaxDynamicSharedMemorySize, SMEM_BYTES);

    // 1) QKV projection: [4096, 2048] @ [6144, 2048]^T + bias
    gemm_nt_bias<<<dim3(N_QKV / 128, MTOT / 128), 256>>>(x, wqkv, bqkv, qkv, N_QKV, E_);

    // 2) Rotary on q, k
    rotary_kernel<<<(B_ * S_ * H_ * HALF_ + 255) / 256, 256>>>(qkv);

    // 3) Causal flash attention
    flash_attn_kernel<<<dim3(S_ / 64, B_ * H_), 256, SMEM_BYTES>>>(qkv, ctx);

    // 4) Output projection: [4096, 2048] @ [2048, 2048]^T + bias
    gemm_nt_bias<<<dim3(E_ / 128, MTOT / 128), 256>>>(ctx, wout, bout, out, E_, E_);
}

// round 5
// speedup vs baseline: 1.7367x; 1.7367x over previous
#include <cuda_runtime.h>
#include <cuda_bf16.h>
#include <math.h>
#include <stdint.h>

#define B_    2
#define S_    2048
#define E_    2048
#define H_    16
#define D_    128
#define HALF_ 64
#define MTOT  (B_ * S_)          // 4096
#define N_QKV (3 * E_)           // 6144
#define KDIM  E_                 // 2048

// ---------------- scratch (__device__ globals; allocation-free) -------------
__device__ float g_qkv[(size_t)MTOT * 3 * E_];
__device__ float g_ctx[(size_t)MTOT * E_];
__device__ __nv_bfloat16 g_xh[(size_t)MTOT * E_],  g_xl[(size_t)MTOT * E_];
__device__ __nv_bfloat16 g_wqh[(size_t)N_QKV * E_], g_wql[(size_t)N_QKV * E_];
__device__ __nv_bfloat16 g_woh[(size_t)E_ * E_],   g_wol[(size_t)E_ * E_];
__device__ __nv_bfloat16 g_ch[(size_t)MTOT * E_],  g_cl[(size_t)MTOT * E_];

// ---------------- helpers ---------------------------------------------------
__device__ __forceinline__ uint32_t smem_u32(const void* p) {
    uint32_t a;
    asm("{ .reg .u64 t; cvta.to.shared.u64 t, %1; cvt.u32.u64 %0, t; }"
        : "=r"(a) : "l"(p));
    return a;
}

#define CP_ASYNC16(sa, gp) \
    asm volatile("cp.async.cg.shared.global [%0], [%1], 16;" :: "r"(sa), "l"(gp))
#define CP_COMMIT() asm volatile("cp.async.commit_group;" ::: "memory")
#define CP_WAIT(n)  asm volatile("cp.async.wait_group %0;" :: "n"(n) : "memory")

__device__ __forceinline__ void ldsm4(uint32_t& r0, uint32_t& r1, uint32_t& r2,
                                      uint32_t& r3, uint32_t addr) {
    asm volatile("ldmatrix.sync.aligned.m8n8.x4.shared.b16 {%0,%1,%2,%3}, [%4];"
                 : "=r"(r0), "=r"(r1), "=r"(r2), "=r"(r3) : "r"(addr));
}

__device__ __forceinline__ void mma_bf16(float* c, uint32_t a0, uint32_t a1,
                                         uint32_t a2, uint32_t a3,
                                         uint32_t b0, uint32_t b1) {
    asm volatile(
        "mma.sync.aligned.m16n8k16.row.col.f32.bf16.bf16.f32 "
        "{%0,%1,%2,%3}, {%4,%5,%6,%7}, {%8,%9}, {%0,%1,%2,%3};"
        : "+f"(c[0]), "+f"(c[1]), "+f"(c[2]), "+f"(c[3])
        : "r"(a0), "r"(a1), "r"(a2), "r"(a3), "r"(b0), "r"(b1));
}

// ---------------------------------------------------------------------------
// split fp32 -> bf16 hi/lo   (hi = rn(x), lo = rn(x - hi))
// ---------------------------------------------------------------------------
__global__ void __launch_bounds__(256) split_bf16(
    const float* __restrict__ in, __nv_bfloat16* __restrict__ hi,
    __nv_bfloat16* __restrict__ lo, int n4)
{
    const int i = blockIdx.x * blockDim.x + threadIdx.x;
    if (i >= n4) return;
    const float4 v = reinterpret_cast<const float4*>(in)[i];
    __nv_bfloat16 h0 = __float2bfloat16(v.x), h1 = __float2bfloat16(v.y);
    __nv_bfloat16 h2 = __float2bfloat16(v.z), h3 = __float2bfloat16(v.w);
    __nv_bfloat16 l0 = __float2bfloat16(v.x - __bfloat162float(h0));
    __nv_bfloat16 l1 = __float2bfloat16(v.y - __bfloat162float(h1));
    __nv_bfloat16 l2 = __float2bfloat16(v.z - __bfloat162float(h2));
    __nv_bfloat16 l3 = __float2bfloat16(v.w - __bfloat162float(h3));
    __nv_bfloat162 ha(h0, h1), hb(h2, h3), la(l0, l1), lb(l2, l3);
    uint2 hp, lp;
    hp.x = *reinterpret_cast<uint32_t*>(&ha); hp.y = *reinterpret_cast<uint32_t*>(&hb);
    lp.x = *reinterpret_cast<uint32_t*>(&la); lp.y = *reinterpret_cast<uint32_t*>(&lb);
    reinterpret_cast<uint2*>(hi)[i] = hp;
    reinterpret_cast<uint2*>(lo)[i] = lp;
}

// ---------------------------------------------------------------------------
// HMMA split-bf16 GEMM:  C[M,N] = A[M,K] @ W[N,K]^T + bias
//   C_fp32 ≈ Ah·Wh^T + Ah·Wl^T + Al·Wh^T
// 128x128 tile, BK=32, 8 warps (2m x 4n), warp = 64x32 via m16n8k16.
// cp.async double-buffered. Smem rows padded to 80B (conflict-free ldmatrix).
// ---------------------------------------------------------------------------
#define RSTRIDE   80                       // bytes per 32-bf16 row (64 + 16 pad)
#define TILE_B    (128 * RSTRIDE)          // 10240 B per operand tile
#define STAGE_B   (4 * TILE_B)             // Ah, Al, Wh, Wl
#define GSM_TOTAL (2 * STAGE_B)            // 81920 B

__global__ void __launch_bounds__(256) gemm_hmma_x3(
    const __nv_bfloat16* __restrict__ Ah, const __nv_bfloat16* __restrict__ Al,
    const __nv_bfloat16* __restrict__ Wh, const __nv_bfloat16* __restrict__ Wl,
    const float* __restrict__ bias, float* __restrict__ C, int N, int K)
{
    extern __shared__ char smem[];
    const uint32_t sb = smem_u32(smem);

    const int tid  = threadIdx.x;
    const int wid  = tid >> 5;
    const int lane = tid & 31;
    const int wm   = wid & 1;              // 0/1 -> m offset 0/64
    const int wn   = wid >> 1;             // 0..3 -> n offset 0/32/64/96
    const int rowBlk = blockIdx.y * 128;
    const int colBlk = blockIdx.x * 128;

    // global-load mapping: 2 float4 per thread per tile
    const int gr0 = tid >> 2;              // row for l=0  (0..63)
    const int gc  = (tid & 3) * 16;        // 16B column offset within 64B row

    const __nv_bfloat16* gA[2] = { Ah, Al };
    const __nv_bfloat16* gW[2] = { Wh, Wl };

    auto issue_stage = [&](int k0, int stg) {
        const uint32_t s0 = sb + stg * STAGE_B;
#pragma unroll
        for (int t = 0; t < 2; ++t) {       // hi / lo
#pragma unroll
            for (int l = 0; l < 2; ++l) {   // two rows per thread
                const int r = gr0 + l * 64;
                const uint32_t so = r * RSTRIDE + gc;
                CP_ASYNC16(s0 + t * TILE_B + so,
                           gA[t] + (size_t)(rowBlk + r) * K + k0 + (gc >> 1));
                CP_ASYNC16(s0 + (2 + t) * TILE_B + so,
                           gW[t] + (size_t)(colBlk + r) * K + k0 + (gc >> 1));
            }
        }
        CP_COMMIT();
    };

    float acc[4][4][4];
#pragma unroll
    for (int i = 0; i < 4; ++i)
#pragma unroll
        for (int j = 0; j < 4; ++j)
#pragma unroll
            for (int q = 0; q < 4; ++q) acc[i][j][q] = 0.0f;

    // lane-dependent ldmatrix byte offsets (within an operand tile)
    const uint32_t aOff = (uint32_t)((wm * 64 + (lane & 15)) * RSTRIDE +
                                     (lane >> 4) * 16);
    const uint32_t bOff = (uint32_t)((wn * 32 + (lane & 7) + ((lane >> 4) << 3)) * RSTRIDE +
                                     ((lane >> 3) & 1) * 16);

    const int NCH = K / 32;
    issue_stage(0, 0);

    for (int c = 0; c < NCH; ++c) {
        if (c + 1 < NCH) issue_stage((c + 1) * 32, (c + 1) & 1);
        if (c + 1 < NCH) { CP_WAIT(1); } else { CP_WAIT(0); }
        __syncthreads();

        const uint32_t s0 = sb + (c & 1) * STAGE_B;
        const uint32_t sAh = s0 + aOff;
        const uint32_t sAl = s0 + TILE_B + aOff;
        const uint32_t sWh = s0 + 2 * TILE_B + bOff;
        const uint32_t sWl = s0 + 3 * TILE_B + bOff;

#pragma unroll
        for (int ks = 0; ks < 2; ++ks) {
            const uint32_t ko = ks * 32;   // 16 bf16 = 32 bytes
            uint32_t ah[4][4], al[4][4], wh[4][2], wl[4][2];
#pragma unroll
            for (int mt = 0; mt < 4; ++mt) {
                ldsm4(ah[mt][0], ah[mt][1], ah[mt][2], ah[mt][3],
                      sAh + mt * 16 * RSTRIDE + ko);
                ldsm4(al[mt][0], al[mt][1], al[mt][2], al[mt][3],
                      sAl + mt * 16 * RSTRIDE + ko);
            }
#pragma unroll
            for (int p = 0; p < 2; ++p) {  // each x4 covers 2 n-tiles
                ldsm4(wh[2 * p][0], wh[2 * p][1], wh[2 * p + 1][0], wh[2 * p + 1][1],
                      sWh + p * 16 * RSTRIDE + ko);
                ldsm4(wl[2 * p][0], wl[2 * p][1], wl[2 * p + 1][0], wl[2 * p + 1][1],
                      sWl + p * 16 * RSTRIDE + ko);
            }
#pragma unroll
            for (int mt = 0; mt < 4; ++mt)
#pragma unroll
                for (int nt = 0; nt < 4; ++nt) {
                    mma_bf16(acc[mt][nt], ah[mt][0], ah[mt][1], ah[mt][2], ah[mt][3],
                             wh[nt][0], wh[nt][1]);
                    mma_bf16(acc[mt][nt], ah[mt][0], ah[mt][1], ah[mt][2], ah[mt][3],
                             wl[nt][0], wl[nt][1]);
                    mma_bf16(acc[mt][nt], al[mt][0], al[mt][1], al[mt][2], al[mt][3],
                             wh[nt][0], wh[nt][1]);
                }
        }
        __syncthreads();
    }

    // epilogue: bias + fp32 store
    const int g = lane >> 2;
    const int t = lane & 3;
#pragma unroll
    for (int mt = 0; mt < 4; ++mt) {
        const int row0 = rowBlk + wm * 64 + mt * 16 + g;
#pragma unroll
        for (int nt = 0; nt < 4; ++nt) {
            const int col = colBlk + wn * 32 + nt * 8 + 2 * t;
            const float b0 = bias[col], b1 = bias[col + 1];
            float2 v0 = make_float2(acc[mt][nt][0] + b0, acc[mt][nt][1] + b1);
            float2 v1 = make_float2(acc[mt][nt][2] + b0, acc[mt][nt][3] + b1);
            *reinterpret_cast<float2*>(C + (size_t)row0 * N + col) = v0;
            *reinterpret_cast<float2*>(C + (size_t)(row0 + 8) * N + col) = v1;
        }
    }
}

// ---------------------------------------------------------------------------
// Rotary: in-place on qkv [B,S,3,H,D] for q(0), k(1)
// ---------------------------------------------------------------------------
__global__ void __launch_bounds__(256) rotary_kernel(float* __restrict__ qkv)
{
    const int idx = blockIdx.x * blockDim.x + threadIdx.x;
    const int total = B_ * S_ * H_ * HALF_;
    if (idx >= total) return;

    const int dh = idx & (HALF_ - 1);
    const int h  = (idx >> 6) & (H_ - 1);
    const int s  = (idx >> 10) & (S_ - 1);
    const int b  = idx >> 21;

    const double inv = exp(-(double)dh * (log(10000.0) / 64.0));
    const float  f   = (float)((double)s * inv);
    float c, sn;
    sincosf(f, &sn, &c);

#pragma unroll
    for (int comp = 0; comp < 2; ++comp) {
        const size_t base = (((size_t)(b * S_ + s) * 3 + comp) * H_ + h) * (size_t)D_;
        const float x1 = qkv[base + dh];
        const float x2 = qkv[base + dh + HALF_];
        qkv[base + dh]         = x1 * c - x2 * sn;
        qkv[base + dh + HALF_] = x2 * c + x1 * sn;
    }
}

// ---------------------------------------------------------------------------
// Flash attention (fp32, causal) — unchanged (next optimization target)
// ---------------------------------------------------------------------------
#define KS_STRIDE 132
#define PS_STRIDE 66
#define SMEM_FLOATS (64 * 128 + 64 * KS_STRIDE + 64 * 128 + 64 * PS_STRIDE)
#define SMEM_BYTES  (SMEM_FLOATS * 4)

__global__ void __launch_bounds__(256) flash_attn_kernel(
    const float* __restrict__ qkv, float* __restrict__ ctx)
{
    extern __shared__ float fsm[];
    float* Qs = fsm;
    float* Ks = Qs + 64 * 128;
    float* Vs = Ks + 64 * KS_STRIDE;
    float* Ps = Vs + 64 * 128;

    const int qt = blockIdx.x;
    const int bh = blockIdx.y;
    const int b  = bh >> 4;
    const int h  = bh & 15;
    const int tid = threadIdx.x;
    const int tx  = tid & 15;
    const int ty  = tid >> 4;

#pragma unroll
    for (int l = 0; l < 8; ++l) {
        const int idx = tid + l * 256;
        const int r   = idx >> 5;
        const int d4  = idx & 31;
        const int sq  = (qt << 6) + r;
        const float4 v = *reinterpret_cast<const float4*>(
            qkv + ((size_t)(b * S_ + sq) * 3 + 0) * E_ + h * D_ + d4 * 4);
        *reinterpret_cast<float4*>(Qs + r * 128 + d4 * 4) = v;
    }

    float m_i[4], l_i[4], O[4][8];
#pragma unroll
    for (int i = 0; i < 4; ++i) {
        m_i[i] = -1e30f;
        l_i[i] = 0.0f;
#pragma unroll
        for (int j = 0; j < 8; ++j) O[i][j] = 0.0f;
    }

    const float scale = 0.08838834764831843f;

    for (int kt = 0; kt <= qt; ++kt) {
        __syncthreads();
#pragma unroll
        for (int l = 0; l < 8; ++l) {
            const int idx = tid + l * 256;
            const int r   = idx >> 5;
            const int d4  = idx & 31;
            const int sk  = (kt << 6) + r;
            const float4 kv4 = *reinterpret_cast<const float4*>(
                qkv + ((size_t)(b * S_ + sk) * 3 + 1) * E_ + h * D_ + d4 * 4);
            *reinterpret_cast<float4*>(Ks + r * KS_STRIDE + d4 * 4) = kv4;
            const float4 vv4 = *reinterpret_cast<const float4*>(
                qkv + ((size_t)(b * S_ + sk) * 3 + 2) * E_ + h * D_ + d4 * 4);
            *reinterpret_cast<float4*>(Vs + r * 128 + d4 * 4) = vv4;
        }
        __syncthreads();

        float sacc[4][4];
#pragma unroll
        for (int i = 0; i < 4; ++i)
#pragma unroll
            for (int j = 0; j < 4; ++j) sacc[i][j] = 0.0f;

#pragma unroll 8
        for (int k4 = 0; k4 < 32; ++k4) {
            float4 qv[4], kv[4];
#pragma unroll
            for (int i = 0; i < 4; ++i)
                qv[i] = *reinterpret_cast<const float4*>(Qs + (ty * 4 + i) * 128 + k4 * 4);
#pragma unroll
            for (int j = 0; j < 4; ++j)
                kv[j] = *reinterpret_cast<const float4*>(Ks + (tx + 16 * j) * KS_STRIDE + k4 * 4);
#pragma unroll
            for (int i = 0; i < 4; ++i)
#pragma unroll
                for (int j = 0; j < 4; ++j)
                    sacc[i][j] += qv[i].x * kv[j].x + qv[i].y * kv[j].y +
                                  qv[i].z * kv[j].z + qv[i].w * kv[j].w;
        }

#pragma unroll
        for (int i = 0; i < 4; ++i) {
            const int qg = (qt << 6) + ty * 4 + i;
#pragma unroll
            for (int j = 0; j < 4; ++j) {
                float s = sacc[i][j] * scale;
                if (kt == qt) {
                    const int kg = (kt << 6) + tx + 16 * j;
                    if (kg > qg) s = -1e30f;
                }
                sacc[i][j] = s;
            }
            float rm = fmaxf(fmaxf(sacc[i][0], sacc[i][1]), fmaxf(sacc[i][2], sacc[i][3]));
            rm = fmaxf(rm, __shfl_xor_sync(0xffffffffu, rm, 8));
            rm = fmaxf(rm, __shfl_xor_sync(0xffffffffu, rm, 4));
            rm = fmaxf(rm, __shfl_xor_sync(0xffffffffu, rm, 2));
            rm = fmaxf(rm, __shfl_xor_sync(0xffffffffu, rm, 1));

            const float mn    = fmaxf(m_i[i], rm);
            const float alpha = __expf(m_i[i] - mn);
            float rsum = 0.0f;
#pragma unroll
            for (int j = 0; j < 4; ++j) {
                const float p = __expf(sacc[i][j] - mn);
                rsum += p;
                Ps[(ty * 4 + i) * PS_STRIDE + tx + 16 * j] = p;
            }
            rsum += __shfl_xor_sync(0xffffffffu, rsum, 8);
            rsum += __shfl_xor_sync(0xffffffffu, rsum, 4);
            rsum += __shfl_xor_sync(0xffffffffu, rsum, 2);
            rsum += __shfl_xor_sync(0xffffffffu, rsum, 1);

            l_i[i] = l_i[i] * alpha + rsum;
            m_i[i] = mn;
#pragma unroll
            for (int j = 0; j < 8; ++j) O[i][j] *= alpha;
        }
        __syncthreads();

#pragma unroll 4
        for (int kk = 0; kk < 64; ++kk) {
            float vv[8];
#pragma unroll
            for (int j = 0; j < 8; ++j) vv[j] = Vs[kk * 128 + tx + 16 * j];
#pragma unroll
            for (int i = 0; i < 4; ++i) {
                const float p = Ps[(ty * 4 + i) * PS_STRIDE + kk];
#pragma unroll
                for (int j = 0; j < 8; ++j) O[i][j] += p * vv[j];
            }
        }
    }

#pragma unroll
    for (int i = 0; i < 4; ++i) {
        const float invl = 1.0f / l_i[i];
        const int t = (qt << 6) + ty * 4 + i;
        float* dst = ctx + (size_t)(b * S_ + t) * E_ + h * D_;
#pragma unroll
        for (int j = 0; j < 8; ++j)
            dst[tx + 16 * j] = O[i][j] * invl;
    }
}

// ---------------------------------------------------------------------------
extern "C" void kernel_launch(void* const* d_in, const int* in_sizes, int n_in,
                              void* d_out, int out_size)
{
    const float* x    = (const float*)d_in[0];
    const float* wqkv = (const float*)d_in[1];
    const float* bqkv = (const float*)d_in[2];
    const float* wout = (const float*)d_in[3];
    const float* bout = (const float*)d_in[4];
    float* out = (float*)d_out;

    float *qkv, *ctx;
    __nv_bfloat16 *xh, *xl, *wqh, *wql, *woh, *wol, *ch, *cl;
    cudaGetSymbolAddress((void**)&qkv, g_qkv);
    cudaGetSymbolAddress((void**)&ctx, g_ctx);
    cudaGetSymbolAddress((void**)&xh, g_xh);
    cudaGetSymbolAddress((void**)&xl, g_xl);
    cudaGetSymbolAddress((void**)&wqh, g_wqh);
    cudaGetSymbolAddress((void**)&wql, g_wql);
    cudaGetSymbolAddress((void**)&woh, g_woh);
    cudaGetSymbolAddress((void**)&wol, g_wol);
    cudaGetSymbolAddress((void**)&ch, g_ch);
    cudaGetSymbolAddress((void**)&cl, g_cl);

    cudaFuncSetAttribute(flash_attn_kernel,
                         cudaFuncAttributeMaxDynamicSharedMemorySize, SMEM_BYTES);
    cudaFuncSetAttribute(gemm_hmma_x3,
                         cudaFuncAttributeMaxDynamicSharedMemorySize, GSM_TOTAL);

    // 0) split inputs/weights to bf16 hi/lo
    {
        int n4;
        n4 = MTOT * E_ / 4;
        split_bf16<<<(n4 + 255) / 256, 256>>>(x, xh, xl, n4);
        n4 = N_QKV * E_ / 4;
        split_bf16<<<(n4 + 255) / 256, 256>>>(wqkv, wqh, wql, n4);
        n4 = E_ * E_ / 4;
        split_bf16<<<(n4 + 255) / 256, 256>>>(wout, woh, wol, n4);
    }

    // 1) QKV projection (HMMA): [4096,2048] @ [6144,2048]^T + bias
    gemm_hmma_x3<<<dim3(N_QKV / 128, MTOT / 128), 256, GSM_TOTAL>>>(
        xh, xl, wqh, wql, bqkv, qkv, N_QKV, KDIM);

    // 2) Rotary on q, k
    rotary_kernel<<<(B_ * S_ * H_ * HALF_ + 255) / 256, 256>>>(qkv);

    // 3) Causal flash attention (fp32)
    flash_attn_kernel<<<dim3(S_ / 64, B_ * H_), 256, SMEM_BYTES>>>(qkv, ctx);

    // 4) split ctx, output projection (HMMA)
    {
        int n4 = MTOT * E_ / 4;
        split_bf16<<<(n4 + 255) / 256, 256>>>(ctx, ch, cl, n4);
    }
    gemm_hmma_x3<<<dim3(E_ / 128, MTOT / 128), 256, GSM_TOTAL>>>(
        ch, cl, woh, wol, bout, out, E_, KDIM);
}

// round 6
// speedup vs baseline: 2.4762x; 1.4258x over previous
#include <cuda_runtime.h>
#include <cuda_bf16.h>
#include <math.h>
#include <stdint.h>

#define B_    2
#define S_    2048
#define E_    2048
#define H_    16
#define D_    128
#define HALF_ 64
#define MTOT  (B_ * S_)          // 4096
#define N_QKV (3 * E_)           // 6144
#define KDIM  E_                 // 2048
#define BH_   (B_ * H_)          // 32

// ---------------- scratch (__device__ globals; allocation-free) -------------
__device__ float g_qkv[(size_t)MTOT * 3 * E_];
__device__ __nv_bfloat16 g_xh[(size_t)MTOT * E_],  g_xl[(size_t)MTOT * E_];
__device__ __nv_bfloat16 g_wqh[(size_t)N_QKV * E_], g_wql[(size_t)N_QKV * E_];
__device__ __nv_bfloat16 g_woh[(size_t)E_ * E_],   g_wol[(size_t)E_ * E_];
__device__ __nv_bfloat16 g_ch[(size_t)MTOT * E_],  g_cl[(size_t)MTOT * E_];
// attention operands, head-major
__device__ __nv_bfloat16 g_Qh[(size_t)BH_ * S_ * D_], g_Ql[(size_t)BH_ * S_ * D_];
__device__ __nv_bfloat16 g_Kh[(size_t)BH_ * S_ * D_], g_Kl[(size_t)BH_ * S_ * D_];
__device__ __nv_bfloat16 g_Vth[(size_t)BH_ * D_ * S_], g_Vtl[(size_t)BH_ * D_ * S_];

// ---------------- helpers ---------------------------------------------------
__device__ __forceinline__ uint32_t smem_u32(const void* p) {
    uint32_t a;
    asm("{ .reg .u64 t; cvta.to.shared.u64 t, %1; cvt.u32.u64 %0, t; }"
        : "=r"(a) : "l"(p));
    return a;
}

#define CP_ASYNC16(sa, gp) \
    asm volatile("cp.async.cg.shared.global [%0], [%1], 16;" :: "r"(sa), "l"(gp))
#define CP_COMMIT() asm volatile("cp.async.commit_group;" ::: "memory")
#define CP_WAIT(n)  asm volatile("cp.async.wait_group %0;" :: "n"(n) : "memory")

__device__ __forceinline__ void ldsm4(uint32_t& r0, uint32_t& r1, uint32_t& r2,
                                      uint32_t& r3, uint32_t addr) {
    asm volatile("ldmatrix.sync.aligned.m8n8.x4.shared.b16 {%0,%1,%2,%3}, [%4];"
                 : "=r"(r0), "=r"(r1), "=r"(r2), "=r"(r3) : "r"(addr));
}

__device__ __forceinline__ void mma_bf16(float* c, const uint32_t* a,
                                         const uint32_t* b) {
    asm volatile(
        "mma.sync.aligned.m16n8k16.row.col.f32.bf16.bf16.f32 "
        "{%0,%1,%2,%3}, {%4,%5,%6,%7}, {%8,%9}, {%0,%1,%2,%3};"
        : "+f"(c[0]), "+f"(c[1]), "+f"(c[2]), "+f"(c[3])
        : "r"(a[0]), "r"(a[1]), "r"(a[2]), "r"(a[3]), "r"(b[0]), "r"(b[1]));
}

__device__ __forceinline__ void split2(float f0, float f1,
                                       uint32_t& h, uint32_t& l) {
    __nv_bfloat16 h0 = __float2bfloat16(f0), h1 = __float2bfloat16(f1);
    __nv_bfloat162 hp(h0, h1);
    __nv_bfloat162 lp(__float2bfloat16(f0 - __bfloat162float(h0)),
                      __float2bfloat16(f1 - __bfloat162float(h1)));
    h = *reinterpret_cast<uint32_t*>(&hp);
    l = *reinterpret_cast<uint32_t*>(&lp);
}

// ---------------------------------------------------------------------------
// split fp32 -> bf16 hi/lo
// ---------------------------------------------------------------------------
__global__ void __launch_bounds__(256) split_bf16(
    const float* __restrict__ in, __nv_bfloat16* __restrict__ hi,
    __nv_bfloat16* __restrict__ lo, int n4)
{
    const int i = blockIdx.x * blockDim.x + threadIdx.x;
    if (i >= n4) return;
    const float4 v = reinterpret_cast<const float4*>(in)[i];
    uint32_t h0, l0, h1, l1;
    split2(v.x, v.y, h0, l0);
    split2(v.z, v.w, h1, l1);
    uint2 hp = make_uint2(h0, h1), lp = make_uint2(l0, l1);
    reinterpret_cast<uint2*>(hi)[i] = hp;
    reinterpret_cast<uint2*>(lo)[i] = lp;
}

// ---------------------------------------------------------------------------
// HMMA split-bf16 GEMM (unchanged from round 5, passing)
// ---------------------------------------------------------------------------
#define RSTRIDE   80
#define TILE_B    (128 * RSTRIDE)
#define STAGE_B   (4 * TILE_B)
#define GSM_TOTAL (2 * STAGE_B)

__global__ void __launch_bounds__(256) gemm_hmma_x3(
    const __nv_bfloat16* __restrict__ Ah, const __nv_bfloat16* __restrict__ Al,
    const __nv_bfloat16* __restrict__ Wh, const __nv_bfloat16* __restrict__ Wl,
    const float* __restrict__ bias, float* __restrict__ C, int N, int K)
{
    extern __shared__ char smem[];
    const uint32_t sb = smem_u32(smem);

    const int tid  = threadIdx.x;
    const int wid  = tid >> 5;
    const int lane = tid & 31;
    const int wm   = wid & 1;
    const int wn   = wid >> 1;
    const int rowBlk = blockIdx.y * 128;
    const int colBlk = blockIdx.x * 128;

    const int gr0 = tid >> 2;
    const int gc  = (tid & 3) * 16;

    const __nv_bfloat16* gA[2] = { Ah, Al };
    const __nv_bfloat16* gW[2] = { Wh, Wl };

    auto issue_stage = [&](int k0, int stg) {
        const uint32_t s0 = sb + stg * STAGE_B;
#pragma unroll
        for (int t = 0; t < 2; ++t) {
#pragma unroll
            for (int l = 0; l < 2; ++l) {
                const int r = gr0 + l * 64;
                const uint32_t so = r * RSTRIDE + gc;
                CP_ASYNC16(s0 + t * TILE_B + so,
                           gA[t] + (size_t)(rowBlk + r) * K + k0 + (gc >> 1));
                CP_ASYNC16(s0 + (2 + t) * TILE_B + so,
                           gW[t] + (size_t)(colBlk + r) * K + k0 + (gc >> 1));
            }
        }
        CP_COMMIT();
    };

    float acc[4][4][4];
#pragma unroll
    for (int i = 0; i < 4; ++i)
#pragma unroll
        for (int j = 0; j < 4; ++j)
#pragma unroll
            for (int q = 0; q < 4; ++q) acc[i][j][q] = 0.0f;

    const uint32_t aOff = (uint32_t)((wm * 64 + (lane & 15)) * RSTRIDE +
                                     (lane >> 4) * 16);
    const uint32_t bOff = (uint32_t)((wn * 32 + (lane & 7) + ((lane >> 4) << 3)) * RSTRIDE +
                                     ((lane >> 3) & 1) * 16);

    const int NCH = K / 32;
    issue_stage(0, 0);

    for (int c = 0; c < NCH; ++c) {
        if (c + 1 < NCH) issue_stage((c + 1) * 32, (c + 1) & 1);
        if (c + 1 < NCH) { CP_WAIT(1); } else { CP_WAIT(0); }
        __syncthreads();

        const uint32_t s0 = sb + (c & 1) * STAGE_B;
        const uint32_t sAh = s0 + aOff;
        const uint32_t sAl = s0 + TILE_B + aOff;
        const uint32_t sWh = s0 + 2 * TILE_B + bOff;
        const uint32_t sWl = s0 + 3 * TILE_B + bOff;

#pragma unroll
        for (int ks = 0; ks < 2; ++ks) {
            const uint32_t ko = ks * 32;
            uint32_t ah[4][4], al[4][4], wh[4][2], wl[4][2];
#pragma unroll
            for (int mt = 0; mt < 4; ++mt) {
                ldsm4(ah[mt][0], ah[mt][1], ah[mt][2], ah[mt][3],
                      sAh + mt * 16 * RSTRIDE + ko);
                ldsm4(al[mt][0], al[mt][1], al[mt][2], al[mt][3],
                      sAl + mt * 16 * RSTRIDE + ko);
            }
#pragma unroll
            for (int p = 0; p < 2; ++p) {
                ldsm4(wh[2 * p][0], wh[2 * p][1], wh[2 * p + 1][0], wh[2 * p + 1][1],
                      sWh + p * 16 * RSTRIDE + ko);
                ldsm4(wl[2 * p][0], wl[2 * p][1], wl[2 * p + 1][0], wl[2 * p + 1][1],
                      sWl + p * 16 * RSTRIDE + ko);
            }
#pragma unroll
            for (int mt = 0; mt < 4; ++mt)
#pragma unroll
                for (int nt = 0; nt < 4; ++nt) {
                    mma_bf16(acc[mt][nt], ah[mt], wh[nt]);
                    mma_bf16(acc[mt][nt], ah[mt], wl[nt]);
                    mma_bf16(acc[mt][nt], al[mt], wh[nt]);
                }
        }
        __syncthreads();
    }

    const int g = lane >> 2;
    const int t = lane & 3;
#pragma unroll
    for (int mt = 0; mt < 4; ++mt) {
        const int row0 = rowBlk + wm * 64 + mt * 16 + g;
#pragma unroll
        for (int nt = 0; nt < 4; ++nt) {
            const int col = colBlk + wn * 32 + nt * 8 + 2 * t;
            const float b0 = bias[col], b1 = bias[col + 1];
            float2 v0 = make_float2(acc[mt][nt][0] + b0, acc[mt][nt][1] + b1);
            float2 v1 = make_float2(acc[mt][nt][2] + b0, acc[mt][nt][3] + b1);
            *reinterpret_cast<float2*>(C + (size_t)row0 * N + col) = v0;
            *reinterpret_cast<float2*>(C + (size_t)(row0 + 8) * N + col) = v1;
        }
    }
}

// ---------------------------------------------------------------------------
// Fused rotary + split for Q,K: qkv[B,S,3,H,D] fp32 -> Qh/Ql/Kh/Kl [BH,S,D]
// ---------------------------------------------------------------------------
__global__ void __launch_bounds__(256) qk_rope_split(
    const float* __restrict__ qkv,
    __nv_bfloat16* __restrict__ Qh, __nv_bfloat16* __restrict__ Ql,
    __nv_bfloat16* __restrict__ Kh, __nv_bfloat16* __restrict__ Kl)
{
    const int idx = blockIdx.x * blockDim.x + threadIdx.x;
    const int total = B_ * S_ * H_ * HALF_;
    if (idx >= total) return;

    const int dh = idx & (HALF_ - 1);
    const int h  = (idx >> 6) & (H_ - 1);
    const int s  = (idx >> 10) & (S_ - 1);
    const int b  = idx >> 21;

    const double inv = exp(-(double)dh * (log(10000.0) / 64.0));
    const float  f   = (float)((double)s * inv);
    float c, sn;
    sincosf(f, &sn, &c);

    const size_t obase = ((size_t)(b * H_ + h) * S_ + s) * D_;

    // q (comp 0)
    {
        const size_t ib = (((size_t)(b * S_ + s) * 3 + 0) * H_ + h) * (size_t)D_;
        const float x1 = qkv[ib + dh], x2 = qkv[ib + dh + HALF_];
        const float y1 = x1 * c - x2 * sn, y2 = x2 * c + x1 * sn;
        __nv_bfloat16 h1 = __float2bfloat16(y1), h2 = __float2bfloat16(y2);
        Qh[obase + dh] = h1;
        Qh[obase + dh + HALF_] = h2;
        Ql[obase + dh] = __float2bfloat16(y1 - __bfloat162float(h1));
        Ql[obase + dh + HALF_] = __float2bfloat16(y2 - __bfloat162float(h2));
    }
    // k (comp 1)
    {
        const size_t ib = (((size_t)(b * S_ + s) * 3 + 1) * H_ + h) * (size_t)D_;
        const float x1 = qkv[ib + dh], x2 = qkv[ib + dh + HALF_];
        const float y1 = x1 * c - x2 * sn, y2 = x2 * c + x1 * sn;
        __nv_bfloat16 h1 = __float2bfloat16(y1), h2 = __float2bfloat16(y2);
        Kh[obase + dh] = h1;
        Kh[obase + dh + HALF_] = h2;
        Kl[obase + dh] = __float2bfloat16(y1 - __bfloat162float(h1));
        Kl[obase + dh + HALF_] = __float2bfloat16(y2 - __bfloat162float(h2));
    }
}

// ---------------------------------------------------------------------------
// V transpose + split: qkv comp2 [B,S,H,D] -> Vth/Vtl [BH, D, S]
// 32x32 tiles via smem.
// ---------------------------------------------------------------------------
__global__ void __launch_bounds__(256) v_transpose_split(
    const float* __restrict__ qkv,
    __nv_bfloat16* __restrict__ Vth, __nv_bfloat16* __restrict__ Vtl)
{
    __shared__ float tile[32][33];
    const int tx = threadIdx.x;          // 0..31
    const int ty = threadIdx.y;          // 0..7
    const int s0 = blockIdx.x * 32;
    const int d0 = blockIdx.y * 32;
    const int bh = blockIdx.z;
    const int b  = bh >> 4;
    const int h  = bh & 15;

#pragma unroll
    for (int i = 0; i < 4; ++i) {
        const int s = s0 + ty + i * 8;
        const int d = d0 + tx;
        tile[ty + i * 8][tx] =
            qkv[(((size_t)(b * S_ + s) * 3 + 2) * H_ + h) * (size_t)D_ + d];
    }
    __syncthreads();

#pragma unroll
    for (int i = 0; i < 4; ++i) {
        const int d = d0 + ty + i * 8;
        const int s = s0 + tx;
        const float v = tile[tx][ty + i * 8];
        const __nv_bfloat16 hv = __float2bfloat16(v);
        const size_t o = ((size_t)bh * D_ + d) * S_ + s;
        Vth[o] = hv;
        Vtl[o] = __float2bfloat16(v - __bfloat162float(hv));
    }
}

// ---------------------------------------------------------------------------
// HMMA flash attention (split-bf16, causal).
// Block: 128 threads (4 warps x m16) = 64 q rows.  KV tile = 64.
// Writes ctx directly as bf16 hi/lo into ch/cl [MTOT, E].
// ---------------------------------------------------------------------------
#define QK_STR 272                  // bytes per 128-bf16 row (256 + 16 pad)
#define VT_STR 144                  // bytes per 64-bf16 row (128 + 16 pad)
#define ASM_QH 0
#define ASM_QL (64 * QK_STR)
#define ASM_KH (2 * 64 * QK_STR)
#define ASM_KL (3 * 64 * QK_STR)
#define ASM_VH (4 * 64 * QK_STR)
#define ASM_VL (4 * 64 * QK_STR + 128 * VT_STR)
#define ASM_TOTAL (4 * 64 * QK_STR + 2 * 128 * VT_STR)   // 106496 B

__global__ void __launch_bounds__(128, 1) attn_hmma(
    const __nv_bfloat16* __restrict__ Qh, const __nv_bfloat16* __restrict__ Ql,
    const __nv_bfloat16* __restrict__ Kh, const __nv_bfloat16* __restrict__ Kl,
    const __nv_bfloat16* __restrict__ Vth, const __nv_bfloat16* __restrict__ Vtl,
    __nv_bfloat16* __restrict__ ch, __nv_bfloat16* __restrict__ cl)
{
    extern __shared__ char smem[];
    const uint32_t sb = smem_u32(smem);

    const int qt  = gridDim.x - 1 - blockIdx.x;   // long blocks first
    const int bh  = blockIdx.y;
    const int tid = threadIdx.x;
    const int wq  = tid >> 5;                      // warp: q-row group
    const int lane = tid & 31;
    const int g   = lane >> 2;
    const int t   = lane & 3;

    const size_t qkBase = (size_t)bh * S_ * D_;
    const size_t vBase  = (size_t)bh * D_ * S_;

    // ---- load Q tile (64x128 hi+lo) into smem ----
#pragma unroll
    for (int l = 0; l < 8; ++l) {
        const int idx = tid + l * 128;             // 1024
        const int r = idx >> 4, c = idx & 15;
        const size_t go = qkBase + (size_t)(qt * 64 + r) * D_ + c * 8;
        *reinterpret_cast<float4*>(smem + ASM_QH + r * QK_STR + c * 16) =
            *reinterpret_cast<const float4*>(Qh + go);
        *reinterpret_cast<float4*>(smem + ASM_QL + r * QK_STR + c * 16) =
            *reinterpret_cast<const float4*>(Ql + go);
    }
    __syncthreads();

    // ---- preload Q fragments into registers ----
    const uint32_t aOff = (uint32_t)((wq * 16 + (lane & 15)) * QK_STR +
                                     (lane >> 4) * 16);
    uint32_t qfh[8][4], qfl[8][4];
#pragma unroll
    for (int kc = 0; kc < 8; ++kc) {
        ldsm4(qfh[kc][0], qfh[kc][1], qfh[kc][2], qfh[kc][3],
              sb + ASM_QH + aOff + kc * 32);
        ldsm4(qfl[kc][0], qfl[kc][1], qfl[kc][2], qfl[kc][3],
              sb + ASM_QL + aOff + kc * 32);
    }

    const uint32_t bOffK = (uint32_t)(((lane & 7) + ((lane >> 4) << 3)) * QK_STR +
                                      ((lane >> 3) & 1) * 16);
    const uint32_t bOffV = (uint32_t)(((lane & 7) + ((lane >> 4) << 3)) * VT_STR +
                                      ((lane >> 3) & 1) * 16);

    float O[16][4];
#pragma unroll
    for (int nt = 0; nt < 16; ++nt)
#pragma unroll
        for (int q = 0; q < 4; ++q) O[nt][q] = 0.0f;
    float m0 = -1e30f, m1 = -1e30f, l0 = 0.0f, l1 = 0.0f;

    const float scale = 0.08838834764831843f;   // 1/sqrt(128)
    const int rl0 = wq * 16 + g;                // local q row of c0/c1
    const int rl1 = rl0 + 8;                    // local q row of c2/c3

    for (int kt = 0; kt <= qt; ++kt) {
        __syncthreads();
        // ---- load K (64x128) and Vt (128x64) hi+lo ----
#pragma unroll
        for (int l = 0; l < 8; ++l) {
            const int idx = tid + l * 128;
            {
                const int r = idx >> 4, c = idx & 15;
                const size_t go = qkBase + (size_t)(kt * 64 + r) * D_ + c * 8;
                *reinterpret_cast<float4*>(smem + ASM_KH + r * QK_STR + c * 16) =
                    *reinterpret_cast<const float4*>(Kh + go);
                *reinterpret_cast<float4*>(smem + ASM_KL + r * QK_STR + c * 16) =
                    *reinterpret_cast<const float4*>(Kl + go);
            }
            {
                const int r = idx >> 3, c = idx & 7;
                const size_t go = vBase + (size_t)r * S_ + kt * 64 + c * 8;
                *reinterpret_cast<float4*>(smem + ASM_VH + r * VT_STR + c * 16) =
                    *reinterpret_cast<const float4*>(Vth + go);
                *reinterpret_cast<float4*>(smem + ASM_VL + r * VT_STR + c * 16) =
                    *reinterpret_cast<const float4*>(Vtl + go);
            }
        }
        __syncthreads();

        // ---- S = Q K^T (3-pass split) ----
        float sacc[8][4];
#pragma unroll
        for (int nt = 0; nt < 8; ++nt)
#pragma unroll
            for (int q = 0; q < 4; ++q) sacc[nt][q] = 0.0f;

#pragma unroll
        for (int kc = 0; kc < 8; ++kc) {
            uint32_t kfh[8][2], kfl[8][2];
#pragma unroll
            for (int p = 0; p < 4; ++p) {
                ldsm4(kfh[2 * p][0], kfh[2 * p][1], kfh[2 * p + 1][0], kfh[2 * p + 1][1],
                      sb + ASM_KH + p * 16 * QK_STR + bOffK + kc * 32);
                ldsm4(kfl[2 * p][0], kfl[2 * p][1], kfl[2 * p + 1][0], kfl[2 * p + 1][1],
                      sb + ASM_KL + p * 16 * QK_STR + bOffK + kc * 32);
            }
#pragma unroll
            for (int nt = 0; nt < 8; ++nt) {
                mma_bf16(sacc[nt], qfh[kc], kfh[nt]);
                mma_bf16(sacc[nt], qfh[kc], kfl[nt]);
                mma_bf16(sacc[nt], qfl[kc], kfh[nt]);
            }
        }

        // ---- scale + causal mask + online softmax ----
        const bool diag = (kt == qt);
        float rm0 = -1e30f, rm1 = -1e30f;
#pragma unroll
        for (int nt = 0; nt < 8; ++nt) {
            const int cl0 = nt * 8 + 2 * t;
            float s0v = sacc[nt][0] * scale;
            float s1v = sacc[nt][1] * scale;
            float s2v = sacc[nt][2] * scale;
            float s3v = sacc[nt][3] * scale;
            if (diag) {
                if (cl0 > rl0)     s0v = -1e30f;
                if (cl0 + 1 > rl0) s1v = -1e30f;
                if (cl0 > rl1)     s2v = -1e30f;
                if (cl0 + 1 > rl1) s3v = -1e30f;
            }
            sacc[nt][0] = s0v; sacc[nt][1] = s1v;
            sacc[nt][2] = s2v; sacc[nt][3] = s3v;
            rm0 = fmaxf(rm0, fmaxf(s0v, s1v));
            rm1 = fmaxf(rm1, fmaxf(s2v, s3v));
        }
        rm0 = fmaxf(rm0, __shfl_xor_sync(0xffffffffu, rm0, 1));
        rm0 = fmaxf(rm0, __shfl_xor_sync(0xffffffffu, rm0, 2));
        rm1 = fmaxf(rm1, __shfl_xor_sync(0xffffffffu, rm1, 1));
        rm1 = fmaxf(rm1, __shfl_xor_sync(0xffffffffu, rm1, 2));

        const float mn0 = fmaxf(m0, rm0), mn1 = fmaxf(m1, rm1);
        const float a0 = __expf(m0 - mn0), a1 = __expf(m1 - mn1);
        m0 = mn0; m1 = mn1;

        float rs0 = 0.0f, rs1 = 0.0f;
#pragma unroll
        for (int nt = 0; nt < 8; ++nt) {
            const float p0 = __expf(sacc[nt][0] - mn0);
            const float p1 = __expf(sacc[nt][1] - mn0);
            const float p2 = __expf(sacc[nt][2] - mn1);
            const float p3 = __expf(sacc[nt][3] - mn1);
            sacc[nt][0] = p0; sacc[nt][1] = p1;
            sacc[nt][2] = p2; sacc[nt][3] = p3;
            rs0 += p0 + p1;
            rs1 += p2 + p3;
        }
        rs0 += __shfl_xor_sync(0xffffffffu, rs0, 1);
        rs0 += __shfl_xor_sync(0xffffffffu, rs0, 2);
        rs1 += __shfl_xor_sync(0xffffffffu, rs1, 1);
        rs1 += __shfl_xor_sync(0xffffffffu, rs1, 2);
        l0 = l0 * a0 + rs0;
        l1 = l1 * a1 + rs1;

#pragma unroll
        for (int nt = 0; nt < 16; ++nt) {
            O[nt][0] *= a0; O[nt][1] *= a0;
            O[nt][2] *= a1; O[nt][3] *= a1;
        }

        // ---- pack P into A fragments (hi/lo) ----
        uint32_t pah[4][4], pal[4][4];
#pragma unroll
        for (int kc = 0; kc < 4; ++kc) {
            const int n0 = 2 * kc, n1 = 2 * kc + 1;
            split2(sacc[n0][0], sacc[n0][1], pah[kc][0], pal[kc][0]);
            split2(sacc[n0][2], sacc[n0][3], pah[kc][1], pal[kc][1]);
            split2(sacc[n1][0], sacc[n1][1], pah[kc][2], pal[kc][2]);
            split2(sacc[n1][2], sacc[n1][3], pah[kc][3], pal[kc][3]);
        }

        // ---- O += P V (3-pass split) ----
#pragma unroll
        for (int p = 0; p < 8; ++p) {
#pragma unroll
            for (int kc = 0; kc < 4; ++kc) {
                uint32_t vh[2][2], vl[2][2];
                ldsm4(vh[0][0], vh[0][1], vh[1][0], vh[1][1],
                      sb + ASM_VH + p * 16 * VT_STR + bOffV + kc * 32);
                ldsm4(vl[0][0], vl[0][1], vl[1][0], vl[1][1],
                      sb + ASM_VL + p * 16 * VT_STR + bOffV + kc * 32);
                mma_bf16(O[2 * p],     pah[kc], vh[0]);
                mma_bf16(O[2 * p],     pal[kc], vh[0]);
                mma_bf16(O[2 * p],     pah[kc], vl[0]);
                mma_bf16(O[2 * p + 1], pah[kc], vh[1]);
                mma_bf16(O[2 * p + 1], pal[kc], vh[1]);
                mma_bf16(O[2 * p + 1], pah[kc], vl[1]);
            }
        }
    }

    // ---- epilogue: normalize, split, store to ch/cl [MTOT, E] ----
    const int b = bh >> 4, h = bh & 15;
    const float i0 = 1.0f / l0, i1 = 1.0f / l1;
    const int row0 = qt * 64 + wq * 16 + g;
#pragma unroll
    for (int nt = 0; nt < 16; ++nt) {
        const int col = h * D_ + nt * 8 + 2 * t;
        uint32_t hv, lv;
        split2(O[nt][0] * i0, O[nt][1] * i0, hv, lv);
        const size_t o0 = (size_t)(b * S_ + row0) * E_ + col;
        *reinterpret_cast<uint32_t*>(ch + o0) = hv;
        *reinterpret_cast<uint32_t*>(cl + o0) = lv;
        split2(O[nt][2] * i1, O[nt][3] * i1, hv, lv);
        const size_t o1 = (size_t)(b * S_ + row0 + 8) * E_ + col;
        *reinterpret_cast<uint32_t*>(ch + o1) = hv;
        *reinterpret_cast<uint32_t*>(cl + o1) = lv;
    }
}

// ---------------------------------------------------------------------------
extern "C" void kernel_launch(void* const* d_in, const int* in_sizes, int n_in,
                              void* d_out, int out_size)
{
    const float* x    = (const float*)d_in[0];
    const float* wqkv = (const float*)d_in[1];
    const float* bqkv = (const float*)d_in[2];
    const float* wout = (const float*)d_in[3];
    const float* bout = (const float*)d_in[4];
    float* out = (float*)d_out;

    float* qkv;
    __nv_bfloat16 *xh, *xl, *wqh, *wql, *woh, *wol, *ch, *cl;
    __nv_bfloat16 *Qh, *Ql, *Kh, *Kl, *Vth, *Vtl;
    cudaGetSymbolAddress((void**)&qkv, g_qkv);
    cudaGetSymbolAddress((void**)&xh, g_xh);
    cudaGetSymbolAddress((void**)&xl, g_xl);
    cudaGetSymbolAddress((void**)&wqh, g_wqh);
    cudaGetSymbolAddress((void**)&wql, g_wql);
    cudaGetSymbolAddress((void**)&woh, g_woh);
    cudaGetSymbolAddress((void**)&wol, g_wol);
    cudaGetSymbolAddress((void**)&ch, g_ch);
    cudaGetSymbolAddress((void**)&cl, g_cl);
    cudaGetSymbolAddress((void**)&Qh, g_Qh);
    cudaGetSymbolAddress((void**)&Ql, g_Ql);
    cudaGetSymbolAddress((void**)&Kh, g_Kh);
    cudaGetSymbolAddress((void**)&Kl, g_Kl);
    cudaGetSymbolAddress((void**)&Vth, g_Vth);
    cudaGetSymbolAddress((void**)&Vtl, g_Vtl);

    cudaFuncSetAttribute(gemm_hmma_x3,
                         cudaFuncAttributeMaxDynamicSharedMemorySize, GSM_TOTAL);
    cudaFuncSetAttribute(attn_hmma,
                         cudaFuncAttributeMaxDynamicSharedMemorySize, ASM_TOTAL);

    // 0) split inputs/weights
    {
        int n4;
        n4 = MTOT * E_ / 4;
        split_bf16<<<(n4 + 255) / 256, 256>>>(x, xh, xl, n4);
        n4 = N_QKV * E_ / 4;
        split_bf16<<<(n4 + 255) / 256, 256>>>(wqkv, wqh, wql, n4);
        n4 = E_ * E_ / 4;
        split_bf16<<<(n4 + 255) / 256, 256>>>(wout, woh, wol, n4);
    }

    // 1) QKV projection
    gemm_hmma_x3<<<dim3(N_QKV / 128, MTOT / 128), 256, GSM_TOTAL>>>(
        xh, xl, wqh, wql, bqkv, qkv, N_QKV, KDIM);

    // 2) rotary + split Q,K ; transpose + split V
    qk_rope_split<<<(B_ * S_ * H_ * HALF_ + 255) / 256, 256>>>(
        qkv, Qh, Ql, Kh, Kl);
    v_transpose_split<<<dim3(S_ / 32, D_ / 32, BH_), dim3(32, 8)>>>(
        qkv, Vth, Vtl);

    // 3) HMMA flash attention -> ch/cl (bf16 hi/lo)
    attn_hmma<<<dim3(S_ / 64, BH_), 128, ASM_TOTAL>>>(
        Qh, Ql, Kh, Kl, Vth, Vtl, ch, cl);

    // 4) output projection
    gemm_hmma_x3<<<dim3(E_ / 128, MTOT / 128), 256, GSM_TOTAL>>>(
        ch, cl, woh, wol, bout, out, E_, KDIM);
}

// round 7
// speedup vs baseline: 2.5181x; 1.0169x over previous
#include <cuda_runtime.h>
#include <cuda_bf16.h>
#include <math.h>
#include <stdint.h>

#define B_    2
#define S_    2048
#define E_    2048
#define H_    16
#define D_    128
#define HALF_ 64
#define MTOT  (B_ * S_)          // 4096
#define N_QKV (3 * E_)           // 6144
#define KDIM  E_                 // 2048
#define BH_   (B_ * H_)          // 32

// ---------------- scratch (__device__ globals; allocation-free) -------------
__device__ float g_qkv[(size_t)MTOT * 3 * E_];
__device__ __nv_bfloat16 g_xh[(size_t)MTOT * E_],  g_xl[(size_t)MTOT * E_];
__device__ __nv_bfloat16 g_wqh[(size_t)N_QKV * E_], g_wql[(size_t)N_QKV * E_];
__device__ __nv_bfloat16 g_woh[(size_t)E_ * E_],   g_wol[(size_t)E_ * E_];
__device__ __nv_bfloat16 g_ch[(size_t)MTOT * E_],  g_cl[(size_t)MTOT * E_];
__device__ __nv_bfloat16 g_Qh[(size_t)BH_ * S_ * D_], g_Ql[(size_t)BH_ * S_ * D_];
__device__ __nv_bfloat16 g_Kh[(size_t)BH_ * S_ * D_], g_Kl[(size_t)BH_ * S_ * D_];
__device__ __nv_bfloat16 g_Vth[(size_t)BH_ * D_ * S_], g_Vtl[(size_t)BH_ * D_ * S_];

// ---------------- helpers ---------------------------------------------------
__device__ __forceinline__ uint32_t smem_u32(const void* p) {
    uint32_t a;
    asm("{ .reg .u64 t; cvta.to.shared.u64 t, %1; cvt.u32.u64 %0, t; }"
        : "=r"(a) : "l"(p));
    return a;
}

#define CP_ASYNC16(sa, gp) \
    asm volatile("cp.async.cg.shared.global [%0], [%1], 16;" :: "r"(sa), "l"(gp))
#define CP_COMMIT() asm volatile("cp.async.commit_group;" ::: "memory")
#define CP_WAIT(n)  asm volatile("cp.async.wait_group %0;" :: "n"(n) : "memory")

__device__ __forceinline__ void ldsm4(uint32_t& r0, uint32_t& r1, uint32_t& r2,
                                      uint32_t& r3, uint32_t addr) {
    asm volatile("ldmatrix.sync.aligned.m8n8.x4.shared.b16 {%0,%1,%2,%3}, [%4];"
                 : "=r"(r0), "=r"(r1), "=r"(r2), "=r"(r3) : "r"(addr));
}

__device__ __forceinline__ void mma_bf16(float* c, const uint32_t* a,
                                         const uint32_t* b) {
    asm volatile(
        "mma.sync.aligned.m16n8k16.row.col.f32.bf16.bf16.f32 "
        "{%0,%1,%2,%3}, {%4,%5,%6,%7}, {%8,%9}, {%0,%1,%2,%3};"
        : "+f"(c[0]), "+f"(c[1]), "+f"(c[2]), "+f"(c[3])
        : "r"(a[0]), "r"(a[1]), "r"(a[2]), "r"(a[3]), "r"(b[0]), "r"(b[1]));
}

__device__ __forceinline__ void split2(float f0, float f1,
                                       uint32_t& h, uint32_t& l) {
    __nv_bfloat16 h0 = __float2bfloat16(f0), h1 = __float2bfloat16(f1);
    __nv_bfloat162 hp(h0, h1);
    __nv_bfloat162 lp(__float2bfloat16(f0 - __bfloat162float(h0)),
                      __float2bfloat16(f1 - __bfloat162float(h1)));
    h = *reinterpret_cast<uint32_t*>(&hp);
    l = *reinterpret_cast<uint32_t*>(&lp);
}

// ---------------------------------------------------------------------------
// split fp32 -> bf16 hi/lo
// ---------------------------------------------------------------------------
__global__ void __launch_bounds__(256) split_bf16(
    const float* __restrict__ in, __nv_bfloat16* __restrict__ hi,
    __nv_bfloat16* __restrict__ lo, int n4)
{
    const int i = blockIdx.x * blockDim.x + threadIdx.x;
    if (i >= n4) return;
    const float4 v = reinterpret_cast<const float4*>(in)[i];
    uint32_t h0, l0, h1, l1;
    split2(v.x, v.y, h0, l0);
    split2(v.z, v.w, h1, l1);
    uint2 hp = make_uint2(h0, h1), lp = make_uint2(l0, l1);
    reinterpret_cast<uint2*>(hi)[i] = hp;
    reinterpret_cast<uint2*>(lo)[i] = lp;
}

// ---------------------------------------------------------------------------
// HMMA split-bf16 GEMM (unchanged — passing, tensor=60%)
// ---------------------------------------------------------------------------
#define RSTRIDE   80
#define TILE_B    (128 * RSTRIDE)
#define STAGE_B   (4 * TILE_B)
#define GSM_TOTAL (2 * STAGE_B)

__global__ void __launch_bounds__(256) gemm_hmma_x3(
    const __nv_bfloat16* __restrict__ Ah, const __nv_bfloat16* __restrict__ Al,
    const __nv_bfloat16* __restrict__ Wh, const __nv_bfloat16* __restrict__ Wl,
    const float* __restrict__ bias, float* __restrict__ C, int N, int K)
{
    extern __shared__ char smem[];
    const uint32_t sb = smem_u32(smem);

    const int tid  = threadIdx.x;
    const int wid  = tid >> 5;
    const int lane = tid & 31;
    const int wm   = wid & 1;
    const int wn   = wid >> 1;
    const int rowBlk = blockIdx.y * 128;
    const int colBlk = blockIdx.x * 128;

    const int gr0 = tid >> 2;
    const int gc  = (tid & 3) * 16;

    const __nv_bfloat16* gA[2] = { Ah, Al };
    const __nv_bfloat16* gW[2] = { Wh, Wl };

    auto issue_stage = [&](int k0, int stg) {
        const uint32_t s0 = sb + stg * STAGE_B;
#pragma unroll
        for (int t = 0; t < 2; ++t) {
#pragma unroll
            for (int l = 0; l < 2; ++l) {
                const int r = gr0 + l * 64;
                const uint32_t so = r * RSTRIDE + gc;
                CP_ASYNC16(s0 + t * TILE_B + so,
                           gA[t] + (size_t)(rowBlk + r) * K + k0 + (gc >> 1));
                CP_ASYNC16(s0 + (2 + t) * TILE_B + so,
                           gW[t] + (size_t)(colBlk + r) * K + k0 + (gc >> 1));
            }
        }
        CP_COMMIT();
    };

    float acc[4][4][4];
#pragma unroll
    for (int i = 0; i < 4; ++i)
#pragma unroll
        for (int j = 0; j < 4; ++j)
#pragma unroll
            for (int q = 0; q < 4; ++q) acc[i][j][q] = 0.0f;

    const uint32_t aOff = (uint32_t)((wm * 64 + (lane & 15)) * RSTRIDE +
                                     (lane >> 4) * 16);
    const uint32_t bOff = (uint32_t)((wn * 32 + (lane & 7) + ((lane >> 4) << 3)) * RSTRIDE +
                                     ((lane >> 3) & 1) * 16);

    const int NCH = K / 32;
    issue_stage(0, 0);

    for (int c = 0; c < NCH; ++c) {
        if (c + 1 < NCH) issue_stage((c + 1) * 32, (c + 1) & 1);
        if (c + 1 < NCH) { CP_WAIT(1); } else { CP_WAIT(0); }
        __syncthreads();

        const uint32_t s0 = sb + (c & 1) * STAGE_B;
        const uint32_t sAh = s0 + aOff;
        const uint32_t sAl = s0 + TILE_B + aOff;
        const uint32_t sWh = s0 + 2 * TILE_B + bOff;
        const uint32_t sWl = s0 + 3 * TILE_B + bOff;

#pragma unroll
        for (int ks = 0; ks < 2; ++ks) {
            const uint32_t ko = ks * 32;
            uint32_t ah[4][4], al[4][4], wh[4][2], wl[4][2];
#pragma unroll
            for (int mt = 0; mt < 4; ++mt) {
                ldsm4(ah[mt][0], ah[mt][1], ah[mt][2], ah[mt][3],
                      sAh + mt * 16 * RSTRIDE + ko);
                ldsm4(al[mt][0], al[mt][1], al[mt][2], al[mt][3],
                      sAl + mt * 16 * RSTRIDE + ko);
            }
#pragma unroll
            for (int p = 0; p < 2; ++p) {
                ldsm4(wh[2 * p][0], wh[2 * p][1], wh[2 * p + 1][0], wh[2 * p + 1][1],
                      sWh + p * 16 * RSTRIDE + ko);
                ldsm4(wl[2 * p][0], wl[2 * p][1], wl[2 * p + 1][0], wl[2 * p + 1][1],
                      sWl + p * 16 * RSTRIDE + ko);
            }
#pragma unroll
            for (int mt = 0; mt < 4; ++mt)
#pragma unroll
                for (int nt = 0; nt < 4; ++nt) {
                    mma_bf16(acc[mt][nt], ah[mt], wh[nt]);
                    mma_bf16(acc[mt][nt], ah[mt], wl[nt]);
                    mma_bf16(acc[mt][nt], al[mt], wh[nt]);
                }
        }
        __syncthreads();
    }

    const int g = lane >> 2;
    const int t = lane & 3;
#pragma unroll
    for (int mt = 0; mt < 4; ++mt) {
        const int row0 = rowBlk + wm * 64 + mt * 16 + g;
#pragma unroll
        for (int nt = 0; nt < 4; ++nt) {
            const int col = colBlk + wn * 32 + nt * 8 + 2 * t;
            const float b0 = bias[col], b1 = bias[col + 1];
            float2 v0 = make_float2(acc[mt][nt][0] + b0, acc[mt][nt][1] + b1);
            float2 v1 = make_float2(acc[mt][nt][2] + b0, acc[mt][nt][3] + b1);
            *reinterpret_cast<float2*>(C + (size_t)row0 * N + col) = v0;
            *reinterpret_cast<float2*>(C + (size_t)(row0 + 8) * N + col) = v1;
        }
    }
}

// ---------------------------------------------------------------------------
// Fused rotary + split for Q,K: qkv[B,S,3,H,D] fp32 -> Qh/Ql/Kh/Kl [BH,S,D]
// ---------------------------------------------------------------------------
__global__ void __launch_bounds__(256) qk_rope_split(
    const float* __restrict__ qkv,
    __nv_bfloat16* __restrict__ Qh, __nv_bfloat16* __restrict__ Ql,
    __nv_bfloat16* __restrict__ Kh, __nv_bfloat16* __restrict__ Kl)
{
    const int idx = blockIdx.x * blockDim.x + threadIdx.x;
    const int total = B_ * S_ * H_ * HALF_;
    if (idx >= total) return;

    const int dh = idx & (HALF_ - 1);
    const int h  = (idx >> 6) & (H_ - 1);
    const int s  = (idx >> 10) & (S_ - 1);
    const int b  = idx >> 21;

    const double inv = exp(-(double)dh * (log(10000.0) / 64.0));
    const float  f   = (float)((double)s * inv);
    float c, sn;
    sincosf(f, &sn, &c);

    const size_t obase = ((size_t)(b * H_ + h) * S_ + s) * D_;

    {
        const size_t ib = (((size_t)(b * S_ + s) * 3 + 0) * H_ + h) * (size_t)D_;
        const float x1 = qkv[ib + dh], x2 = qkv[ib + dh + HALF_];
        const float y1 = x1 * c - x2 * sn, y2 = x2 * c + x1 * sn;
        __nv_bfloat16 h1 = __float2bfloat16(y1), h2 = __float2bfloat16(y2);
        Qh[obase + dh] = h1;
        Qh[obase + dh + HALF_] = h2;
        Ql[obase + dh] = __float2bfloat16(y1 - __bfloat162float(h1));
        Ql[obase + dh + HALF_] = __float2bfloat16(y2 - __bfloat162float(h2));
    }
    {
        const size_t ib = (((size_t)(b * S_ + s) * 3 + 1) * H_ + h) * (size_t)D_;
        const float x1 = qkv[ib + dh], x2 = qkv[ib + dh + HALF_];
        const float y1 = x1 * c - x2 * sn, y2 = x2 * c + x1 * sn;
        __nv_bfloat16 h1 = __float2bfloat16(y1), h2 = __float2bfloat16(y2);
        Kh[obase + dh] = h1;
        Kh[obase + dh + HALF_] = h2;
        Kl[obase + dh] = __float2bfloat16(y1 - __bfloat162float(h1));
        Kl[obase + dh + HALF_] = __float2bfloat16(y2 - __bfloat162float(h2));
    }
}

// ---------------------------------------------------------------------------
// V transpose + split: qkv comp2 [B,S,H,D] -> Vth/Vtl [BH, D, S]
// ---------------------------------------------------------------------------
__global__ void __launch_bounds__(256) v_transpose_split(
    const float* __restrict__ qkv,
    __nv_bfloat16* __restrict__ Vth, __nv_bfloat16* __restrict__ Vtl)
{
    __shared__ float tile[32][33];
    const int tx = threadIdx.x;
    const int ty = threadIdx.y;
    const int s0 = blockIdx.x * 32;
    const int d0 = blockIdx.y * 32;
    const int bh = blockIdx.z;
    const int b  = bh >> 4;
    const int h  = bh & 15;

#pragma unroll
    for (int i = 0; i < 4; ++i) {
        const int s = s0 + ty + i * 8;
        const int d = d0 + tx;
        tile[ty + i * 8][tx] =
            qkv[(((size_t)(b * S_ + s) * 3 + 2) * H_ + h) * (size_t)D_ + d];
    }
    __syncthreads();

#pragma unroll
    for (int i = 0; i < 4; ++i) {
        const int d = d0 + ty + i * 8;
        const int s = s0 + tx;
        const float v = tile[tx][ty + i * 8];
        const __nv_bfloat16 hv = __float2bfloat16(v);
        const size_t o = ((size_t)bh * D_ + d) * S_ + s;
        Vth[o] = hv;
        Vtl[o] = __float2bfloat16(v - __bfloat162float(hv));
    }
}

// ---------------------------------------------------------------------------
// HMMA flash attention (split-bf16, causal), 2 CTAs/SM.
// Smem: K hi/lo (Q staged here first) + Vt hi/lo = 71680 B.
// ---------------------------------------------------------------------------
#define QK_STR 272
#define VT_STR 144
#define ASM_KH 0
#define ASM_KL (64 * QK_STR)                  // 17408
#define ASM_VH (2 * 64 * QK_STR)              // 34816
#define ASM_VL (2 * 64 * QK_STR + 128 * VT_STR)
#define ASM_TOTAL (2 * 64 * QK_STR + 2 * 128 * VT_STR)   // 71680

__global__ void __launch_bounds__(128, 2) attn_hmma(
    const __nv_bfloat16* __restrict__ Qh, const __nv_bfloat16* __restrict__ Ql,
    const __nv_bfloat16* __restrict__ Kh, const __nv_bfloat16* __restrict__ Kl,
    const __nv_bfloat16* __restrict__ Vth, const __nv_bfloat16* __restrict__ Vtl,
    __nv_bfloat16* __restrict__ ch, __nv_bfloat16* __restrict__ cl)
{
    extern __shared__ char smem[];
    const uint32_t sb = smem_u32(smem);

    const int qt  = gridDim.x - 1 - blockIdx.x;   // long blocks first
    const int bh  = blockIdx.y;
    const int tid = threadIdx.x;
    const int wq  = tid >> 5;
    const int lane = tid & 31;
    const int g   = lane >> 2;
    const int t   = lane & 3;

    const size_t qkBase = (size_t)bh * S_ * D_;
    const size_t vBase  = (size_t)bh * D_ * S_;

    // ---- stage Q tile in K buffer (hi->KH, lo->KL) via cp.async ----
#pragma unroll
    for (int l = 0; l < 8; ++l) {
        const int idx = tid + l * 128;
        const int r = idx >> 4, c = idx & 15;
        const size_t go = qkBase + (size_t)(qt * 64 + r) * D_ + c * 8;
        CP_ASYNC16(sb + ASM_KH + r * QK_STR + c * 16,
                   Qh + go);
        CP_ASYNC16(sb + ASM_KL + r * QK_STR + c * 16,
                   Ql + go);
    }
    CP_COMMIT();
    CP_WAIT(0);
    __syncthreads();

    // ---- preload Q fragments into registers ----
    const uint32_t aOff = (uint32_t)((wq * 16 + (lane & 15)) * QK_STR +
                                     (lane >> 4) * 16);
    uint32_t qfh[8][4], qfl[8][4];
#pragma unroll
    for (int kc = 0; kc < 8; ++kc) {
        ldsm4(qfh[kc][0], qfh[kc][1], qfh[kc][2], qfh[kc][3],
              sb + ASM_KH + aOff + kc * 32);
        ldsm4(qfl[kc][0], qfl[kc][1], qfl[kc][2], qfl[kc][3],
              sb + ASM_KL + aOff + kc * 32);
    }
    __syncthreads();   // Q fragments extracted; K may overwrite the buffer

    const uint32_t bOffK = (uint32_t)(((lane & 7) + ((lane >> 4) << 3)) * QK_STR +
                                      ((lane >> 3) & 1) * 16);
    const uint32_t bOffV = (uint32_t)(((lane & 7) + ((lane >> 4) << 3)) * VT_STR +
                                      ((lane >> 3) & 1) * 16);

    float O[16][4];
#pragma unroll
    for (int nt = 0; nt < 16; ++nt)
#pragma unroll
        for (int q = 0; q < 4; ++q) O[nt][q] = 0.0f;
    float m0 = -1e30f, m1 = -1e30f, l0 = 0.0f, l1 = 0.0f;

    const float scale = 0.08838834764831843f;   // 1/sqrt(128)
    const int rl0 = wq * 16 + g;
    const int rl1 = rl0 + 8;

    for (int kt = 0; kt <= qt; ++kt) {
        // ---- load K (64x128) and Vt (128x64) hi+lo via cp.async ----
#pragma unroll
        for (int l = 0; l < 8; ++l) {
            const int idx = tid + l * 128;
            {
                const int r = idx >> 4, c = idx & 15;
                const size_t go = qkBase + (size_t)(kt * 64 + r) * D_ + c * 8;
                CP_ASYNC16(sb + ASM_KH + r * QK_STR + c * 16, Kh + go);
                CP_ASYNC16(sb + ASM_KL + r * QK_STR + c * 16, Kl + go);
            }
            {
                const int r = idx >> 3, c = idx & 7;
                const size_t go = vBase + (size_t)r * S_ + kt * 64 + c * 8;
                CP_ASYNC16(sb + ASM_VH + r * VT_STR + c * 16, Vth + go);
                CP_ASYNC16(sb + ASM_VL + r * VT_STR + c * 16, Vtl + go);
            }
        }
        CP_COMMIT();
        CP_WAIT(0);
        __syncthreads();

        // ---- S = Q K^T (3-pass split) ----
        float sacc[8][4];
#pragma unroll
        for (int nt = 0; nt < 8; ++nt)
#pragma unroll
            for (int q = 0; q < 4; ++q) sacc[nt][q] = 0.0f;

#pragma unroll
        for (int kc = 0; kc < 8; ++kc) {
            uint32_t kfh[8][2], kfl[8][2];
#pragma unroll
            for (int p = 0; p < 4; ++p) {
                ldsm4(kfh[2 * p][0], kfh[2 * p][1], kfh[2 * p + 1][0], kfh[2 * p + 1][1],
                      sb + ASM_KH + p * 16 * QK_STR + bOffK + kc * 32);
                ldsm4(kfl[2 * p][0], kfl[2 * p][1], kfl[2 * p + 1][0], kfl[2 * p + 1][1],
                      sb + ASM_KL + p * 16 * QK_STR + bOffK + kc * 32);
            }
#pragma unroll
            for (int nt = 0; nt < 8; ++nt) {
                mma_bf16(sacc[nt], qfh[kc], kfh[nt]);
                mma_bf16(sacc[nt], qfh[kc], kfl[nt]);
                mma_bf16(sacc[nt], qfl[kc], kfh[nt]);
            }
        }

        // ---- scale + causal mask + online softmax ----
        const bool diag = (kt == qt);
        float rm0 = -1e30f, rm1 = -1e30f;
#pragma unroll
        for (int nt = 0; nt < 8; ++nt) {
            const int cl0 = nt * 8 + 2 * t;
            float s0v = sacc[nt][0] * scale;
            float s1v = sacc[nt][1] * scale;
            float s2v = sacc[nt][2] * scale;
            float s3v = sacc[nt][3] * scale;
            if (diag) {
                if (cl0 > rl0)     s0v = -1e30f;
                if (cl0 + 1 > rl0) s1v = -1e30f;
                if (cl0 > rl1)     s2v = -1e30f;
                if (cl0 + 1 > rl1) s3v = -1e30f;
            }
            sacc[nt][0] = s0v; sacc[nt][1] = s1v;
            sacc[nt][2] = s2v; sacc[nt][3] = s3v;
            rm0 = fmaxf(rm0, fmaxf(s0v, s1v));
            rm1 = fmaxf(rm1, fmaxf(s2v, s3v));
        }
        rm0 = fmaxf(rm0, __shfl_xor_sync(0xffffffffu, rm0, 1));
        rm0 = fmaxf(rm0, __shfl_xor_sync(0xffffffffu, rm0, 2));
        rm1 = fmaxf(rm1, __shfl_xor_sync(0xffffffffu, rm1, 1));
        rm1 = fmaxf(rm1, __shfl_xor_sync(0xffffffffu, rm1, 2));

        const float mn0 = fmaxf(m0, rm0), mn1 = fmaxf(m1, rm1);
        const float a0 = __expf(m0 - mn0), a1 = __expf(m1 - mn1);
        m0 = mn0; m1 = mn1;

        float rs0 = 0.0f, rs1 = 0.0f;
#pragma unroll
        for (int nt = 0; nt < 8; ++nt) {
            const float p0 = __expf(sacc[nt][0] - mn0);
            const float p1 = __expf(sacc[nt][1] - mn0);
            const float p2 = __expf(sacc[nt][2] - mn1);
            const float p3 = __expf(sacc[nt][3] - mn1);
            sacc[nt][0] = p0; sacc[nt][1] = p1;
            sacc[nt][2] = p2; sacc[nt][3] = p3;
            rs0 += p0 + p1;
            rs1 += p2 + p3;
        }
        rs0 += __shfl_xor_sync(0xffffffffu, rs0, 1);
        rs0 += __shfl_xor_sync(0xffffffffu, rs0, 2);
        rs1 += __shfl_xor_sync(0xffffffffu, rs1, 1);
        rs1 += __shfl_xor_sync(0xffffffffu, rs1, 2);
        l0 = l0 * a0 + rs0;
        l1 = l1 * a1 + rs1;

#pragma unroll
        for (int nt = 0; nt < 16; ++nt) {
            O[nt][0] *= a0; O[nt][1] *= a0;
            O[nt][2] *= a1; O[nt][3] *= a1;
        }

        // ---- pack P into A fragments (hi/lo) ----
        uint32_t pah[4][4], pal[4][4];
#pragma unroll
        for (int kc = 0; kc < 4; ++kc) {
            const int n0 = 2 * kc, n1 = 2 * kc + 1;
            split2(sacc[n0][0], sacc[n0][1], pah[kc][0], pal[kc][0]);
            split2(sacc[n0][2], sacc[n0][3], pah[kc][1], pal[kc][1]);
            split2(sacc[n1][0], sacc[n1][1], pah[kc][2], pal[kc][2]);
            split2(sacc[n1][2], sacc[n1][3], pah[kc][3], pal[kc][3]);
        }

        // ---- O += P V (3-pass split) ----
#pragma unroll
        for (int p = 0; p < 8; ++p) {
#pragma unroll
            for (int kc = 0; kc < 4; ++kc) {
                uint32_t vh[2][2], vl[2][2];
                ldsm4(vh[0][0], vh[0][1], vh[1][0], vh[1][1],
                      sb + ASM_VH + p * 16 * VT_STR + bOffV + kc * 32);
                ldsm4(vl[0][0], vl[0][1], vl[1][0], vl[1][1],
                      sb + ASM_VL + p * 16 * VT_STR + bOffV + kc * 32);
                mma_bf16(O[2 * p],     pah[kc], vh[0]);
                mma_bf16(O[2 * p],     pal[kc], vh[0]);
                mma_bf16(O[2 * p],     pah[kc], vl[0]);
                mma_bf16(O[2 * p + 1], pah[kc], vh[1]);
                mma_bf16(O[2 * p + 1], pal[kc], vh[1]);
                mma_bf16(O[2 * p + 1], pah[kc], vl[1]);
            }
        }
        __syncthreads();   // all reads done before next tile's cp.async stores
    }

    // ---- epilogue: normalize, split, store to ch/cl [MTOT, E] ----
    const int b = bh >> 4, h = bh & 15;
    const float i0 = 1.0f / l0, i1 = 1.0f / l1;
    const int row0 = qt * 64 + wq * 16 + g;
#pragma unroll
    for (int nt = 0; nt < 16; ++nt) {
        const int col = h * D_ + nt * 8 + 2 * t;
        uint32_t hv, lv;
        split2(O[nt][0] * i0, O[nt][1] * i0, hv, lv);
        const size_t o0 = (size_t)(b * S_ + row0) * E_ + col;
        *reinterpret_cast<uint32_t*>(ch + o0) = hv;
        *reinterpret_cast<uint32_t*>(cl + o0) = lv;
        split2(O[nt][2] * i1, O[nt][3] * i1, hv, lv);
        const size_t o1 = (size_t)(b * S_ + row0 + 8) * E_ + col;
        *reinterpret_cast<uint32_t*>(ch + o1) = hv;
        *reinterpret_cast<uint32_t*>(cl + o1) = lv;
    }
}

// ---------------------------------------------------------------------------
extern "C" void kernel_launch(void* const* d_in, const int* in_sizes, int n_in,
                              void* d_out, int out_size)
{
    const float* x    = (const float*)d_in[0];
    const float* wqkv = (const float*)d_in[1];
    const float* bqkv = (const float*)d_in[2];
    const float* wout = (const float*)d_in[3];
    const float* bout = (const float*)d_in[4];
    float* out = (float*)d_out;

    float* qkv;
    __nv_bfloat16 *xh, *xl, *wqh, *wql, *woh, *wol, *ch, *cl;
    __nv_bfloat16 *Qh, *Ql, *Kh, *Kl, *Vth, *Vtl;
    cudaGetSymbolAddress((void**)&qkv, g_qkv);
    cudaGetSymbolAddress((void**)&xh, g_xh);
    cudaGetSymbolAddress((void**)&xl, g_xl);
    cudaGetSymbolAddress((void**)&wqh, g_wqh);
    cudaGetSymbolAddress((void**)&wql, g_wql);
    cudaGetSymbolAddress((void**)&woh, g_woh);
    cudaGetSymbolAddress((void**)&wol, g_wol);
    cudaGetSymbolAddress((void**)&ch, g_ch);
    cudaGetSymbolAddress((void**)&cl, g_cl);
    cudaGetSymbolAddress((void**)&Qh, g_Qh);
    cudaGetSymbolAddress((void**)&Ql, g_Ql);
    cudaGetSymbolAddress((void**)&Kh, g_Kh);
    cudaGetSymbolAddress((void**)&Kl, g_Kl);
    cudaGetSymbolAddress((void**)&Vth, g_Vth);
    cudaGetSymbolAddress((void**)&Vtl, g_Vtl);

    cudaFuncSetAttribute(gemm_hmma_x3,
                         cudaFuncAttributeMaxDynamicSharedMemorySize, GSM_TOTAL);
    cudaFuncSetAttribute(attn_hmma,
                         cudaFuncAttributeMaxDynamicSharedMemorySize, ASM_TOTAL);

    // 0) split inputs/weights
    {
        int n4;
        n4 = MTOT * E_ / 4;
        split_bf16<<<(n4 + 255) / 256, 256>>>(x, xh, xl, n4);
        n4 = N_QKV * E_ / 4;
        split_bf16<<<(n4 + 255) / 256, 256>>>(wqkv, wqh, wql, n4);
        n4 = E_ * E_ / 4;
        split_bf16<<<(n4 + 255) / 256, 256>>>(wout, woh, wol, n4);
    }

    // 1) QKV projection
    gemm_hmma_x3<<<dim3(N_QKV / 128, MTOT / 128), 256, GSM_TOTAL>>>(
        xh, xl, wqh, wql, bqkv, qkv, N_QKV, KDIM);

    // 2) rotary + split Q,K ; transpose + split V
    qk_rope_split<<<(B_ * S_ * H_ * HALF_ + 255) / 256, 256>>>(
        qkv, Qh, Ql, Kh, Kl);
    v_transpose_split<<<dim3(S_ / 32, D_ / 32, BH_), dim3(32, 8)>>>(
        qkv, Vth, Vtl);

    // 3) HMMA flash attention -> ch/cl (bf16 hi/lo)
    attn_hmma<<<dim3(S_ / 64, BH_), 128, ASM_TOTAL>>>(
        Qh, Ql, Kh, Kl, Vth, Vtl, ch, cl);

    // 4) output projection
    gemm_hmma_x3<<<dim3(E_ / 128, MTOT / 128), 256, GSM_TOTAL>>>(
        ch, cl, woh, wol, bout, out, E_, KDIM);
}

// round 8
// speedup vs baseline: 3.3479x; 1.3295x over previous
#include <cuda_runtime.h>
#include <cuda_fp16.h>
#include <math.h>
#include <stdint.h>

#define B_    2
#define S_    2048
#define E_    2048
#define H_    16
#define D_    128
#define HALF_ 64
#define MTOT  (B_ * S_)          // 4096
#define N_QKV (3 * E_)           // 6144
#define KDIM  E_                 // 2048
#define BH_   (B_ * H_)          // 32

// ---------------- scratch (__device__ globals; allocation-free) -------------
__device__ float g_qkv[(size_t)MTOT * 3 * E_];
__device__ __half g_x16[(size_t)MTOT * E_];
__device__ __half g_wqh[(size_t)N_QKV * E_], g_wql[(size_t)N_QKV * E_];
__device__ __half g_woh[(size_t)E_ * E_],   g_wol[(size_t)E_ * E_];
__device__ __half g_c16[(size_t)MTOT * E_];
__device__ __half g_Q16[(size_t)BH_ * S_ * D_];
__device__ __half g_Kh[(size_t)BH_ * S_ * D_], g_Kl[(size_t)BH_ * S_ * D_];
__device__ __half g_Vth[(size_t)BH_ * D_ * S_], g_Vtl[(size_t)BH_ * D_ * S_];

// ---------------- helpers ---------------------------------------------------
__device__ __forceinline__ uint32_t smem_u32(const void* p) {
    uint32_t a;
    asm("{ .reg .u64 t; cvta.to.shared.u64 t, %1; cvt.u32.u64 %0, t; }"
        : "=r"(a) : "l"(p));
    return a;
}

#define CP_ASYNC16(sa, gp) \
    asm volatile("cp.async.cg.shared.global [%0], [%1], 16;" :: "r"(sa), "l"(gp))
#define CP_COMMIT() asm volatile("cp.async.commit_group;" ::: "memory")
#define CP_WAIT(n)  asm volatile("cp.async.wait_group %0;" :: "n"(n) : "memory")

__device__ __forceinline__ void ldsm4(uint32_t& r0, uint32_t& r1, uint32_t& r2,
                                      uint32_t& r3, uint32_t addr) {
    asm volatile("ldmatrix.sync.aligned.m8n8.x4.shared.b16 {%0,%1,%2,%3}, [%4];"
                 : "=r"(r0), "=r"(r1), "=r"(r2), "=r"(r3) : "r"(addr));
}

__device__ __forceinline__ void mma_f16(float* c, const uint32_t* a,
                                        const uint32_t* b) {
    asm volatile(
        "mma.sync.aligned.m16n8k16.row.col.f32.f16.f16.f32 "
        "{%0,%1,%2,%3}, {%4,%5,%6,%7}, {%8,%9}, {%0,%1,%2,%3};"
        : "+f"(c[0]), "+f"(c[1]), "+f"(c[2]), "+f"(c[3])
        : "r"(a[0]), "r"(a[1]), "r"(a[2]), "r"(a[3]), "r"(b[0]), "r"(b[1]));
}

__device__ __forceinline__ uint32_t pack_h2(float f0, float f1) {
    __half2 p = __floats2half2_rn(f0, f1);
    return *reinterpret_cast<uint32_t*>(&p);
}
__device__ __forceinline__ void split2h(float f0, float f1,
                                        uint32_t& h, uint32_t& l) {
    __half h0 = __float2half(f0), h1 = __float2half(f1);
    __half2 hp(h0, h1);
    __half2 lp(__float2half(f0 - __half2float(h0)),
               __float2half(f1 - __half2float(h1)));
    h = *reinterpret_cast<uint32_t*>(&hp);
    l = *reinterpret_cast<uint32_t*>(&lp);
}

// ---------------------------------------------------------------------------
// fp32 -> single fp16 (A operands)
// ---------------------------------------------------------------------------
__global__ void __launch_bounds__(256) to_f16(
    const float* __restrict__ in, __half* __restrict__ o16, int n4)
{
    const int i = blockIdx.x * blockDim.x + threadIdx.x;
    if (i >= n4) return;
    const float4 v = reinterpret_cast<const float4*>(in)[i];
    uint2 p;
    p.x = pack_h2(v.x, v.y);
    p.y = pack_h2(v.z, v.w);
    reinterpret_cast<uint2*>(o16)[i] = p;
}

// ---------------------------------------------------------------------------
// fp32 -> fp16 hi/lo (weight/B operands)
// ---------------------------------------------------------------------------
__global__ void __launch_bounds__(256) split_f16(
    const float* __restrict__ in, __half* __restrict__ hi,
    __half* __restrict__ lo, int n4)
{
    const int i = blockIdx.x * blockDim.x + threadIdx.x;
    if (i >= n4) return;
    const float4 v = reinterpret_cast<const float4*>(in)[i];
    uint32_t h0, l0, h1, l1;
    split2h(v.x, v.y, h0, l0);
    split2h(v.z, v.w, h1, l1);
    reinterpret_cast<uint2*>(hi)[i] = make_uint2(h0, h1);
    reinterpret_cast<uint2*>(lo)[i] = make_uint2(l0, l1);
}

// ---------------------------------------------------------------------------
// HMMA fp16 2-pass GEMM:  C[M,N] = A[M,K] @ W[N,K]^T + bias
//   C_fp32 ≈ A16·Wh^T + A16·Wl^T
// 128x128 tile, BK=32, 8 warps (2m x 4n), cp.async double-buffered.
// ---------------------------------------------------------------------------
#define RSTRIDE   80
#define TILE_B    (128 * RSTRIDE)          // 10240
#define STAGE_B   (3 * TILE_B)             // A, Wh, Wl
#define GSM_TOTAL (2 * STAGE_B)            // 61440

__global__ void __launch_bounds__(256) gemm_hmma_x2(
    const __half* __restrict__ A16,
    const __half* __restrict__ Wh, const __half* __restrict__ Wl,
    const float* __restrict__ bias, float* __restrict__ C, int N, int K)
{
    extern __shared__ char smem[];
    const uint32_t sb = smem_u32(smem);

    const int tid  = threadIdx.x;
    const int wid  = tid >> 5;
    const int lane = tid & 31;
    const int wm   = wid & 1;
    const int wn   = wid >> 1;
    const int rowBlk = blockIdx.y * 128;
    const int colBlk = blockIdx.x * 128;

    const int gr0 = tid >> 2;
    const int gc  = (tid & 3) * 16;

    auto issue_stage = [&](int k0, int stg) {
        const uint32_t s0 = sb + stg * STAGE_B;
#pragma unroll
        for (int l = 0; l < 2; ++l) {
            const int r = gr0 + l * 64;
            const uint32_t so = r * RSTRIDE + gc;
            CP_ASYNC16(s0 + so,
                       A16 + (size_t)(rowBlk + r) * K + k0 + (gc >> 1));
            CP_ASYNC16(s0 + TILE_B + so,
                       Wh + (size_t)(colBlk + r) * K + k0 + (gc >> 1));
            CP_ASYNC16(s0 + 2 * TILE_B + so,
                       Wl + (size_t)(colBlk + r) * K + k0 + (gc >> 1));
        }
        CP_COMMIT();
    };

    float acc[4][4][4];
#pragma unroll
    for (int i = 0; i < 4; ++i)
#pragma unroll
        for (int j = 0; j < 4; ++j)
#pragma unroll
            for (int q = 0; q < 4; ++q) acc[i][j][q] = 0.0f;

    const uint32_t aOff = (uint32_t)((wm * 64 + (lane & 15)) * RSTRIDE +
                                     (lane >> 4) * 16);
    const uint32_t bOff = (uint32_t)((wn * 32 + (lane & 7) + ((lane >> 4) << 3)) * RSTRIDE +
                                     ((lane >> 3) & 1) * 16);

    const int NCH = K / 32;
    issue_stage(0, 0);

    for (int c = 0; c < NCH; ++c) {
        if (c + 1 < NCH) issue_stage((c + 1) * 32, (c + 1) & 1);
        if (c + 1 < NCH) { CP_WAIT(1); } else { CP_WAIT(0); }
        __syncthreads();

        const uint32_t s0 = sb + (c & 1) * STAGE_B;
        const uint32_t sA  = s0 + aOff;
        const uint32_t sWh = s0 + TILE_B + bOff;
        const uint32_t sWl = s0 + 2 * TILE_B + bOff;

#pragma unroll
        for (int ks = 0; ks < 2; ++ks) {
            const uint32_t ko = ks * 32;
            uint32_t a[4][4], wh[4][2], wl[4][2];
#pragma unroll
            for (int mt = 0; mt < 4; ++mt)
                ldsm4(a[mt][0], a[mt][1], a[mt][2], a[mt][3],
                      sA + mt * 16 * RSTRIDE + ko);
#pragma unroll
            for (int p = 0; p < 2; ++p) {
                ldsm4(wh[2 * p][0], wh[2 * p][1], wh[2 * p + 1][0], wh[2 * p + 1][1],
                      sWh + p * 16 * RSTRIDE + ko);
                ldsm4(wl[2 * p][0], wl[2 * p][1], wl[2 * p + 1][0], wl[2 * p + 1][1],
                      sWl + p * 16 * RSTRIDE + ko);
            }
#pragma unroll
            for (int mt = 0; mt < 4; ++mt)
#pragma unroll
                for (int nt = 0; nt < 4; ++nt) {
                    mma_f16(acc[mt][nt], a[mt], wh[nt]);
                    mma_f16(acc[mt][nt], a[mt], wl[nt]);
                }
        }
        __syncthreads();
    }

    const int g = lane >> 2;
    const int t = lane & 3;
#pragma unroll
    for (int mt = 0; mt < 4; ++mt) {
        const int row0 = rowBlk + wm * 64 + mt * 16 + g;
#pragma unroll
        for (int nt = 0; nt < 4; ++nt) {
            const int col = colBlk + wn * 32 + nt * 8 + 2 * t;
            const float b0 = bias[col], b1 = bias[col + 1];
            float2 v0 = make_float2(acc[mt][nt][0] + b0, acc[mt][nt][1] + b1);
            float2 v1 = make_float2(acc[mt][nt][2] + b0, acc[mt][nt][3] + b1);
            *reinterpret_cast<float2*>(C + (size_t)row0 * N + col) = v0;
            *reinterpret_cast<float2*>(C + (size_t)(row0 + 8) * N + col) = v1;
        }
    }
}

// ---------------------------------------------------------------------------
// Fused rotary + convert: qkv[B,S,3,H,D] fp32 -> Q16 [BH,S,D], Kh/Kl [BH,S,D]
// (fp64 phase — measured-safe 2e-5 floor)
// ---------------------------------------------------------------------------
__global__ void __launch_bounds__(256) qk_rope_cvt(
    const float* __restrict__ qkv,
    __half* __restrict__ Q16,
    __half* __restrict__ Kh, __half* __restrict__ Kl)
{
    const int idx = blockIdx.x * blockDim.x + threadIdx.x;
    const int total = B_ * S_ * H_ * HALF_;
    if (idx >= total) return;

    const int dh = idx & (HALF_ - 1);
    const int h  = (idx >> 6) & (H_ - 1);
    const int s  = (idx >> 10) & (S_ - 1);
    const int b  = idx >> 21;

    const double inv = exp(-(double)dh * (log(10000.0) / 64.0));
    const float  f   = (float)((double)s * inv);
    float c, sn;
    sincosf(f, &sn, &c);

    const size_t obase = ((size_t)(b * H_ + h) * S_ + s) * D_;

    // q (comp 0) -> single fp16
    {
        const size_t ib = (((size_t)(b * S_ + s) * 3 + 0) * H_ + h) * (size_t)D_;
        const float x1 = qkv[ib + dh], x2 = qkv[ib + dh + HALF_];
        Q16[obase + dh]         = __float2half(x1 * c - x2 * sn);
        Q16[obase + dh + HALF_] = __float2half(x2 * c + x1 * sn);
    }
    // k (comp 1) -> hi/lo
    {
        const size_t ib = (((size_t)(b * S_ + s) * 3 + 1) * H_ + h) * (size_t)D_;
        const float x1 = qkv[ib + dh], x2 = qkv[ib + dh + HALF_];
        const float y1 = x1 * c - x2 * sn, y2 = x2 * c + x1 * sn;
        __half h1 = __float2half(y1), h2 = __float2half(y2);
        Kh[obase + dh] = h1;
        Kh[obase + dh + HALF_] = h2;
        Kl[obase + dh] = __float2half(y1 - __half2float(h1));
        Kl[obase + dh + HALF_] = __float2half(y2 - __half2float(h2));
    }
}

// ---------------------------------------------------------------------------
// V transpose + split: qkv comp2 [B,S,H,D] -> Vth/Vtl [BH, D, S]
// ---------------------------------------------------------------------------
__global__ void __launch_bounds__(256) v_transpose_split(
    const float* __restrict__ qkv,
    __half* __restrict__ Vth, __half* __restrict__ Vtl)
{
    __shared__ float tile[32][33];
    const int tx = threadIdx.x;
    const int ty = threadIdx.y;
    const int s0 = blockIdx.x * 32;
    const int d0 = blockIdx.y * 32;
    const int bh = blockIdx.z;
    const int b  = bh >> 4;
    const int h  = bh & 15;

#pragma unroll
    for (int i = 0; i < 4; ++i) {
        const int s = s0 + ty + i * 8;
        const int d = d0 + tx;
        tile[ty + i * 8][tx] =
            qkv[(((size_t)(b * S_ + s) * 3 + 2) * H_ + h) * (size_t)D_ + d];
    }
    __syncthreads();

#pragma unroll
    for (int i = 0; i < 4; ++i) {
        const int d = d0 + ty + i * 8;
        const int s = s0 + tx;
        const float v = tile[tx][ty + i * 8];
        const __half hv = __float2half(v);
        const size_t o = ((size_t)bh * D_ + d) * S_ + s;
        Vth[o] = hv;
        Vtl[o] = __float2half(v - __half2float(hv));
    }
}

// ---------------------------------------------------------------------------
// HMMA fp16 2-pass flash attention (causal), 2 CTAs/SM.
// S = Q16·(Kh+Kl)^T ; O += P16·(Vh+Vl).  Writes ctx as single fp16.
// ---------------------------------------------------------------------------
#define QK_STR 272
#define VT_STR 144
#define ASM_KH 0
#define ASM_KL (64 * QK_STR)
#define ASM_VH (2 * 64 * QK_STR)
#define ASM_VL (2 * 64 * QK_STR + 128 * VT_STR)
#define ASM_TOTAL (2 * 64 * QK_STR + 2 * 128 * VT_STR)   // 71680

__global__ void __launch_bounds__(128, 2) attn_hmma(
    const __half* __restrict__ Q16,
    const __half* __restrict__ Kh, const __half* __restrict__ Kl,
    const __half* __restrict__ Vth, const __half* __restrict__ Vtl,
    __half* __restrict__ c16)
{
    extern __shared__ char smem[];
    const uint32_t sb = smem_u32(smem);

    const int qt  = gridDim.x - 1 - blockIdx.x;   // long blocks first
    const int bh  = blockIdx.y;
    const int tid = threadIdx.x;
    const int wq  = tid >> 5;
    const int lane = tid & 31;
    const int g   = lane >> 2;
    const int t   = lane & 3;

    const size_t qkBase = (size_t)bh * S_ * D_;
    const size_t vBase  = (size_t)bh * D_ * S_;

    // ---- stage Q tile in K-hi buffer via cp.async ----
#pragma unroll
    for (int l = 0; l < 8; ++l) {
        const int idx = tid + l * 128;
        const int r = idx >> 4, c = idx & 15;
        const size_t go = qkBase + (size_t)(qt * 64 + r) * D_ + c * 8;
        CP_ASYNC16(sb + ASM_KH + r * QK_STR + c * 16, Q16 + go);
    }
    CP_COMMIT();
    CP_WAIT(0);
    __syncthreads();

    // ---- preload Q fragments ----
    const uint32_t aOff = (uint32_t)((wq * 16 + (lane & 15)) * QK_STR +
                                     (lane >> 4) * 16);
    uint32_t qf[8][4];
#pragma unroll
    for (int kc = 0; kc < 8; ++kc)
        ldsm4(qf[kc][0], qf[kc][1], qf[kc][2], qf[kc][3],
              sb + ASM_KH + aOff + kc * 32);
    __syncthreads();   // Q extracted; K may overwrite

    const uint32_t bOffK = (uint32_t)(((lane & 7) + ((lane >> 4) << 3)) * QK_STR +
                                      ((lane >> 3) & 1) * 16);
    const uint32_t bOffV = (uint32_t)(((lane & 7) + ((lane >> 4) << 3)) * VT_STR +
                                      ((lane >> 3) & 1) * 16);

    float O[16][4];
#pragma unroll
    for (int nt = 0; nt < 16; ++nt)
#pragma unroll
        for (int q = 0; q < 4; ++q) O[nt][q] = 0.0f;
    float m0 = -1e30f, m1 = -1e30f, l0 = 0.0f, l1 = 0.0f;

    const float scale = 0.08838834764831843f;
    const int rl0 = wq * 16 + g;
    const int rl1 = rl0 + 8;

    for (int kt = 0; kt <= qt; ++kt) {
        // ---- load K hi/lo (64x128) and Vt hi/lo (128x64) via cp.async ----
#pragma unroll
        for (int l = 0; l < 8; ++l) {
            const int idx = tid + l * 128;
            {
                const int r = idx >> 4, c = idx & 15;
                const size_t go = qkBase + (size_t)(kt * 64 + r) * D_ + c * 8;
                CP_ASYNC16(sb + ASM_KH + r * QK_STR + c * 16, Kh + go);
                CP_ASYNC16(sb + ASM_KL + r * QK_STR + c * 16, Kl + go);
            }
            {
                const int r = idx >> 3, c = idx & 7;
                const size_t go = vBase + (size_t)r * S_ + kt * 64 + c * 8;
                CP_ASYNC16(sb + ASM_VH + r * VT_STR + c * 16, Vth + go);
                CP_ASYNC16(sb + ASM_VL + r * VT_STR + c * 16, Vtl + go);
            }
        }
        CP_COMMIT();
        CP_WAIT(0);
        __syncthreads();

        // ---- S = Q16 (Kh + Kl)^T ----
        float sacc[8][4];
#pragma unroll
        for (int nt = 0; nt < 8; ++nt)
#pragma unroll
            for (int q = 0; q < 4; ++q) sacc[nt][q] = 0.0f;

#pragma unroll
        for (int kc = 0; kc < 8; ++kc) {
            uint32_t kfh[8][2], kfl[8][2];
#pragma unroll
            for (int p = 0; p < 4; ++p) {
                ldsm4(kfh[2 * p][0], kfh[2 * p][1], kfh[2 * p + 1][0], kfh[2 * p + 1][1],
                      sb + ASM_KH + p * 16 * QK_STR + bOffK + kc * 32);
                ldsm4(kfl[2 * p][0], kfl[2 * p][1], kfl[2 * p + 1][0], kfl[2 * p + 1][1],
                      sb + ASM_KL + p * 16 * QK_STR + bOffK + kc * 32);
            }
#pragma unroll
            for (int nt = 0; nt < 8; ++nt) {
                mma_f16(sacc[nt], qf[kc], kfh[nt]);
                mma_f16(sacc[nt], qf[kc], kfl[nt]);
            }
        }

        // ---- scale + causal mask + online softmax ----
        const bool diag = (kt == qt);
        float rm0 = -1e30f, rm1 = -1e30f;
#pragma unroll
        for (int nt = 0; nt < 8; ++nt) {
            const int cl0 = nt * 8 + 2 * t;
            float s0v = sacc[nt][0] * scale;
            float s1v = sacc[nt][1] * scale;
            float s2v = sacc[nt][2] * scale;
            float s3v = sacc[nt][3] * scale;
            if (diag) {
                if (cl0 > rl0)     s0v = -1e30f;
                if (cl0 + 1 > rl0) s1v = -1e30f;
                if (cl0 > rl1)     s2v = -1e30f;
                if (cl0 + 1 > rl1) s3v = -1e30f;
            }
            sacc[nt][0] = s0v; sacc[nt][1] = s1v;
            sacc[nt][2] = s2v; sacc[nt][3] = s3v;
            rm0 = fmaxf(rm0, fmaxf(s0v, s1v));
            rm1 = fmaxf(rm1, fmaxf(s2v, s3v));
        }
        rm0 = fmaxf(rm0, __shfl_xor_sync(0xffffffffu, rm0, 1));
        rm0 = fmaxf(rm0, __shfl_xor_sync(0xffffffffu, rm0, 2));
        rm1 = fmaxf(rm1, __shfl_xor_sync(0xffffffffu, rm1, 1));
        rm1 = fmaxf(rm1, __shfl_xor_sync(0xffffffffu, rm1, 2));

        const float mn0 = fmaxf(m0, rm0), mn1 = fmaxf(m1, rm1);
        const float a0 = __expf(m0 - mn0), a1 = __expf(m1 - mn1);
        m0 = mn0; m1 = mn1;

        float rs0 = 0.0f, rs1 = 0.0f;
#pragma unroll
        for (int nt = 0; nt < 8; ++nt) {
            const float p0 = __expf(sacc[nt][0] - mn0);
            const float p1 = __expf(sacc[nt][1] - mn0);
            const float p2 = __expf(sacc[nt][2] - mn1);
            const float p3 = __expf(sacc[nt][3] - mn1);
            sacc[nt][0] = p0; sacc[nt][1] = p1;
            sacc[nt][2] = p2; sacc[nt][3] = p3;
            rs0 += p0 + p1;
            rs1 += p2 + p3;
        }
        rs0 += __shfl_xor_sync(0xffffffffu, rs0, 1);
        rs0 += __shfl_xor_sync(0xffffffffu, rs0, 2);
        rs1 += __shfl_xor_sync(0xffffffffu, rs1, 1);
        rs1 += __shfl_xor_sync(0xffffffffu, rs1, 2);
        l0 = l0 * a0 + rs0;
        l1 = l1 * a1 + rs1;

#pragma unroll
        for (int nt = 0; nt < 16; ++nt) {
            O[nt][0] *= a0; O[nt][1] *= a0;
            O[nt][2] *= a1; O[nt][3] *= a1;
        }

        // ---- pack P into single-fp16 A fragments ----
        uint32_t pf[4][4];
#pragma unroll
        for (int kc = 0; kc < 4; ++kc) {
            const int n0 = 2 * kc, n1 = 2 * kc + 1;
            pf[kc][0] = pack_h2(sacc[n0][0], sacc[n0][1]);
            pf[kc][1] = pack_h2(sacc[n0][2], sacc[n0][3]);
            pf[kc][2] = pack_h2(sacc[n1][0], sacc[n1][1]);
            pf[kc][3] = pack_h2(sacc[n1][2], sacc[n1][3]);
        }

        // ---- O += P16 (Vh + Vl) ----
#pragma unroll
        for (int p = 0; p < 8; ++p) {
#pragma unroll
            for (int kc = 0; kc < 4; ++kc) {
                uint32_t vh[2][2], vl[2][2];
                ldsm4(vh[0][0], vh[0][1], vh[1][0], vh[1][1],
                      sb + ASM_VH + p * 16 * VT_STR + bOffV + kc * 32);
                ldsm4(vl[0][0], vl[0][1], vl[1][0], vl[1][1],
                      sb + ASM_VL + p * 16 * VT_STR + bOffV + kc * 32);
                mma_f16(O[2 * p],     pf[kc], vh[0]);
                mma_f16(O[2 * p],     pf[kc], vl[0]);
                mma_f16(O[2 * p + 1], pf[kc], vh[1]);
                mma_f16(O[2 * p + 1], pf[kc], vl[1]);
            }
        }
        __syncthreads();
    }

    // ---- epilogue: normalize, convert to fp16, store ctx [MTOT, E] ----
    const int b = bh >> 4, h = bh & 15;
    const float i0 = 1.0f / l0, i1 = 1.0f / l1;
    const int row0 = qt * 64 + wq * 16 + g;
#pragma unroll
    for (int nt = 0; nt < 16; ++nt) {
        const int col = h * D_ + nt * 8 + 2 * t;
        const size_t o0 = (size_t)(b * S_ + row0) * E_ + col;
        const size_t o1 = (size_t)(b * S_ + row0 + 8) * E_ + col;
        *reinterpret_cast<uint32_t*>(c16 + o0) = pack_h2(O[nt][0] * i0, O[nt][1] * i0);
        *reinterpret_cast<uint32_t*>(c16 + o1) = pack_h2(O[nt][2] * i1, O[nt][3] * i1);
    }
}

// ---------------------------------------------------------------------------
extern "C" void kernel_launch(void* const* d_in, const int* in_sizes, int n_in,
                              void* d_out, int out_size)
{
    const float* x    = (const float*)d_in[0];
    const float* wqkv = (const float*)d_in[1];
    const float* bqkv = (const float*)d_in[2];
    const float* wout = (const float*)d_in[3];
    const float* bout = (const float*)d_in[4];
    float* out = (float*)d_out;

    float* qkv;
    __half *x16, *wqh, *wql, *woh, *wol, *c16;
    __half *Q16, *Kh, *Kl, *Vth, *Vtl;
    cudaGetSymbolAddress((void**)&qkv, g_qkv);
    cudaGetSymbolAddress((void**)&x16, g_x16);
    cudaGetSymbolAddress((void**)&wqh, g_wqh);
    cudaGetSymbolAddress((void**)&wql, g_wql);
    cudaGetSymbolAddress((void**)&woh, g_woh);
    cudaGetSymbolAddress((void**)&wol, g_wol);
    cudaGetSymbolAddress((void**)&c16, g_c16);
    cudaGetSymbolAddress((void**)&Q16, g_Q16);
    cudaGetSymbolAddress((void**)&Kh, g_Kh);
    cudaGetSymbolAddress((void**)&Kl, g_Kl);
    cudaGetSymbolAddress((void**)&Vth, g_Vth);
    cudaGetSymbolAddress((void**)&Vtl, g_Vtl);

    cudaFuncSetAttribute(gemm_hmma_x2,
                         cudaFuncAttributeMaxDynamicSharedMemorySize, GSM_TOTAL);
    cudaFuncSetAttribute(attn_hmma,
                         cudaFuncAttributeMaxDynamicSharedMemorySize, ASM_TOTAL);

    // 0) converts
    {
        int n4;
        n4 = MTOT * E_ / 4;
        to_f16<<<(n4 + 255) / 256, 256>>>(x, x16, n4);
        n4 = N_QKV * E_ / 4;
        split_f16<<<(n4 + 255) / 256, 256>>>(wqkv, wqh, wql, n4);
        n4 = E_ * E_ / 4;
        split_f16<<<(n4 + 255) / 256, 256>>>(wout, woh, wol, n4);
    }

    // 1) QKV projection
    gemm_hmma_x2<<<dim3(N_QKV / 128, MTOT / 128), 256, GSM_TOTAL>>>(
        x16, wqh, wql, bqkv, qkv, N_QKV, KDIM);

    // 2) rotary + convert Q,K ; transpose + split V
    qk_rope_cvt<<<(B_ * S_ * H_ * HALF_ + 255) / 256, 256>>>(
        qkv, Q16, Kh, Kl);
    v_transpose_split<<<dim3(S_ / 32, D_ / 32, BH_), dim3(32, 8)>>>(
        qkv, Vth, Vtl);

    // 3) fp16 flash attention -> c16
    attn_hmma<<<dim3(S_ / 64, BH_), 128, ASM_TOTAL>>>(
        Q16, Kh, Kl, Vth, Vtl, c16);

    // 4) output projection
    gemm_hmma_x2<<<dim3(E_ / 128, MTOT / 128), 256, GSM_TOTAL>>>(
        c16, woh, wol, bout, out, E_, KDIM);
}

// round 10
// speedup vs baseline: 3.3763x; 1.0085x over previous
#include <cuda_runtime.h>
#include <cuda_fp16.h>
#include <math.h>
#include <stdint.h>

#define B_    2
#define S_    2048
#define E_    2048
#define H_    16
#define D_    128
#define HALF_ 64
#define MTOT  (B_ * S_)          // 4096
#define N_QKV (3 * E_)           // 6144
#define KDIM  E_                 // 2048
#define BH_   (B_ * H_)          // 32

// ---------------- scratch (__device__ globals; allocation-free) -------------
__device__ float g_qkv[(size_t)MTOT * 3 * E_];
__device__ __half g_x16[(size_t)MTOT * E_];
__device__ __half g_wqh[(size_t)N_QKV * E_], g_wql[(size_t)N_QKV * E_];
__device__ __half g_woh[(size_t)E_ * E_],   g_wol[(size_t)E_ * E_];
__device__ __half g_c16[(size_t)MTOT * E_];
__device__ __half g_Q16[(size_t)BH_ * S_ * D_];
__device__ __half g_Kh[(size_t)BH_ * S_ * D_], g_Kl[(size_t)BH_ * S_ * D_];
__device__ __half g_Vt16[(size_t)BH_ * D_ * S_];

// ---------------- helpers ---------------------------------------------------
__device__ __forceinline__ uint32_t smem_u32(const void* p) {
    uint32_t a;
    asm("{ .reg .u64 t; cvta.to.shared.u64 t, %1; cvt.u32.u64 %0, t; }"
        : "=r"(a) : "l"(p));
    return a;
}

#define CP_ASYNC16(sa, gp) \
    asm volatile("cp.async.cg.shared.global [%0], [%1], 16;" :: "r"(sa), "l"(gp))
#define CP_COMMIT() asm volatile("cp.async.commit_group;" ::: "memory")
#define CP_WAIT(n)  asm volatile("cp.async.wait_group %0;" :: "n"(n) : "memory")

__device__ __forceinline__ void ldsm4(uint32_t& r0, uint32_t& r1, uint32_t& r2,
                                      uint32_t& r3, uint32_t addr) {
    asm volatile("ldmatrix.sync.aligned.m8n8.x4.shared.b16 {%0,%1,%2,%3}, [%4];"
                 : "=r"(r0), "=r"(r1), "=r"(r2), "=r"(r3) : "r"(addr));
}

__device__ __forceinline__ void mma_f16(float* c, const uint32_t* a,
                                        const uint32_t* b) {
    asm volatile(
        "mma.sync.aligned.m16n8k16.row.col.f32.f16.f16.f32 "
        "{%0,%1,%2,%3}, {%4,%5,%6,%7}, {%8,%9}, {%0,%1,%2,%3};"
        : "+f"(c[0]), "+f"(c[1]), "+f"(c[2]), "+f"(c[3])
        : "r"(a[0]), "r"(a[1]), "r"(a[2]), "r"(a[3]), "r"(b[0]), "r"(b[1]));
}

__device__ __forceinline__ uint32_t pack_h2(float f0, float f1) {
    __half2 p = __floats2half2_rn(f0, f1);
    return *reinterpret_cast<uint32_t*>(&p);
}
__device__ __forceinline__ void split2h(float f0, float f1,
                                        uint32_t& h, uint32_t& l) {
    __half h0 = __float2half(f0), h1 = __float2half(f1);
    __half2 hp(h0, h1);
    __half2 lp(__float2half(f0 - __half2float(h0)),
               __float2half(f1 - __half2float(h1)));
    h = *reinterpret_cast<uint32_t*>(&hp);
    l = *reinterpret_cast<uint32_t*>(&lp);
}

// ---------------------------------------------------------------------------
// fp32 -> single fp16 (A operands)
// ---------------------------------------------------------------------------
__global__ void __launch_bounds__(256) to_f16(
    const float* __restrict__ in, __half* __restrict__ o16, int n4)
{
    const int i = blockIdx.x * blockDim.x + threadIdx.x;
    if (i >= n4) return;
    const float4 v = reinterpret_cast<const float4*>(in)[i];
    uint2 p;
    p.x = pack_h2(v.x, v.y);
    p.y = pack_h2(v.z, v.w);
    reinterpret_cast<uint2*>(o16)[i] = p;
}

// ---------------------------------------------------------------------------
// fp32 -> fp16 hi/lo (weight/B operands)
// ---------------------------------------------------------------------------
__global__ void __launch_bounds__(256) split_f16(
    const float* __restrict__ in, __half* __restrict__ hi,
    __half* __restrict__ lo, int n4)
{
    const int i = blockIdx.x * blockDim.x + threadIdx.x;
    if (i >= n4) return;
    const float4 v = reinterpret_cast<const float4*>(in)[i];
    uint32_t h0, l0, h1, l1;
    split2h(v.x, v.y, h0, l0);
    split2h(v.z, v.w, h1, l1);
    reinterpret_cast<uint2*>(hi)[i] = make_uint2(h0, h1);
    reinterpret_cast<uint2*>(lo)[i] = make_uint2(l0, l1);
}

// ---------------------------------------------------------------------------
// HMMA fp16 2-pass GEMM:  C[M,N] = A16[M,K] @ (Wh+Wl)[N,K]^T + bias
// 128x128 tile, BK=32, 8 warps (2m x 4n). Hi sweep, then lo sweep
// (dependency distance 16 MMAs -> no accumulator RAW stalls).
// ---------------------------------------------------------------------------
#define RSTRIDE   80
#define TILE_B    (128 * RSTRIDE)          // 10240
#define STAGE_B   (3 * TILE_B)             // A, Wh, Wl
#define GSM_TOTAL (2 * STAGE_B)            // 61440

__global__ void __launch_bounds__(256) gemm_hmma_x2(
    const __half* __restrict__ A16,
    const __half* __restrict__ Wh, const __half* __restrict__ Wl,
    const float* __restrict__ bias, float* __restrict__ C, int N, int K)
{
    extern __shared__ char smem[];
    const uint32_t sb = smem_u32(smem);

    const int tid  = threadIdx.x;
    const int wid  = tid >> 5;
    const int lane = tid & 31;
    const int wm   = wid & 1;
    const int wn   = wid >> 1;
    const int rowBlk = blockIdx.y * 128;
    const int colBlk = blockIdx.x * 128;

    const int gr0 = tid >> 2;
    const int gc  = (tid & 3) * 16;

    auto issue_stage = [&](int k0, int stg) {
        const uint32_t s0 = sb + stg * STAGE_B;
#pragma unroll
        for (int l = 0; l < 2; ++l) {
            const int r = gr0 + l * 64;
            const uint32_t so = r * RSTRIDE + gc;
            CP_ASYNC16(s0 + so,
                       A16 + (size_t)(rowBlk + r) * K + k0 + (gc >> 1));
            CP_ASYNC16(s0 + TILE_B + so,
                       Wh + (size_t)(colBlk + r) * K + k0 + (gc >> 1));
            CP_ASYNC16(s0 + 2 * TILE_B + so,
                       Wl + (size_t)(colBlk + r) * K + k0 + (gc >> 1));
        }
        CP_COMMIT();
    };

    float acc[4][4][4];
#pragma unroll
    for (int i = 0; i < 4; ++i)
#pragma unroll
        for (int j = 0; j < 4; ++j)
#pragma unroll
            for (int q = 0; q < 4; ++q) acc[i][j][q] = 0.0f;

    const uint32_t aOff = (uint32_t)((wm * 64 + (lane & 15)) * RSTRIDE +
                                     (lane >> 4) * 16);
    const uint32_t bOff = (uint32_t)((wn * 32 + (lane & 7) + ((lane >> 4) << 3)) * RSTRIDE +
                                     ((lane >> 3) & 1) * 16);

    const int NCH = K / 32;
    issue_stage(0, 0);

    for (int c = 0; c < NCH; ++c) {
        if (c + 1 < NCH) issue_stage((c + 1) * 32, (c + 1) & 1);
        if (c + 1 < NCH) { CP_WAIT(1); } else { CP_WAIT(0); }
        __syncthreads();

        const uint32_t s0 = sb + (c & 1) * STAGE_B;
        const uint32_t sA  = s0 + aOff;
        const uint32_t sWh = s0 + TILE_B + bOff;
        const uint32_t sWl = s0 + 2 * TILE_B + bOff;

#pragma unroll
        for (int ks = 0; ks < 2; ++ks) {
            const uint32_t ko = ks * 32;
            uint32_t a[4][4], wh[4][2], wl[4][2];
#pragma unroll
            for (int mt = 0; mt < 4; ++mt)
                ldsm4(a[mt][0], a[mt][1], a[mt][2], a[mt][3],
                      sA + mt * 16 * RSTRIDE + ko);
#pragma unroll
            for (int p = 0; p < 2; ++p) {
                ldsm4(wh[2 * p][0], wh[2 * p][1], wh[2 * p + 1][0], wh[2 * p + 1][1],
                      sWh + p * 16 * RSTRIDE + ko);
                ldsm4(wl[2 * p][0], wl[2 * p][1], wl[2 * p + 1][0], wl[2 * p + 1][1],
                      sWl + p * 16 * RSTRIDE + ko);
            }
            // hi sweep (16 independent MMAs), then lo sweep
#pragma unroll
            for (int mt = 0; mt < 4; ++mt)
#pragma unroll
                for (int nt = 0; nt < 4; ++nt)
                    mma_f16(acc[mt][nt], a[mt], wh[nt]);
#pragma unroll
            for (int mt = 0; mt < 4; ++mt)
#pragma unroll
                for (int nt = 0; nt < 4; ++nt)
                    mma_f16(acc[mt][nt], a[mt], wl[nt]);
        }
        __syncthreads();
    }

    const int g = lane >> 2;
    const int t = lane & 3;
#pragma unroll
    for (int mt = 0; mt < 4; ++mt) {
        const int row0 = rowBlk + wm * 64 + mt * 16 + g;
#pragma unroll
        for (int nt = 0; nt < 4; ++nt) {
            const int col = colBlk + wn * 32 + nt * 8 + 2 * t;
            const float b0 = bias[col], b1 = bias[col + 1];
            float2 v0 = make_float2(acc[mt][nt][0] + b0, acc[mt][nt][1] + b1);
            float2 v1 = make_float2(acc[mt][nt][2] + b0, acc[mt][nt][3] + b1);
            *reinterpret_cast<float2*>(C + (size_t)row0 * N + col) = v0;
            *reinterpret_cast<float2*>(C + (size_t)(row0 + 8) * N + col) = v1;
        }
    }
}

// ---------------------------------------------------------------------------
// Fused rotary + convert: qkv[B,S,3,H,D] fp32 -> Q16, Kh/Kl [BH,S,D]
// ---------------------------------------------------------------------------
__global__ void __launch_bounds__(256) qk_rope_cvt(
    const float* __restrict__ qkv,
    __half* __restrict__ Q16,
    __half* __restrict__ Kh, __half* __restrict__ Kl)
{
    const int idx = blockIdx.x * blockDim.x + threadIdx.x;
    const int total = B_ * S_ * H_ * HALF_;
    if (idx >= total) return;

    const int dh = idx & (HALF_ - 1);
    const int h  = (idx >> 6) & (H_ - 1);
    const int s  = (idx >> 10) & (S_ - 1);
    const int b  = idx >> 21;

    const double inv = exp(-(double)dh * (log(10000.0) / 64.0));
    const float  f   = (float)((double)s * inv);
    float c, sn;
    sincosf(f, &sn, &c);

    const size_t obase = ((size_t)(b * H_ + h) * S_ + s) * D_;

    {
        const size_t ib = (((size_t)(b * S_ + s) * 3 + 0) * H_ + h) * (size_t)D_;
        const float x1 = qkv[ib + dh], x2 = qkv[ib + dh + HALF_];
        Q16[obase + dh]         = __float2half(x1 * c - x2 * sn);
        Q16[obase + dh + HALF_] = __float2half(x2 * c + x1 * sn);
    }
    {
        const size_t ib = (((size_t)(b * S_ + s) * 3 + 1) * H_ + h) * (size_t)D_;
        const float x1 = qkv[ib + dh], x2 = qkv[ib + dh + HALF_];
        const float y1 = x1 * c - x2 * sn, y2 = x2 * c + x1 * sn;
        __half h1 = __float2half(y1), h2 = __float2half(y2);
        Kh[obase + dh] = h1;
        Kh[obase + dh + HALF_] = h2;
        Kl[obase + dh] = __float2half(y1 - __half2float(h1));
        Kl[obase + dh + HALF_] = __float2half(y2 - __half2float(h2));
    }
}

// ---------------------------------------------------------------------------
// V transpose: qkv comp2 [B,S,H,D] -> Vt16 [BH, D, S]  (single fp16)
// ---------------------------------------------------------------------------
__global__ void __launch_bounds__(256) v_transpose(
    const float* __restrict__ qkv, __half* __restrict__ Vt16)
{
    __shared__ float tile[32][33];
    const int tx = threadIdx.x;
    const int ty = threadIdx.y;
    const int s0 = blockIdx.x * 32;
    const int d0 = blockIdx.y * 32;
    const int bh = blockIdx.z;
    const int b  = bh >> 4;
    const int h  = bh & 15;

#pragma unroll
    for (int i = 0; i < 4; ++i) {
        const int s = s0 + ty + i * 8;
        const int d = d0 + tx;
        tile[ty + i * 8][tx] =
            qkv[(((size_t)(b * S_ + s) * 3 + 2) * H_ + h) * (size_t)D_ + d];
    }
    __syncthreads();

#pragma unroll
    for (int i = 0; i < 4; ++i) {
        const int d = d0 + ty + i * 8;
        const int s = s0 + tx;
        Vt16[((size_t)bh * D_ + d) * S_ + s] = __float2half(tile[tx][ty + i * 8]);
    }
}

// ---------------------------------------------------------------------------
// HMMA fp16 flash attention (causal), 3 CTAs/SM.
// S = Q16·(Kh+Kl)^T (hi sweep then lo sweep) ; O += P16·V16 (single pass).
// ---------------------------------------------------------------------------
#define QK_STR 272
#define VT_STR 144
#define ASM_KH 0
#define ASM_KL (64 * QK_STR)
#define ASM_VH (2 * 64 * QK_STR)
#define ASM_TOTAL (2 * 64 * QK_STR + 128 * VT_STR)   // 53248

__global__ void __launch_bounds__(128, 3) attn_hmma(
    const __half* __restrict__ Q16,
    const __half* __restrict__ Kh, const __half* __restrict__ Kl,
    const __half* __restrict__ Vt16,
    __half* __restrict__ c16)
{
    extern __shared__ char smem[];
    const uint32_t sb = smem_u32(smem);

    const int qt  = gridDim.x - 1 - blockIdx.x;   // long blocks first
    const int bh  = blockIdx.y;
    const int tid = threadIdx.x;
    const int wq  = tid >> 5;
    const int lane = tid & 31;
    const int g   = lane >> 2;
    const int t   = lane & 3;

    const size_t qkBase = (size_t)bh * S_ * D_;
    const size_t vBase  = (size_t)bh * D_ * S_;

    // ---- stage Q tile in K-hi buffer via cp.async ----
#pragma unroll
    for (int l = 0; l < 8; ++l) {
        const int idx = tid + l * 128;
        const int r = idx >> 4, c = idx & 15;
        const size_t go = qkBase + (size_t)(qt * 64 + r) * D_ + c * 8;
        CP_ASYNC16(sb + ASM_KH + r * QK_STR + c * 16, Q16 + go);
    }
    CP_COMMIT();
    CP_WAIT(0);
    __syncthreads();

    // ---- preload Q fragments ----
    const uint32_t aOff = (uint32_t)((wq * 16 + (lane & 15)) * QK_STR +
                                     (lane >> 4) * 16);
    uint32_t qf[8][4];
#pragma unroll
    for (int kc = 0; kc < 8; ++kc)
        ldsm4(qf[kc][0], qf[kc][1], qf[kc][2], qf[kc][3],
              sb + ASM_KH + aOff + kc * 32);
    __syncthreads();   // Q extracted; K may overwrite

    const uint32_t bOffK = (uint32_t)(((lane & 7) + ((lane >> 4) << 3)) * QK_STR +
                                      ((lane >> 3) & 1) * 16);
    const uint32_t bOffV = (uint32_t)(((lane & 7) + ((lane >> 4) << 3)) * VT_STR +
                                      ((lane >> 3) & 1) * 16);

    float O[16][4];
#pragma unroll
    for (int nt = 0; nt < 16; ++nt)
#pragma unroll
        for (int q = 0; q < 4; ++q) O[nt][q] = 0.0f;
    float m0 = -1e30f, m1 = -1e30f, l0 = 0.0f, l1 = 0.0f;

    const float scale = 0.08838834764831843f;
    const int rl0 = wq * 16 + g;
    const int rl1 = rl0 + 8;

    for (int kt = 0; kt <= qt; ++kt) {
        // ---- load K hi/lo (64x128) and Vt (128x64) via cp.async ----
#pragma unroll
        for (int l = 0; l < 8; ++l) {
            const int idx = tid + l * 128;
            {
                const int r = idx >> 4, c = idx & 15;
                const size_t go = qkBase + (size_t)(kt * 64 + r) * D_ + c * 8;
                CP_ASYNC16(sb + ASM_KH + r * QK_STR + c * 16, Kh + go);
                CP_ASYNC16(sb + ASM_KL + r * QK_STR + c * 16, Kl + go);
            }
            {
                const int r = idx >> 3, c = idx & 7;
                const size_t go = vBase + (size_t)r * S_ + kt * 64 + c * 8;
                CP_ASYNC16(sb + ASM_VH + r * VT_STR + c * 16, Vt16 + go);
            }
        }
        CP_COMMIT();
        CP_WAIT(0);
        __syncthreads();

        // ---- S = Q16 (Kh + Kl)^T : hi sweep then lo sweep per kc ----
        float sacc[8][4];
#pragma unroll
        for (int nt = 0; nt < 8; ++nt)
#pragma unroll
            for (int q = 0; q < 4; ++q) sacc[nt][q] = 0.0f;

#pragma unroll
        for (int kc = 0; kc < 8; ++kc) {
            uint32_t kfh[8][2], kfl[8][2];
#pragma unroll
            for (int p = 0; p < 4; ++p) {
                ldsm4(kfh[2 * p][0], kfh[2 * p][1], kfh[2 * p + 1][0], kfh[2 * p + 1][1],
                      sb + ASM_KH + p * 16 * QK_STR + bOffK + kc * 32);
                ldsm4(kfl[2 * p][0], kfl[2 * p][1], kfl[2 * p + 1][0], kfl[2 * p + 1][1],
                      sb + ASM_KL + p * 16 * QK_STR + bOffK + kc * 32);
            }
#pragma unroll
            for (int nt = 0; nt < 8; ++nt)
                mma_f16(sacc[nt], qf[kc], kfh[nt]);
#pragma unroll
            for (int nt = 0; nt < 8; ++nt)
                mma_f16(sacc[nt], qf[kc], kfl[nt]);
        }

        // ---- scale + causal mask + online softmax ----
        const bool diag = (kt == qt);
        float rm0 = -1e30f, rm1 = -1e30f;
#pragma unroll
        for (int nt = 0; nt < 8; ++nt) {
            const int cl0 = nt * 8 + 2 * t;
            float s0v = sacc[nt][0] * scale;
            float s1v = sacc[nt][1] * scale;
            float s2v = sacc[nt][2] * scale;
            float s3v = sacc[nt][3] * scale;
            if (diag) {
                if (cl0 > rl0)     s0v = -1e30f;
                if (cl0 + 1 > rl0) s1v = -1e30f;
                if (cl0 > rl1)     s2v = -1e30f;
                if (cl0 + 1 > rl1) s3v = -1e30f;
            }
            sacc[nt][0] = s0v; sacc[nt][1] = s1v;
            sacc[nt][2] = s2v; sacc[nt][3] = s3v;
            rm0 = fmaxf(rm0, fmaxf(s0v, s1v));
            rm1 = fmaxf(rm1, fmaxf(s2v, s3v));
        }
        rm0 = fmaxf(rm0, __shfl_xor_sync(0xffffffffu, rm0, 1));
        rm0 = fmaxf(rm0, __shfl_xor_sync(0xffffffffu, rm0, 2));
        rm1 = fmaxf(rm1, __shfl_xor_sync(0xffffffffu, rm1, 1));
        rm1 = fmaxf(rm1, __shfl_xor_sync(0xffffffffu, rm1, 2));

        const float mn0 = fmaxf(m0, rm0), mn1 = fmaxf(m1, rm1);
        const float a0 = __expf(m0 - mn0), a1 = __expf(m1 - mn1);
        m0 = mn0; m1 = mn1;

        float rs0 = 0.0f, rs1 = 0.0f;
#pragma unroll
        for (int nt = 0; nt < 8; ++nt) {
            const float p0 = __expf(sacc[nt][0] - mn0);
            const float p1 = __expf(sacc[nt][1] - mn0);
            const float p2 = __expf(sacc[nt][2] - mn1);
            const float p3 = __expf(sacc[nt][3] - mn1);
            sacc[nt][0] = p0; sacc[nt][1] = p1;
            sacc[nt][2] = p2; sacc[nt][3] = p3;
            rs0 += p0 + p1;
            rs1 += p2 + p3;
        }
        rs0 += __shfl_xor_sync(0xffffffffu, rs0, 1);
        rs0 += __shfl_xor_sync(0xffffffffu, rs0, 2);
        rs1 += __shfl_xor_sync(0xffffffffu, rs1, 1);
        rs1 += __shfl_xor_sync(0xffffffffu, rs1, 2);
        l0 = l0 * a0 + rs0;
        l1 = l1 * a1 + rs1;

#pragma unroll
        for (int nt = 0; nt < 16; ++nt) {
            O[nt][0] *= a0; O[nt][1] *= a0;
            O[nt][2] *= a1; O[nt][3] *= a1;
        }

        // ---- pack P into single-fp16 A fragments ----
        uint32_t pf[4][4];
#pragma unroll
        for (int kc = 0; kc < 4; ++kc) {
            const int n0 = 2 * kc, n1 = 2 * kc + 1;
            pf[kc][0] = pack_h2(sacc[n0][0], sacc[n0][1]);
            pf[kc][1] = pack_h2(sacc[n0][2], sacc[n0][3]);
            pf[kc][2] = pack_h2(sacc[n1][0], sacc[n1][1]);
            pf[kc][3] = pack_h2(sacc[n1][2], sacc[n1][3]);
        }

        // ---- O += P16 V16 (kc outer: O regs reused every 16 MMAs) ----
#pragma unroll
        for (int kc = 0; kc < 4; ++kc) {
#pragma unroll
            for (int p = 0; p < 8; ++p) {
                uint32_t vh[2][2];
                ldsm4(vh[0][0], vh[0][1], vh[1][0], vh[1][1],
                      sb + ASM_VH + p * 16 * VT_STR + bOffV + kc * 32);
                mma_f16(O[2 * p],     pf[kc], vh[0]);
                mma_f16(O[2 * p + 1], pf[kc], vh[1]);
            }
        }
        __syncthreads();
    }

    // ---- epilogue: normalize, convert to fp16, store ctx [MTOT, E] ----
    const int b = bh >> 4, h = bh & 15;
    const float i0 = 1.0f / l0, i1 = 1.0f / l1;
    const int row0 = qt * 64 + wq * 16 + g;
#pragma unroll
    for (int nt = 0; nt < 16; ++nt) {
        const int col = h * D_ + nt * 8 + 2 * t;
        const size_t o0 = (size_t)(b * S_ + row0) * E_ + col;
        const size_t o1 = (size_t)(b * S_ + row0 + 8) * E_ + col;
        *reinterpret_cast<uint32_t*>(c16 + o0) = pack_h2(O[nt][0] * i0, O[nt][1] * i0);
        *reinterpret_cast<uint32_t*>(c16 + o1) = pack_h2(O[nt][2] * i1, O[nt][3] * i1);
    }
}

// ---------------------------------------------------------------------------
extern "C" void kernel_launch(void* const* d_in, const int* in_sizes, int n_in,
                              void* d_out, int out_size)
{
    const float* x    = (const float*)d_in[0];
    const float* wqkv = (const float*)d_in[1];
    const float* bqkv = (const float*)d_in[2];
    const float* wout = (const float*)d_in[3];
    const float* bout = (const float*)d_in[4];
    float* out = (float*)d_out;

    float* qkv;
    __half *x16, *wqh, *wql, *woh, *wol, *c16;
    __half *Q16, *Kh, *Kl, *Vt16;
    cudaGetSymbolAddress((void**)&qkv, g_qkv);
    cudaGetSymbolAddress((void**)&x16, g_x16);
    cudaGetSymbolAddress((void**)&wqh, g_wqh);
    cudaGetSymbolAddress((void**)&wql, g_wql);
    cudaGetSymbolAddress((void**)&woh, g_woh);
    cudaGetSymbolAddress((void**)&wol, g_wol);
    cudaGetSymbolAddress((void**)&c16, g_c16);
    cudaGetSymbolAddress((void**)&Q16, g_Q16);
    cudaGetSymbolAddress((void**)&Kh, g_Kh);
    cudaGetSymbolAddress((void**)&Kl, g_Kl);
    cudaGetSymbolAddress((void**)&Vt16, g_Vt16);

    cudaFuncSetAttribute(gemm_hmma_x2,
                         cudaFuncAttributeMaxDynamicSharedMemorySize, GSM_TOTAL);
    cudaFuncSetAttribute(attn_hmma,
                         cudaFuncAttributeMaxDynamicSharedMemorySize, ASM_TOTAL);

    // 0) converts
    {
        int n4;
        n4 = MTOT * E_ / 4;
        to_f16<<<(n4 + 255) / 256, 256>>>(x, x16, n4);
        n4 = N_QKV * E_ / 4;
        split_f16<<<(n4 + 255) / 256, 256>>>(wqkv, wqh, wql, n4);
        n4 = E_ * E_ / 4;
        split_f16<<<(n4 + 255) / 256, 256>>>(wout, woh, wol, n4);
    }

    // 1) QKV projection
    gemm_hmma_x2<<<dim3(N_QKV / 128, MTOT / 128), 256, GSM_TOTAL>>>(
        x16, wqh, wql, bqkv, qkv, N_QKV, KDIM);

    // 2) rotary + convert Q,K ; transpose V
    qk_rope_cvt<<<(B_ * S_ * H_ * HALF_ + 255) / 256, 256>>>(
        qkv, Q16, Kh, Kl);
    v_transpose<<<dim3(S_ / 32, D_ / 32, BH_), dim3(32, 8)>>>(qkv, Vt16);

    // 3) fp16 flash attention -> c16
    attn_hmma<<<dim3(S_ / 64, BH_), 128, ASM_TOTAL>>>(
        Q16, Kh, Kl, Vt16, c16);

    // 4) output projection
    gemm_hmma_x2<<<dim3(E_ / 128, MTOT / 128), 256, GSM_TOTAL>>>(
        c16, woh, wol, bout, out, E_, KDIM);
}

// round 11
// speedup vs baseline: 4.3448x; 1.2868x over previous
#include <cuda_runtime.h>
#include <cuda_fp16.h>
#include <math.h>
#include <stdint.h>

#define B_    2
#define S_    2048
#define E_    2048
#define H_    16
#define D_    128
#define HALF_ 64
#define MTOT  (B_ * S_)          // 4096
#define N_QKV (3 * E_)           // 6144
#define KDIM  E_                 // 2048
#define BH_   (B_ * H_)          // 32

// ---------------- scratch (__device__ globals; allocation-free) -------------
__device__ float g_qkv[(size_t)MTOT * 3 * E_];
__device__ __half g_x16[(size_t)MTOT * E_];
__device__ __half g_wq16[(size_t)N_QKV * E_];
__device__ __half g_wo16[(size_t)E_ * E_];
__device__ __half g_c16[(size_t)MTOT * E_];
__device__ __half g_Q16[(size_t)BH_ * S_ * D_];
__device__ __half g_Kh[(size_t)BH_ * S_ * D_], g_Kl[(size_t)BH_ * S_ * D_];
__device__ __half g_Vt16[(size_t)BH_ * D_ * S_];

// ---------------- helpers ---------------------------------------------------
__device__ __forceinline__ uint32_t smem_u32(const void* p) {
    uint32_t a;
    asm("{ .reg .u64 t; cvta.to.shared.u64 t, %1; cvt.u32.u64 %0, t; }"
        : "=r"(a) : "l"(p));
    return a;
}

#define CP_ASYNC16(sa, gp) \
    asm volatile("cp.async.cg.shared.global [%0], [%1], 16;" :: "r"(sa), "l"(gp))
#define CP_COMMIT() asm volatile("cp.async.commit_group;" ::: "memory")
#define CP_WAIT(n)  asm volatile("cp.async.wait_group %0;" :: "n"(n) : "memory")

__device__ __forceinline__ void ldsm4(uint32_t& r0, uint32_t& r1, uint32_t& r2,
                                      uint32_t& r3, uint32_t addr) {
    asm volatile("ldmatrix.sync.aligned.m8n8.x4.shared.b16 {%0,%1,%2,%3}, [%4];"
                 : "=r"(r0), "=r"(r1), "=r"(r2), "=r"(r3) : "r"(addr));
}

__device__ __forceinline__ void mma_f16(float* c, const uint32_t* a,
                                        const uint32_t* b) {
    asm volatile(
        "mma.sync.aligned.m16n8k16.row.col.f32.f16.f16.f32 "
        "{%0,%1,%2,%3}, {%4,%5,%6,%7}, {%8,%9}, {%0,%1,%2,%3};"
        : "+f"(c[0]), "+f"(c[1]), "+f"(c[2]), "+f"(c[3])
        : "r"(a[0]), "r"(a[1]), "r"(a[2]), "r"(a[3]), "r"(b[0]), "r"(b[1]));
}

__device__ __forceinline__ uint32_t pack_h2(float f0, float f1) {
    __half2 p = __floats2half2_rn(f0, f1);
    return *reinterpret_cast<uint32_t*>(&p);
}

// ---------------------------------------------------------------------------
// fp32 -> single fp16
// ---------------------------------------------------------------------------
__global__ void __launch_bounds__(256) to_f16(
    const float* __restrict__ in, __half* __restrict__ o16, int n4)
{
    const int i = blockIdx.x * blockDim.x + threadIdx.x;
    if (i >= n4) return;
    const float4 v = reinterpret_cast<const float4*>(in)[i];
    uint2 p;
    p.x = pack_h2(v.x, v.y);
    p.y = pack_h2(v.z, v.w);
    reinterpret_cast<uint2*>(o16)[i] = p;
}

// ---------------------------------------------------------------------------
// HMMA fp16 single-pass GEMM:  C[M,N] = A16[M,K] @ W16[N,K]^T + bias
// 128x128 tile, BK=32, 8 warps (2m x 4n), 4-stage cp.async pipeline.
// ---------------------------------------------------------------------------
#define RSTRIDE   80
#define TILE_B    (128 * RSTRIDE)          // 10240
#define STAGE_B   (2 * TILE_B)             // A, W  = 20480
#define NSTAGE    4
#define GSM_TOTAL (NSTAGE * STAGE_B)       // 81920

__global__ void __launch_bounds__(256) gemm_hmma_x1(
    const __half* __restrict__ A16, const __half* __restrict__ W16,
    const float* __restrict__ bias, float* __restrict__ C, int N, int K)
{
    extern __shared__ char smem[];
    const uint32_t sb = smem_u32(smem);

    const int tid  = threadIdx.x;
    const int wid  = tid >> 5;
    const int lane = tid & 31;
    const int wm   = wid & 1;
    const int wn   = wid >> 1;
    const int rowBlk = blockIdx.y * 128;
    const int colBlk = blockIdx.x * 128;

    const int gr0 = tid >> 2;
    const int gc  = (tid & 3) * 16;

    auto issue_stage = [&](int k0, int stg) {
        const uint32_t s0 = sb + stg * STAGE_B;
#pragma unroll
        for (int l = 0; l < 2; ++l) {
            const int r = gr0 + l * 64;
            const uint32_t so = r * RSTRIDE + gc;
            CP_ASYNC16(s0 + so,
                       A16 + (size_t)(rowBlk + r) * K + k0 + (gc >> 1));
            CP_ASYNC16(s0 + TILE_B + so,
                       W16 + (size_t)(colBlk + r) * K + k0 + (gc >> 1));
        }
        CP_COMMIT();
    };

    float acc[4][4][4];
#pragma unroll
    for (int i = 0; i < 4; ++i)
#pragma unroll
        for (int j = 0; j < 4; ++j)
#pragma unroll
            for (int q = 0; q < 4; ++q) acc[i][j][q] = 0.0f;

    const uint32_t aOff = (uint32_t)((wm * 64 + (lane & 15)) * RSTRIDE +
                                     (lane >> 4) * 16);
    const uint32_t bOff = (uint32_t)((wn * 32 + (lane & 7) + ((lane >> 4) << 3)) * RSTRIDE +
                                     ((lane >> 3) & 1) * 16);

    const int NCH = K / 32;                 // 64
    issue_stage(0, 0);
    issue_stage(32, 1);
    issue_stage(64, 2);

    for (int c = 0; c < NCH; ++c) {
        CP_WAIT(2);          // pending = {c, c+1, c+2}; ensures group c landed
        __syncthreads();     // all warps done with buffer (c-1)%4
        if (c + 3 < NCH) issue_stage((c + 3) * 32, (c + 3) & 3);
        else             CP_COMMIT();       // keep one-commit-per-iter invariant

        const uint32_t s0 = sb + (c & 3) * STAGE_B;
        const uint32_t sA = s0 + aOff;
        const uint32_t sW = s0 + TILE_B + bOff;

#pragma unroll
        for (int ks = 0; ks < 2; ++ks) {
            const uint32_t ko = ks * 32;
            uint32_t a[4][4], w[4][2];
#pragma unroll
            for (int mt = 0; mt < 4; ++mt)
                ldsm4(a[mt][0], a[mt][1], a[mt][2], a[mt][3],
                      sA + mt * 16 * RSTRIDE + ko);
#pragma unroll
            for (int p = 0; p < 2; ++p)
                ldsm4(w[2 * p][0], w[2 * p][1], w[2 * p + 1][0], w[2 * p + 1][1],
                      sW + p * 16 * RSTRIDE + ko);
#pragma unroll
            for (int mt = 0; mt < 4; ++mt)
#pragma unroll
                for (int nt = 0; nt < 4; ++nt)
                    mma_f16(acc[mt][nt], a[mt], w[nt]);
        }
    }
    __syncthreads();

    const int g = lane >> 2;
    const int t = lane & 3;
#pragma unroll
    for (int mt = 0; mt < 4; ++mt) {
        const int row0 = rowBlk + wm * 64 + mt * 16 + g;
#pragma unroll
        for (int nt = 0; nt < 4; ++nt) {
            const int col = colBlk + wn * 32 + nt * 8 + 2 * t;
            const float b0 = bias[col], b1 = bias[col + 1];
            float2 v0 = make_float2(acc[mt][nt][0] + b0, acc[mt][nt][1] + b1);
            float2 v1 = make_float2(acc[mt][nt][2] + b0, acc[mt][nt][3] + b1);
            *reinterpret_cast<float2*>(C + (size_t)row0 * N + col) = v0;
            *reinterpret_cast<float2*>(C + (size_t)(row0 + 8) * N + col) = v1;
        }
    }
}

// ---------------------------------------------------------------------------
// Fused rotary + convert: qkv[B,S,3,H,D] fp32 -> Q16, Kh/Kl [BH,S,D]
// ---------------------------------------------------------------------------
__global__ void __launch_bounds__(256) qk_rope_cvt(
    const float* __restrict__ qkv,
    __half* __restrict__ Q16,
    __half* __restrict__ Kh, __half* __restrict__ Kl)
{
    const int idx = blockIdx.x * blockDim.x + threadIdx.x;
    const int total = B_ * S_ * H_ * HALF_;
    if (idx >= total) return;

    const int dh = idx & (HALF_ - 1);
    const int h  = (idx >> 6) & (H_ - 1);
    const int s  = (idx >> 10) & (S_ - 1);
    const int b  = idx >> 21;

    const double inv = exp(-(double)dh * (log(10000.0) / 64.0));
    const float  f   = (float)((double)s * inv);
    float c, sn;
    sincosf(f, &sn, &c);

    const size_t obase = ((size_t)(b * H_ + h) * S_ + s) * D_;

    {
        const size_t ib = (((size_t)(b * S_ + s) * 3 + 0) * H_ + h) * (size_t)D_;
        const float x1 = qkv[ib + dh], x2 = qkv[ib + dh + HALF_];
        Q16[obase + dh]         = __float2half(x1 * c - x2 * sn);
        Q16[obase + dh + HALF_] = __float2half(x2 * c + x1 * sn);
    }
    {
        const size_t ib = (((size_t)(b * S_ + s) * 3 + 1) * H_ + h) * (size_t)D_;
        const float x1 = qkv[ib + dh], x2 = qkv[ib + dh + HALF_];
        const float y1 = x1 * c - x2 * sn, y2 = x2 * c + x1 * sn;
        __half h1 = __float2half(y1), h2 = __float2half(y2);
        Kh[obase + dh] = h1;
        Kh[obase + dh + HALF_] = h2;
        Kl[obase + dh] = __float2half(y1 - __half2float(h1));
        Kl[obase + dh + HALF_] = __float2half(y2 - __half2float(h2));
    }
}

// ---------------------------------------------------------------------------
// V transpose: qkv comp2 [B,S,H,D] -> Vt16 [BH, D, S]
// ---------------------------------------------------------------------------
__global__ void __launch_bounds__(256) v_transpose(
    const float* __restrict__ qkv, __half* __restrict__ Vt16)
{
    __shared__ float tile[32][33];
    const int tx = threadIdx.x;
    const int ty = threadIdx.y;
    const int s0 = blockIdx.x * 32;
    const int d0 = blockIdx.y * 32;
    const int bh = blockIdx.z;
    const int b  = bh >> 4;
    const int h  = bh & 15;

#pragma unroll
    for (int i = 0; i < 4; ++i) {
        const int s = s0 + ty + i * 8;
        const int d = d0 + tx;
        tile[ty + i * 8][tx] =
            qkv[(((size_t)(b * S_ + s) * 3 + 2) * H_ + h) * (size_t)D_ + d];
    }
    __syncthreads();

#pragma unroll
    for (int i = 0; i < 4; ++i) {
        const int d = d0 + ty + i * 8;
        const int s = s0 + tx;
        Vt16[((size_t)bh * D_ + d) * S_ + s] = __float2half(tile[tx][ty + i * 8]);
    }
}

// ---------------------------------------------------------------------------
// HMMA fp16 flash attention (causal), 3 CTAs/SM — unchanged from R10.
// ---------------------------------------------------------------------------
#define QK_STR 272
#define VT_STR 144
#define ASM_KH 0
#define ASM_KL (64 * QK_STR)
#define ASM_VH (2 * 64 * QK_STR)
#define ASM_TOTAL (2 * 64 * QK_STR + 128 * VT_STR)   // 53248

__global__ void __launch_bounds__(128, 3) attn_hmma(
    const __half* __restrict__ Q16,
    const __half* __restrict__ Kh, const __half* __restrict__ Kl,
    const __half* __restrict__ Vt16,
    __half* __restrict__ c16)
{
    extern __shared__ char smem[];
    const uint32_t sb = smem_u32(smem);

    const int qt  = gridDim.x - 1 - blockIdx.x;   // long blocks first
    const int bh  = blockIdx.y;
    const int tid = threadIdx.x;
    const int wq  = tid >> 5;
    const int lane = tid & 31;
    const int g   = lane >> 2;
    const int t   = lane & 3;

    const size_t qkBase = (size_t)bh * S_ * D_;
    const size_t vBase  = (size_t)bh * D_ * S_;

    // ---- stage Q tile in K-hi buffer via cp.async ----
#pragma unroll
    for (int l = 0; l < 8; ++l) {
        const int idx = tid + l * 128;
        const int r = idx >> 4, c = idx & 15;
        const size_t go = qkBase + (size_t)(qt * 64 + r) * D_ + c * 8;
        CP_ASYNC16(sb + ASM_KH + r * QK_STR + c * 16, Q16 + go);
    }
    CP_COMMIT();
    CP_WAIT(0);
    __syncthreads();

    // ---- preload Q fragments ----
    const uint32_t aOff = (uint32_t)((wq * 16 + (lane & 15)) * QK_STR +
                                     (lane >> 4) * 16);
    uint32_t qf[8][4];
#pragma unroll
    for (int kc = 0; kc < 8; ++kc)
        ldsm4(qf[kc][0], qf[kc][1], qf[kc][2], qf[kc][3],
              sb + ASM_KH + aOff + kc * 32);
    __syncthreads();   // Q extracted; K may overwrite

    const uint32_t bOffK = (uint32_t)(((lane & 7) + ((lane >> 4) << 3)) * QK_STR +
                                      ((lane >> 3) & 1) * 16);
    const uint32_t bOffV = (uint32_t)(((lane & 7) + ((lane >> 4) << 3)) * VT_STR +
                                      ((lane >> 3) & 1) * 16);

    float O[16][4];
#pragma unroll
    for (int nt = 0; nt < 16; ++nt)
#pragma unroll
        for (int q = 0; q < 4; ++q) O[nt][q] = 0.0f;
    float m0 = -1e30f, m1 = -1e30f, l0 = 0.0f, l1 = 0.0f;

    const float scale = 0.08838834764831843f;
    const int rl0 = wq * 16 + g;
    const int rl1 = rl0 + 8;

    for (int kt = 0; kt <= qt; ++kt) {
        // ---- load K hi/lo (64x128) and Vt (128x64) via cp.async ----
#pragma unroll
        for (int l = 0; l < 8; ++l) {
            const int idx = tid + l * 128;
            {
                const int r = idx >> 4, c = idx & 15;
                const size_t go = qkBase + (size_t)(kt * 64 + r) * D_ + c * 8;
                CP_ASYNC16(sb + ASM_KH + r * QK_STR + c * 16, Kh + go);
                CP_ASYNC16(sb + ASM_KL + r * QK_STR + c * 16, Kl + go);
            }
            {
                const int r = idx >> 3, c = idx & 7;
                const size_t go = vBase + (size_t)r * S_ + kt * 64 + c * 8;
                CP_ASYNC16(sb + ASM_VH + r * VT_STR + c * 16, Vt16 + go);
            }
        }
        CP_COMMIT();
        CP_WAIT(0);
        __syncthreads();

        // ---- S = Q16 (Kh + Kl)^T : hi sweep then lo sweep per kc ----
        float sacc[8][4];
#pragma unroll
        for (int nt = 0; nt < 8; ++nt)
#pragma unroll
            for (int q = 0; q < 4; ++q) sacc[nt][q] = 0.0f;

#pragma unroll
        for (int kc = 0; kc < 8; ++kc) {
            uint32_t kfh[8][2], kfl[8][2];
#pragma unroll
            for (int p = 0; p < 4; ++p) {
                ldsm4(kfh[2 * p][0], kfh[2 * p][1], kfh[2 * p + 1][0], kfh[2 * p + 1][1],
                      sb + ASM_KH + p * 16 * QK_STR + bOffK + kc * 32);
                ldsm4(kfl[2 * p][0], kfl[2 * p][1], kfl[2 * p + 1][0], kfl[2 * p + 1][1],
                      sb + ASM_KL + p * 16 * QK_STR + bOffK + kc * 32);
            }
#pragma unroll
            for (int nt = 0; nt < 8; ++nt)
                mma_f16(sacc[nt], qf[kc], kfh[nt]);
#pragma unroll
            for (int nt = 0; nt < 8; ++nt)
                mma_f16(sacc[nt], qf[kc], kfl[nt]);
        }

        // ---- scale + causal mask + online softmax ----
        const bool diag = (kt == qt);
        float rm0 = -1e30f, rm1 = -1e30f;
#pragma unroll
        for (int nt = 0; nt < 8; ++nt) {
            const int cl0 = nt * 8 + 2 * t;
            float s0v = sacc[nt][0] * scale;
            float s1v = sacc[nt][1] * scale;
            float s2v = sacc[nt][2] * scale;
            float s3v = sacc[nt][3] * scale;
            if (diag) {
                if (cl0 > rl0)     s0v = -1e30f;
                if (cl0 + 1 > rl0) s1v = -1e30f;
                if (cl0 > rl1)     s2v = -1e30f;
                if (cl0 + 1 > rl1) s3v = -1e30f;
            }
            sacc[nt][0] = s0v; sacc[nt][1] = s1v;
            sacc[nt][2] = s2v; sacc[nt][3] = s3v;
            rm0 = fmaxf(rm0, fmaxf(s0v, s1v));
            rm1 = fmaxf(rm1, fmaxf(s2v, s3v));
        }
        rm0 = fmaxf(rm0, __shfl_xor_sync(0xffffffffu, rm0, 1));
        rm0 = fmaxf(rm0, __shfl_xor_sync(0xffffffffu, rm0, 2));
        rm1 = fmaxf(rm1, __shfl_xor_sync(0xffffffffu, rm1, 1));
        rm1 = fmaxf(rm1, __shfl_xor_sync(0xffffffffu, rm1, 2));

        const float mn0 = fmaxf(m0, rm0), mn1 = fmaxf(m1, rm1);
        const float a0 = __expf(m0 - mn0), a1 = __expf(m1 - mn1);
        m0 = mn0; m1 = mn1;

        float rs0 = 0.0f, rs1 = 0.0f;
#pragma unroll
        for (int nt = 0; nt < 8; ++nt) {
            const float p0 = __expf(sacc[nt][0] - mn0);
            const float p1 = __expf(sacc[nt][1] - mn0);
            const float p2 = __expf(sacc[nt][2] - mn1);
            const float p3 = __expf(sacc[nt][3] - mn1);
            sacc[nt][0] = p0; sacc[nt][1] = p1;
            sacc[nt][2] = p2; sacc[nt][3] = p3;
            rs0 += p0 + p1;
            rs1 += p2 + p3;
        }
        rs0 += __shfl_xor_sync(0xffffffffu, rs0, 1);
        rs0 += __shfl_xor_sync(0xffffffffu, rs0, 2);
        rs1 += __shfl_xor_sync(0xffffffffu, rs1, 1);
        rs1 += __shfl_xor_sync(0xffffffffu, rs1, 2);
        l0 = l0 * a0 + rs0;
        l1 = l1 * a1 + rs1;

#pragma unroll
        for (int nt = 0; nt < 16; ++nt) {
            O[nt][0] *= a0; O[nt][1] *= a0;
            O[nt][2] *= a1; O[nt][3] *= a1;
        }

        // ---- pack P into single-fp16 A fragments ----
        uint32_t pf[4][4];
#pragma unroll
        for (int kc = 0; kc < 4; ++kc) {
            const int n0 = 2 * kc, n1 = 2 * kc + 1;
            pf[kc][0] = pack_h2(sacc[n0][0], sacc[n0][1]);
            pf[kc][1] = pack_h2(sacc[n0][2], sacc[n0][3]);
            pf[kc][2] = pack_h2(sacc[n1][0], sacc[n1][1]);
            pf[kc][3] = pack_h2(sacc[n1][2], sacc[n1][3]);
        }

        // ---- O += P16 V16 (kc outer) ----
#pragma unroll
        for (int kc = 0; kc < 4; ++kc) {
#pragma unroll
            for (int p = 0; p < 8; ++p) {
                uint32_t vh[2][2];
                ldsm4(vh[0][0], vh[0][1], vh[1][0], vh[1][1],
                      sb + ASM_VH + p * 16 * VT_STR + bOffV + kc * 32);
                mma_f16(O[2 * p],     pf[kc], vh[0]);
                mma_f16(O[2 * p + 1], pf[kc], vh[1]);
            }
        }
        __syncthreads();
    }

    // ---- epilogue ----
    const int b = bh >> 4, h = bh & 15;
    const float i0 = 1.0f / l0, i1 = 1.0f / l1;
    const int row0 = qt * 64 + wq * 16 + g;
#pragma unroll
    for (int nt = 0; nt < 16; ++nt) {
        const int col = h * D_ + nt * 8 + 2 * t;
        const size_t o0 = (size_t)(b * S_ + row0) * E_ + col;
        const size_t o1 = (size_t)(b * S_ + row0 + 8) * E_ + col;
        *reinterpret_cast<uint32_t*>(c16 + o0) = pack_h2(O[nt][0] * i0, O[nt][1] * i0);
        *reinterpret_cast<uint32_t*>(c16 + o1) = pack_h2(O[nt][2] * i1, O[nt][3] * i1);
    }
}

// ---------------------------------------------------------------------------
extern "C" void kernel_launch(void* const* d_in, const int* in_sizes, int n_in,
                              void* d_out, int out_size)
{
    const float* x    = (const float*)d_in[0];
    const float* wqkv = (const float*)d_in[1];
    const float* bqkv = (const float*)d_in[2];
    const float* wout = (const float*)d_in[3];
    const float* bout = (const float*)d_in[4];
    float* out = (float*)d_out;

    float* qkv;
    __half *x16, *wq16, *wo16, *c16;
    __half *Q16, *Kh, *Kl, *Vt16;
    cudaGetSymbolAddress((void**)&qkv, g_qkv);
    cudaGetSymbolAddress((void**)&x16, g_x16);
    cudaGetSymbolAddress((void**)&wq16, g_wq16);
    cudaGetSymbolAddress((void**)&wo16, g_wo16);
    cudaGetSymbolAddress((void**)&c16, g_c16);
    cudaGetSymbolAddress((void**)&Q16, g_Q16);
    cudaGetSymbolAddress((void**)&Kh, g_Kh);
    cudaGetSymbolAddress((void**)&Kl, g_Kl);
    cudaGetSymbolAddress((void**)&Vt16, g_Vt16);

    cudaFuncSetAttribute(gemm_hmma_x1,
                         cudaFuncAttributeMaxDynamicSharedMemorySize, GSM_TOTAL);
    cudaFuncSetAttribute(attn_hmma,
                         cudaFuncAttributeMaxDynamicSharedMemorySize, ASM_TOTAL);

    // 0) converts
    {
        int n4;
        n4 = MTOT * E_ / 4;
        to_f16<<<(n4 + 255) / 256, 256>>>(x, x16, n4);
        n4 = N_QKV * E_ / 4;
        to_f16<<<(n4 + 255) / 256, 256>>>(wqkv, wq16, n4);
        n4 = E_ * E_ / 4;
        to_f16<<<(n4 + 255) / 256, 256>>>(wout, wo16, n4);
    }

    // 1) QKV projection (single-pass fp16)
    gemm_hmma_x1<<<dim3(N_QKV / 128, MTOT / 128), 256, GSM_TOTAL>>>(
        x16, wq16, bqkv, qkv, N_QKV, KDIM);

    // 2) rotary + convert Q,K ; transpose V
    qk_rope_cvt<<<(B_ * S_ * H_ * HALF_ + 255) / 256, 256>>>(
        qkv, Q16, Kh, Kl);
    v_transpose<<<dim3(S_ / 32, D_ / 32, BH_), dim3(32, 8)>>>(qkv, Vt16);

    // 3) fp16 flash attention -> c16
    attn_hmma<<<dim3(S_ / 64, BH_), 128, ASM_TOTAL>>>(
        Q16, Kh, Kl, Vt16, c16);

    // 4) output projection (single-pass fp16)
    gemm_hmma_x1<<<dim3(E_ / 128, MTOT / 128), 256, GSM_TOTAL>>>(
        c16, wo16, bout, out, E_, KDIM);
}

// round 13
// speedup vs baseline: 4.7295x; 1.0886x over previous
#include <cuda_runtime.h>
#include <cuda_fp16.h>
#include <math.h>
#include <stdint.h>

#define B_    2
#define S_    2048
#define E_    2048
#define H_    16
#define D_    128
#define HALF_ 64
#define MTOT  (B_ * S_)          // 4096
#define N_QKV (3 * E_)           // 6144
#define KDIM  E_                 // 2048
#define BH_   (B_ * H_)          // 32

// ---------------- scratch (__device__ globals; allocation-free) -------------
__device__ float g_qkv[(size_t)MTOT * 3 * E_];
__device__ __half g_x16[(size_t)MTOT * E_];
__device__ __half g_wq16[(size_t)N_QKV * E_];
__device__ __half g_wo16[(size_t)E_ * E_];
__device__ __half g_c16[(size_t)MTOT * E_];
__device__ __half g_Q16[(size_t)BH_ * S_ * D_];
__device__ __half g_K16[(size_t)BH_ * S_ * D_];
__device__ __half g_Vt16[(size_t)BH_ * D_ * S_];

// ---------------- helpers ---------------------------------------------------
__device__ __forceinline__ uint32_t smem_u32(const void* p) {
    uint32_t a;
    asm("{ .reg .u64 t; cvta.to.shared.u64 t, %1; cvt.u32.u64 %0, t; }"
        : "=r"(a) : "l"(p));
    return a;
}

#define CP_ASYNC16(sa, gp) \
    asm volatile("cp.async.cg.shared.global [%0], [%1], 16;" :: "r"(sa), "l"(gp))
#define CP_COMMIT() asm volatile("cp.async.commit_group;" ::: "memory")
#define CP_WAIT(n)  asm volatile("cp.async.wait_group %0;" :: "n"(n) : "memory")

__device__ __forceinline__ void ldsm4(uint32_t& r0, uint32_t& r1, uint32_t& r2,
                                      uint32_t& r3, uint32_t addr) {
    asm volatile("ldmatrix.sync.aligned.m8n8.x4.shared.b16 {%0,%1,%2,%3}, [%4];"
                 : "=r"(r0), "=r"(r1), "=r"(r2), "=r"(r3) : "r"(addr));
}

__device__ __forceinline__ void mma_f16(float* c, const uint32_t* a,
                                        const uint32_t* b) {
    asm volatile(
        "mma.sync.aligned.m16n8k16.row.col.f32.f16.f16.f32 "
        "{%0,%1,%2,%3}, {%4,%5,%6,%7}, {%8,%9}, {%0,%1,%2,%3};"
        : "+f"(c[0]), "+f"(c[1]), "+f"(c[2]), "+f"(c[3])
        : "r"(a[0]), "r"(a[1]), "r"(a[2]), "r"(a[3]), "r"(b[0]), "r"(b[1]));
}

__device__ __forceinline__ uint32_t pack_h2(float f0, float f1) {
    __half2 p = __floats2half2_rn(f0, f1);
    return *reinterpret_cast<uint32_t*>(&p);
}

// ---------------------------------------------------------------------------
// fp32 -> single fp16
// ---------------------------------------------------------------------------
__global__ void __launch_bounds__(256) to_f16(
    const float* __restrict__ in, __half* __restrict__ o16, int n4)
{
    const int i = blockIdx.x * blockDim.x + threadIdx.x;
    if (i >= n4) return;
    const float4 v = reinterpret_cast<const float4*>(in)[i];
    uint2 p;
    p.x = pack_h2(v.x, v.y);
    p.y = pack_h2(v.z, v.w);
    reinterpret_cast<uint2*>(o16)[i] = p;
}

// ---------------------------------------------------------------------------
// HMMA fp16 single-pass GEMM (unchanged from R11)
// ---------------------------------------------------------------------------
#define RSTRIDE   80
#define TILE_B    (128 * RSTRIDE)
#define STAGE_B   (2 * TILE_B)
#define NSTAGE    4
#define GSM_TOTAL (NSTAGE * STAGE_B)       // 81920

__global__ void __launch_bounds__(256) gemm_hmma_x1(
    const __half* __restrict__ A16, const __half* __restrict__ W16,
    const float* __restrict__ bias, float* __restrict__ C, int N, int K)
{
    extern __shared__ char smem[];
    const uint32_t sb = smem_u32(smem);

    const int tid  = threadIdx.x;
    const int wid  = tid >> 5;
    const int lane = tid & 31;
    const int wm   = wid & 1;
    const int wn   = wid >> 1;
    const int rowBlk = blockIdx.y * 128;
    const int colBlk = blockIdx.x * 128;

    const int gr0 = tid >> 2;
    const int gc  = (tid & 3) * 16;

    auto issue_stage = [&](int k0, int stg) {
        const uint32_t s0 = sb + stg * STAGE_B;
#pragma unroll
        for (int l = 0; l < 2; ++l) {
            const int r = gr0 + l * 64;
            const uint32_t so = r * RSTRIDE + gc;
            CP_ASYNC16(s0 + so,
                       A16 + (size_t)(rowBlk + r) * K + k0 + (gc >> 1));
            CP_ASYNC16(s0 + TILE_B + so,
                       W16 + (size_t)(colBlk + r) * K + k0 + (gc >> 1));
        }
        CP_COMMIT();
    };

    float acc[4][4][4];
#pragma unroll
    for (int i = 0; i < 4; ++i)
#pragma unroll
        for (int j = 0; j < 4; ++j)
#pragma unroll
            for (int q = 0; q < 4; ++q) acc[i][j][q] = 0.0f;

    const uint32_t aOff = (uint32_t)((wm * 64 + (lane & 15)) * RSTRIDE +
                                     (lane >> 4) * 16);
    const uint32_t bOff = (uint32_t)((wn * 32 + (lane & 7) + ((lane >> 4) << 3)) * RSTRIDE +
                                     ((lane >> 3) & 1) * 16);

    const int NCH = K / 32;
    issue_stage(0, 0);
    issue_stage(32, 1);
    issue_stage(64, 2);

    for (int c = 0; c < NCH; ++c) {
        CP_WAIT(2);
        __syncthreads();
        if (c + 3 < NCH) issue_stage((c + 3) * 32, (c + 3) & 3);
        else             CP_COMMIT();

        const uint32_t s0 = sb + (c & 3) * STAGE_B;
        const uint32_t sA = s0 + aOff;
        const uint32_t sW = s0 + TILE_B + bOff;

#pragma unroll
        for (int ks = 0; ks < 2; ++ks) {
            const uint32_t ko = ks * 32;
            uint32_t a[4][4], w[4][2];
#pragma unroll
            for (int mt = 0; mt < 4; ++mt)
                ldsm4(a[mt][0], a[mt][1], a[mt][2], a[mt][3],
                      sA + mt * 16 * RSTRIDE + ko);
#pragma unroll
            for (int p = 0; p < 2; ++p)
                ldsm4(w[2 * p][0], w[2 * p][1], w[2 * p + 1][0], w[2 * p + 1][1],
                      sW + p * 16 * RSTRIDE + ko);
#pragma unroll
            for (int mt = 0; mt < 4; ++mt)
#pragma unroll
                for (int nt = 0; nt < 4; ++nt)
                    mma_f16(acc[mt][nt], a[mt], w[nt]);
        }
    }
    __syncthreads();

    const int g = lane >> 2;
    const int t = lane & 3;
#pragma unroll
    for (int mt = 0; mt < 4; ++mt) {
        const int row0 = rowBlk + wm * 64 + mt * 16 + g;
#pragma unroll
        for (int nt = 0; nt < 4; ++nt) {
            const int col = colBlk + wn * 32 + nt * 8 + 2 * t;
            const float b0 = bias[col], b1 = bias[col + 1];
            float2 v0 = make_float2(acc[mt][nt][0] + b0, acc[mt][nt][1] + b1);
            float2 v1 = make_float2(acc[mt][nt][2] + b0, acc[mt][nt][3] + b1);
            *reinterpret_cast<float2*>(C + (size_t)row0 * N + col) = v0;
            *reinterpret_cast<float2*>(C + (size_t)(row0 + 8) * N + col) = v1;
        }
    }
}

// ---------------------------------------------------------------------------
// Fused rotary + convert: qkv[B,S,3,H,D] fp32 -> Q16, K16 [BH,S,D]
// ---------------------------------------------------------------------------
__global__ void __launch_bounds__(256) qk_rope_cvt(
    const float* __restrict__ qkv,
    __half* __restrict__ Q16, __half* __restrict__ K16)
{
    const int idx = blockIdx.x * blockDim.x + threadIdx.x;
    const int total = B_ * S_ * H_ * HALF_;
    if (idx >= total) return;

    const int dh = idx & (HALF_ - 1);
    const int h  = (idx >> 6) & (H_ - 1);
    const int s  = (idx >> 10) & (S_ - 1);
    const int b  = idx >> 21;

    const double inv = exp(-(double)dh * (log(10000.0) / 64.0));
    const float  f   = (float)((double)s * inv);
    float c, sn;
    sincosf(f, &sn, &c);

    const size_t obase = ((size_t)(b * H_ + h) * S_ + s) * D_;

    {
        const size_t ib = (((size_t)(b * S_ + s) * 3 + 0) * H_ + h) * (size_t)D_;
        const float x1 = qkv[ib + dh], x2 = qkv[ib + dh + HALF_];
        Q16[obase + dh]         = __float2half(x1 * c - x2 * sn);
        Q16[obase + dh + HALF_] = __float2half(x2 * c + x1 * sn);
    }
    {
        const size_t ib = (((size_t)(b * S_ + s) * 3 + 1) * H_ + h) * (size_t)D_;
        const float x1 = qkv[ib + dh], x2 = qkv[ib + dh + HALF_];
        K16[obase + dh]         = __float2half(x1 * c - x2 * sn);
        K16[obase + dh + HALF_] = __float2half(x2 * c + x1 * sn);
    }
}

// ---------------------------------------------------------------------------
// V transpose: qkv comp2 [B,S,H,D] -> Vt16 [BH, D, S]
// ---------------------------------------------------------------------------
__global__ void __launch_bounds__(256) v_transpose(
    const float* __restrict__ qkv, __half* __restrict__ Vt16)
{
    __shared__ float tile[32][33];
    const int tx = threadIdx.x;
    const int ty = threadIdx.y;
    const int s0 = blockIdx.x * 32;
    const int d0 = blockIdx.y * 32;
    const int bh = blockIdx.z;
    const int b  = bh >> 4;
    const int h  = bh & 15;

#pragma unroll
    for (int i = 0; i < 4; ++i) {
        const int s = s0 + ty + i * 8;
        const int d = d0 + tx;
        tile[ty + i * 8][tx] =
            qkv[(((size_t)(b * S_ + s) * 3 + 2) * H_ + h) * (size_t)D_ + d];
    }
    __syncthreads();

#pragma unroll
    for (int i = 0; i < 4; ++i) {
        const int d = d0 + ty + i * 8;
        const int s = s0 + tx;
        Vt16[((size_t)bh * D_ + d) * S_ + s] = __float2half(tile[tx][ty + i * 8]);
    }
}

// ---------------------------------------------------------------------------
// HMMA fp16 flash attention (causal), single-pass K, 2-stage KV pipeline,
// 3 CTAs/SM.  Stage = K(64x128) 17408 B + Vt(128x64) 18432 B = 35840 B.
// ---------------------------------------------------------------------------
#define QK_STR 272
#define VT_STR 144
#define ATT_K   0
#define ATT_V   (64 * QK_STR)                 // 17408
#define ATT_STAGE (64 * QK_STR + 128 * VT_STR) // 35840
#define ASM_TOTAL (2 * ATT_STAGE)             // 71680

__global__ void __launch_bounds__(128, 3) attn_hmma(
    const __half* __restrict__ Q16, const __half* __restrict__ K16,
    const __half* __restrict__ Vt16,
    __half* __restrict__ c16)
{
    extern __shared__ char smem[];
    const uint32_t sb = smem_u32(smem);

    const int qt  = gridDim.x - 1 - blockIdx.x;   // long blocks first
    const int bh  = blockIdx.y;
    const int tid = threadIdx.x;
    const int wq  = tid >> 5;
    const int lane = tid & 31;
    const int g   = lane >> 2;
    const int t   = lane & 3;

    const size_t qkBase = (size_t)bh * S_ * D_;
    const size_t vBase  = (size_t)bh * D_ * S_;

    auto issue_tile = [&](int kt, int stg) {
        const uint32_t k0 = sb + stg * ATT_STAGE + ATT_K;
        const uint32_t v0 = sb + stg * ATT_STAGE + ATT_V;
#pragma unroll
        for (int l = 0; l < 8; ++l) {
            const int idx = tid + l * 128;
            {
                const int r = idx >> 4, c = idx & 15;
                CP_ASYNC16(k0 + r * QK_STR + c * 16,
                           K16 + qkBase + (size_t)(kt * 64 + r) * D_ + c * 8);
            }
            {
                const int r = idx >> 3, c = idx & 7;
                CP_ASYNC16(v0 + r * VT_STR + c * 16,
                           Vt16 + vBase + (size_t)r * S_ + kt * 64 + c * 8);
            }
        }
        CP_COMMIT();
    };

    // ---- stage Q tile in stage-0 K buffer via cp.async ----
#pragma unroll
    for (int l = 0; l < 8; ++l) {
        const int idx = tid + l * 128;
        const int r = idx >> 4, c = idx & 15;
        CP_ASYNC16(sb + ATT_K + r * QK_STR + c * 16,
                   Q16 + qkBase + (size_t)(qt * 64 + r) * D_ + c * 8);
    }
    CP_COMMIT();
    CP_WAIT(0);
    __syncthreads();

    // ---- preload Q fragments ----
    const uint32_t aOff = (uint32_t)((wq * 16 + (lane & 15)) * QK_STR +
                                     (lane >> 4) * 16);
    uint32_t qf[8][4];
#pragma unroll
    for (int kc = 0; kc < 8; ++kc)
        ldsm4(qf[kc][0], qf[kc][1], qf[kc][2], qf[kc][3],
              sb + ATT_K + aOff + kc * 32);
    __syncthreads();   // Q extracted; stage-0 K may be overwritten

    const uint32_t bOffK = (uint32_t)(((lane & 7) + ((lane >> 4) << 3)) * QK_STR +
                                      ((lane >> 3) & 1) * 16);
    const uint32_t bOffV = (uint32_t)(((lane & 7) + ((lane >> 4) << 3)) * VT_STR +
                                      ((lane >> 3) & 1) * 16);

    float O[16][4];
#pragma unroll
    for (int nt = 0; nt < 16; ++nt)
#pragma unroll
        for (int q = 0; q < 4; ++q) O[nt][q] = 0.0f;
    float m0 = -1e30f, m1 = -1e30f, l0 = 0.0f, l1 = 0.0f;

    const float scale = 0.08838834764831843f;
    const int rl0 = wq * 16 + g;
    const int rl1 = rl0 + 8;

    issue_tile(0, 0);

    for (int kt = 0; kt <= qt; ++kt) {
        // prefetch next tile into the other stage (its last reader synced
        // at the end of iteration kt-1)
        const bool more = (kt + 1 <= qt);
        if (more) issue_tile(kt + 1, (kt + 1) & 1);
        if (more) { CP_WAIT(1); } else { CP_WAIT(0); }
        __syncthreads();

        const uint32_t sK = sb + (kt & 1) * ATT_STAGE + ATT_K;
        const uint32_t sV = sb + (kt & 1) * ATT_STAGE + ATT_V;

        // ---- S = Q16 K16^T (single pass) ----
        float sacc[8][4];
#pragma unroll
        for (int nt = 0; nt < 8; ++nt)
#pragma unroll
            for (int q = 0; q < 4; ++q) sacc[nt][q] = 0.0f;

#pragma unroll
        for (int kc = 0; kc < 8; ++kc) {
            uint32_t kf[8][2];
#pragma unroll
            for (int p = 0; p < 4; ++p)
                ldsm4(kf[2 * p][0], kf[2 * p][1], kf[2 * p + 1][0], kf[2 * p + 1][1],
                      sK + p * 16 * QK_STR + bOffK + kc * 32);
#pragma unroll
            for (int nt = 0; nt < 8; ++nt)
                mma_f16(sacc[nt], qf[kc], kf[nt]);
        }

        // ---- scale + causal mask + online softmax ----
        const bool diag = (kt == qt);
        float rm0 = -1e30f, rm1 = -1e30f;
#pragma unroll
        for (int nt = 0; nt < 8; ++nt) {
            const int cl0 = nt * 8 + 2 * t;
            float s0v = sacc[nt][0] * scale;
            float s1v = sacc[nt][1] * scale;
            float s2v = sacc[nt][2] * scale;
            float s3v = sacc[nt][3] * scale;
            if (diag) {
                if (cl0 > rl0)     s0v = -1e30f;
                if (cl0 + 1 > rl0) s1v = -1e30f;
                if (cl0 > rl1)     s2v = -1e30f;
                if (cl0 + 1 > rl1) s3v = -1e30f;
            }
            sacc[nt][0] = s0v; sacc[nt][1] = s1v;
            sacc[nt][2] = s2v; sacc[nt][3] = s3v;
            rm0 = fmaxf(rm0, fmaxf(s0v, s1v));
            rm1 = fmaxf(rm1, fmaxf(s2v, s3v));
        }
        rm0 = fmaxf(rm0, __shfl_xor_sync(0xffffffffu, rm0, 1));
        rm0 = fmaxf(rm0, __shfl_xor_sync(0xffffffffu, rm0, 2));
        rm1 = fmaxf(rm1, __shfl_xor_sync(0xffffffffu, rm1, 1));
        rm1 = fmaxf(rm1, __shfl_xor_sync(0xffffffffu, rm1, 2));

        const float mn0 = fmaxf(m0, rm0), mn1 = fmaxf(m1, rm1);
        const float a0 = __expf(m0 - mn0), a1 = __expf(m1 - mn1);
        m0 = mn0; m1 = mn1;

        float rs0 = 0.0f, rs1 = 0.0f;
#pragma unroll
        for (int nt = 0; nt < 8; ++nt) {
            const float p0 = __expf(sacc[nt][0] - mn0);
            const float p1 = __expf(sacc[nt][1] - mn0);
            const float p2 = __expf(sacc[nt][2] - mn1);
            const float p3 = __expf(sacc[nt][3] - mn1);
            sacc[nt][0] = p0; sacc[nt][1] = p1;
            sacc[nt][2] = p2; sacc[nt][3] = p3;
            rs0 += p0 + p1;
            rs1 += p2 + p3;
        }
        rs0 += __shfl_xor_sync(0xffffffffu, rs0, 1);
        rs0 += __shfl_xor_sync(0xffffffffu, rs0, 2);
        rs1 += __shfl_xor_sync(0xffffffffu, rs1, 1);
        rs1 += __shfl_xor_sync(0xffffffffu, rs1, 2);
        l0 = l0 * a0 + rs0;
        l1 = l1 * a1 + rs1;

#pragma unroll
        for (int nt = 0; nt < 16; ++nt) {
            O[nt][0] *= a0; O[nt][1] *= a0;
            O[nt][2] *= a1; O[nt][3] *= a1;
        }

        // ---- pack P into single-fp16 A fragments ----
        uint32_t pf[4][4];
#pragma unroll
        for (int kc = 0; kc < 4; ++kc) {
            const int n0 = 2 * kc, n1 = 2 * kc + 1;
            pf[kc][0] = pack_h2(sacc[n0][0], sacc[n0][1]);
            pf[kc][1] = pack_h2(sacc[n0][2], sacc[n0][3]);
            pf[kc][2] = pack_h2(sacc[n1][0], sacc[n1][1]);
            pf[kc][3] = pack_h2(sacc[n1][2], sacc[n1][3]);
        }

        // ---- O += P16 V16 (kc outer) ----
#pragma unroll
        for (int kc = 0; kc < 4; ++kc) {
#pragma unroll
            for (int p = 0; p < 8; ++p) {
                uint32_t vh[2][2];
                ldsm4(vh[0][0], vh[0][1], vh[1][0], vh[1][1],
                      sV + p * 16 * VT_STR + bOffV + kc * 32);
                mma_f16(O[2 * p],     pf[kc], vh[0]);
                mma_f16(O[2 * p + 1], pf[kc], vh[1]);
            }
        }
        __syncthreads();   // readers done before this stage is overwritten
    }

    // ---- epilogue ----
    const int b = bh >> 4, h = bh & 15;
    const float i0 = 1.0f / l0, i1 = 1.0f / l1;
    const int row0 = qt * 64 + wq * 16 + g;
#pragma unroll
    for (int nt = 0; nt < 16; ++nt) {
        const int col = h * D_ + nt * 8 + 2 * t;
        const size_t o0 = (size_t)(b * S_ + row0) * E_ + col;
        const size_t o1 = (size_t)(b * S_ + row0 + 8) * E_ + col;
        *reinterpret_cast<uint32_t*>(c16 + o0) = pack_h2(O[nt][0] * i0, O[nt][1] * i0);
        *reinterpret_cast<uint32_t*>(c16 + o1) = pack_h2(O[nt][2] * i1, O[nt][3] * i1);
    }
}

// ---------------------------------------------------------------------------
extern "C" void kernel_launch(void* const* d_in, const int* in_sizes, int n_in,
                              void* d_out, int out_size)
{
    const float* x    = (const float*)d_in[0];
    const float* wqkv = (const float*)d_in[1];
    const float* bqkv = (const float*)d_in[2];
    const float* wout = (const float*)d_in[3];
    const float* bout = (const float*)d_in[4];
    float* out = (float*)d_out;

    float* qkv;
    __half *x16, *wq16, *wo16, *c16;
    __half *Q16, *K16, *Vt16;
    cudaGetSymbolAddress((void**)&qkv, g_qkv);
    cudaGetSymbolAddress((void**)&x16, g_x16);
    cudaGetSymbolAddress((void**)&wq16, g_wq16);
    cudaGetSymbolAddress((void**)&wo16, g_wo16);
    cudaGetSymbolAddress((void**)&c16, g_c16);
    cudaGetSymbolAddress((void**)&Q16, g_Q16);
    cudaGetSymbolAddress((void**)&K16, g_K16);
    cudaGetSymbolAddress((void**)&Vt16, g_Vt16);

    cudaFuncSetAttribute(gemm_hmma_x1,
                         cudaFuncAttributeMaxDynamicSharedMemorySize, GSM_TOTAL);
    cudaFuncSetAttribute(attn_hmma,
                         cudaFuncAttributeMaxDynamicSharedMemorySize, ASM_TOTAL);

    // 0) converts
    {
        int n4;
        n4 = MTOT * E_ / 4;
        to_f16<<<(n4 + 255) / 256, 256>>>(x, x16, n4);
        n4 = N_QKV * E_ / 4;
        to_f16<<<(n4 + 255) / 256, 256>>>(wqkv, wq16, n4);
        n4 = E_ * E_ / 4;
        to_f16<<<(n4 + 255) / 256, 256>>>(wout, wo16, n4);
    }

    // 1) QKV projection
    gemm_hmma_x1<<<dim3(N_QKV / 128, MTOT / 128), 256, GSM_TOTAL>>>(
        x16, wq16, bqkv, qkv, N_QKV, KDIM);

    // 2) rotary + convert Q,K ; transpose V
    qk_rope_cvt<<<(B_ * S_ * H_ * HALF_ + 255) / 256, 256>>>(qkv, Q16, K16);
    v_transpose<<<dim3(S_ / 32, D_ / 32, BH_), dim3(32, 8)>>>(qkv, Vt16);

    // 3) fp16 flash attention -> c16
    attn_hmma<<<dim3(S_ / 64, BH_), 128, ASM_TOTAL>>>(Q16, K16, Vt16, c16);

    // 4) output projection
    gemm_hmma_x1<<<dim3(E_ / 128, MTOT / 128), 256, GSM_TOTAL>>>(
        c16, wo16, bout, out, E_, KDIM);
}

// round 15
// speedup vs baseline: 4.9988x; 1.0569x over previous
#include <cuda_runtime.h>
#include <cuda_fp16.h>
#include <math.h>
#include <stdint.h>

#define B_    2
#define S_    2048
#define E_    2048
#define H_    16
#define D_    128
#define HALF_ 64
#define MTOT  (B_ * S_)          // 4096
#define N_QKV (3 * E_)           // 6144
#define KDIM  E_                 // 2048
#define BH_   (B_ * H_)          // 32

// ---------------- scratch (__device__ globals; allocation-free) -------------
__device__ float g_qkv[(size_t)MTOT * 3 * E_];
__device__ __half g_x16[(size_t)MTOT * E_];
__device__ __half g_wq16[(size_t)N_QKV * E_];
__device__ __half g_wo16[(size_t)E_ * E_];
__device__ __half g_c16[(size_t)MTOT * E_];
__device__ __half g_Q16[(size_t)BH_ * S_ * D_];
__device__ __half g_K16[(size_t)BH_ * S_ * D_];
__device__ __half g_Vt16[(size_t)BH_ * D_ * S_];

// ---------------- helpers ---------------------------------------------------
__device__ __forceinline__ uint32_t smem_u32(const void* p) {
    uint32_t a;
    asm("{ .reg .u64 t; cvta.to.shared.u64 t, %1; cvt.u32.u64 %0, t; }"
        : "=r"(a) : "l"(p));
    return a;
}

#define CP_ASYNC16(sa, gp) \
    asm volatile("cp.async.cg.shared.global [%0], [%1], 16;" :: "r"(sa), "l"(gp))
#define CP_COMMIT() asm volatile("cp.async.commit_group;" ::: "memory")
#define CP_WAIT(n)  asm volatile("cp.async.wait_group %0;" :: "n"(n) : "memory")

__device__ __forceinline__ void ldsm4(uint32_t& r0, uint32_t& r1, uint32_t& r2,
                                      uint32_t& r3, uint32_t addr) {
    asm volatile("ldmatrix.sync.aligned.m8n8.x4.shared.b16 {%0,%1,%2,%3}, [%4];"
                 : "=r"(r0), "=r"(r1), "=r"(r2), "=r"(r3) : "r"(addr));
}

__device__ __forceinline__ void mma_f16(float* c, const uint32_t* a,
                                        const uint32_t* b) {
    asm volatile(
        "mma.sync.aligned.m16n8k16.row.col.f32.f16.f16.f32 "
        "{%0,%1,%2,%3}, {%4,%5,%6,%7}, {%8,%9}, {%0,%1,%2,%3};"
        : "+f"(c[0]), "+f"(c[1]), "+f"(c[2]), "+f"(c[3])
        : "r"(a[0]), "r"(a[1]), "r"(a[2]), "r"(a[3]), "r"(b[0]), "r"(b[1]));
}

__device__ __forceinline__ uint32_t pack_h2(float f0, float f1) {
    __half2 p = __floats2half2_rn(f0, f1);
    return *reinterpret_cast<uint32_t*>(&p);
}

// ---------------------------------------------------------------------------
// fp32 -> single fp16
// ---------------------------------------------------------------------------
__global__ void __launch_bounds__(256) to_f16(
    const float* __restrict__ in, __half* __restrict__ o16, int n4)
{
    const int i = blockIdx.x * blockDim.x + threadIdx.x;
    if (i >= n4) return;
    const float4 v = reinterpret_cast<const float4*>(in)[i];
    uint2 p;
    p.x = pack_h2(v.x, v.y);
    p.y = pack_h2(v.z, v.w);
    reinterpret_cast<uint2*>(o16)[i] = p;
}

// ---------------------------------------------------------------------------
// HMMA fp16 single-pass GEMM:  C[M,N] = A16[M,K] @ W16[N,K]^T + bias
// 128x128 block, 4 warps (128 thr), warp tile 64x64 (2x2), BK=32,
// 4-stage cp.async pipeline, 2 CTAs/SM.
// ---------------------------------------------------------------------------
#define RSTRIDE   80
#define TILE_B    (128 * RSTRIDE)
#define STAGE_B   (2 * TILE_B)
#define NSTAGE    4
#define GSM_TOTAL (NSTAGE * STAGE_B)       // 81920

__global__ void __launch_bounds__(128, 2) gemm_hmma_x1(
    const __half* __restrict__ A16, const __half* __restrict__ W16,
    const float* __restrict__ bias, float* __restrict__ C, int N, int K)
{
    extern __shared__ char smem[];
    const uint32_t sb = smem_u32(smem);

    const int tid  = threadIdx.x;
    const int wid  = tid >> 5;
    const int lane = tid & 31;
    const int wm   = wid & 1;              // m offset 64*wm
    const int wn   = wid >> 1;             // n offset 64*wn
    const int rowBlk = blockIdx.y * 128;
    const int colBlk = blockIdx.x * 128;

    const int gr0 = tid >> 2;              // 0..31
    const int gc  = (tid & 3) * 16;        // 16B column offset

    auto issue_stage = [&](int k0, int stg) {
        const uint32_t s0 = sb + stg * STAGE_B;
#pragma unroll
        for (int l = 0; l < 4; ++l) {
            const int r = gr0 + l * 32;
            const uint32_t so = r * RSTRIDE + gc;
            CP_ASYNC16(s0 + so,
                       A16 + (size_t)(rowBlk + r) * K + k0 + (gc >> 1));
            CP_ASYNC16(s0 + TILE_B + so,
                       W16 + (size_t)(colBlk + r) * K + k0 + (gc >> 1));
        }
        CP_COMMIT();
    };

    float acc[4][8][4];
#pragma unroll
    for (int i = 0; i < 4; ++i)
#pragma unroll
        for (int j = 0; j < 8; ++j)
#pragma unroll
            for (int q = 0; q < 4; ++q) acc[i][j][q] = 0.0f;

    const uint32_t aOff = (uint32_t)((wm * 64 + (lane & 15)) * RSTRIDE +
                                     (lane >> 4) * 16);
    const uint32_t bOff = (uint32_t)((wn * 64 + (lane & 7) + ((lane >> 4) << 3)) * RSTRIDE +
                                     ((lane >> 3) & 1) * 16);

    const int NCH = K / 32;
    issue_stage(0, 0);
    issue_stage(32, 1);
    issue_stage(64, 2);

    for (int c = 0; c < NCH; ++c) {
        CP_WAIT(2);
        __syncthreads();
        if (c + 3 < NCH) issue_stage((c + 3) * 32, (c + 3) & 3);
        else             CP_COMMIT();

        const uint32_t s0 = sb + (c & 3) * STAGE_B;
        const uint32_t sA = s0 + aOff;
        const uint32_t sW = s0 + TILE_B + bOff;

#pragma unroll
        for (int ks = 0; ks < 2; ++ks) {
            const uint32_t ko = ks * 32;
            uint32_t a[4][4], w[8][2];
#pragma unroll
            for (int mt = 0; mt < 4; ++mt)
                ldsm4(a[mt][0], a[mt][1], a[mt][2], a[mt][3],
                      sA + mt * 16 * RSTRIDE + ko);
#pragma unroll
            for (int p = 0; p < 4; ++p)
                ldsm4(w[2 * p][0], w[2 * p][1], w[2 * p + 1][0], w[2 * p + 1][1],
                      sW + p * 16 * RSTRIDE + ko);
#pragma unroll
            for (int mt = 0; mt < 4; ++mt)
#pragma unroll
                for (int nt = 0; nt < 8; ++nt)
                    mma_f16(acc[mt][nt], a[mt], w[nt]);
        }
    }
    __syncthreads();

    const int g = lane >> 2;
    const int t = lane & 3;
#pragma unroll
    for (int mt = 0; mt < 4; ++mt) {
        const int row0 = rowBlk + wm * 64 + mt * 16 + g;
#pragma unroll
        for (int nt = 0; nt < 8; ++nt) {
            const int col = colBlk + wn * 64 + nt * 8 + 2 * t;
            const float b0 = bias[col], b1 = bias[col + 1];
            float2 v0 = make_float2(acc[mt][nt][0] + b0, acc[mt][nt][1] + b1);
            float2 v1 = make_float2(acc[mt][nt][2] + b0, acc[mt][nt][3] + b1);
            *reinterpret_cast<float2*>(C + (size_t)row0 * N + col) = v0;
            *reinterpret_cast<float2*>(C + (size_t)(row0 + 8) * N + col) = v1;
        }
    }
}

// ---------------------------------------------------------------------------
// Fused rotary + convert: qkv[B,S,3,H,D] fp32 -> Q16, K16 [BH,S,D]
// ---------------------------------------------------------------------------
__global__ void __launch_bounds__(256) qk_rope_cvt(
    const float* __restrict__ qkv,
    __half* __restrict__ Q16, __half* __restrict__ K16)
{
    const int idx = blockIdx.x * blockDim.x + threadIdx.x;
    const int total = B_ * S_ * H_ * HALF_;
    if (idx >= total) return;

    const int dh = idx & (HALF_ - 1);
    const int h  = (idx >> 6) & (H_ - 1);
    const int s  = (idx >> 10) & (S_ - 1);
    const int b  = idx >> 21;

    const double inv = exp(-(double)dh * (log(10000.0) / 64.0));
    const float  f   = (float)((double)s * inv);
    float c, sn;
    sincosf(f, &sn, &c);

    const size_t obase = ((size_t)(b * H_ + h) * S_ + s) * D_;

    {
        const size_t ib = (((size_t)(b * S_ + s) * 3 + 0) * H_ + h) * (size_t)D_;
        const float x1 = qkv[ib + dh], x2 = qkv[ib + dh + HALF_];
        Q16[obase + dh]         = __float2half(x1 * c - x2 * sn);
        Q16[obase + dh + HALF_] = __float2half(x2 * c + x1 * sn);
    }
    {
        const size_t ib = (((size_t)(b * S_ + s) * 3 + 1) * H_ + h) * (size_t)D_;
        const float x1 = qkv[ib + dh], x2 = qkv[ib + dh + HALF_];
        K16[obase + dh]         = __float2half(x1 * c - x2 * sn);
        K16[obase + dh + HALF_] = __float2half(x2 * c + x1 * sn);
    }
}

// ---------------------------------------------------------------------------
// V transpose: qkv comp2 [B,S,H,D] -> Vt16 [BH, D, S]
// ---------------------------------------------------------------------------
__global__ void __launch_bounds__(256) v_transpose(
    const float* __restrict__ qkv, __half* __restrict__ Vt16)
{
    __shared__ float tile[32][33];
    const int tx = threadIdx.x;
    const int ty = threadIdx.y;
    const int s0 = blockIdx.x * 32;
    const int d0 = blockIdx.y * 32;
    const int bh = blockIdx.z;
    const int b  = bh >> 4;
    const int h  = bh & 15;

#pragma unroll
    for (int i = 0; i < 4; ++i) {
        const int s = s0 + ty + i * 8;
        const int d = d0 + tx;
        tile[ty + i * 8][tx] =
            qkv[(((size_t)(b * S_ + s) * 3 + 2) * H_ + h) * (size_t)D_ + d];
    }
    __syncthreads();

#pragma unroll
    for (int i = 0; i < 4; ++i) {
        const int d = d0 + ty + i * 8;
        const int s = s0 + tx;
        Vt16[((size_t)bh * D_ + d) * S_ + s] = __float2half(tile[tx][ty + i * 8]);
    }
}

// ---------------------------------------------------------------------------
// HMMA fp16 flash attention (causal), single-pass K, 2-stage KV pipeline,
// 3 CTAs/SM — unchanged from R13.
// ---------------------------------------------------------------------------
#define QK_STR 272
#define VT_STR 144
#define ATT_K   0
#define ATT_V   (64 * QK_STR)                 // 17408
#define ATT_STAGE (64 * QK_STR + 128 * VT_STR) // 35840
#define ASM_TOTAL (2 * ATT_STAGE)             // 71680

__global__ void __launch_bounds__(128, 3) attn_hmma(
    const __half* __restrict__ Q16, const __half* __restrict__ K16,
    const __half* __restrict__ Vt16,
    __half* __restrict__ c16)
{
    extern __shared__ char smem[];
    const uint32_t sb = smem_u32(smem);

    const int qt  = gridDim.x - 1 - blockIdx.x;   // long blocks first
    const int bh  = blockIdx.y;
    const int tid = threadIdx.x;
    const int wq  = tid >> 5;
    const int lane = tid & 31;
    const int g   = lane >> 2;
    const int t   = lane & 3;

    const size_t qkBase = (size_t)bh * S_ * D_;
    const size_t vBase  = (size_t)bh * D_ * S_;

    auto issue_tile = [&](int kt, int stg) {
        const uint32_t k0 = sb + stg * ATT_STAGE + ATT_K;
        const uint32_t v0 = sb + stg * ATT_STAGE + ATT_V;
#pragma unroll
        for (int l = 0; l < 8; ++l) {
            const int idx = tid + l * 128;
            {
                const int r = idx >> 4, c = idx & 15;
                CP_ASYNC16(k0 + r * QK_STR + c * 16,
                           K16 + qkBase + (size_t)(kt * 64 + r) * D_ + c * 8);
            }
            {
                const int r = idx >> 3, c = idx & 7;
                CP_ASYNC16(v0 + r * VT_STR + c * 16,
                           Vt16 + vBase + (size_t)r * S_ + kt * 64 + c * 8);
            }
        }
        CP_COMMIT();
    };

    // ---- stage Q tile in stage-0 K buffer via cp.async ----
#pragma unroll
    for (int l = 0; l < 8; ++l) {
        const int idx = tid + l * 128;
        const int r = idx >> 4, c = idx & 15;
        CP_ASYNC16(sb + ATT_K + r * QK_STR + c * 16,
                   Q16 + qkBase + (size_t)(qt * 64 + r) * D_ + c * 8);
    }
    CP_COMMIT();
    CP_WAIT(0);
    __syncthreads();

    // ---- preload Q fragments ----
    const uint32_t aOff = (uint32_t)((wq * 16 + (lane & 15)) * QK_STR +
                                     (lane >> 4) * 16);
    uint32_t qf[8][4];
#pragma unroll
    for (int kc = 0; kc < 8; ++kc)
        ldsm4(qf[kc][0], qf[kc][1], qf[kc][2], qf[kc][3],
              sb + ATT_K + aOff + kc * 32);
    __syncthreads();   // Q extracted; stage-0 K may be overwritten

    const uint32_t bOffK = (uint32_t)(((lane & 7) + ((lane >> 4) << 3)) * QK_STR +
                                      ((lane >> 3) & 1) * 16);
    const uint32_t bOffV = (uint32_t)(((lane & 7) + ((lane >> 4) << 3)) * VT_STR +
                                      ((lane >> 3) & 1) * 16);

    float O[16][4];
#pragma unroll
    for (int nt = 0; nt < 16; ++nt)
#pragma unroll
        for (int q = 0; q < 4; ++q) O[nt][q] = 0.0f;
    float m0 = -1e30f, m1 = -1e30f, l0 = 0.0f, l1 = 0.0f;

    const float scale = 0.08838834764831843f;
    const int rl0 = wq * 16 + g;
    const int rl1 = rl0 + 8;

    issue_tile(0, 0);

    for (int kt = 0; kt <= qt; ++kt) {
        const bool more = (kt + 1 <= qt);
        if (more) issue_tile(kt + 1, (kt + 1) & 1);
        if (more) { CP_WAIT(1); } else { CP_WAIT(0); }
        __syncthreads();

        const uint32_t sK = sb + (kt & 1) * ATT_STAGE + ATT_K;
        const uint32_t sV = sb + (kt & 1) * ATT_STAGE + ATT_V;

        // ---- S = Q16 K16^T ----
        float sacc[8][4];
#pragma unroll
        for (int nt = 0; nt < 8; ++nt)
#pragma unroll
            for (int q = 0; q < 4; ++q) sacc[nt][q] = 0.0f;

#pragma unroll
        for (int kc = 0; kc < 8; ++kc) {
            uint32_t kf[8][2];
#pragma unroll
            for (int p = 0; p < 4; ++p)
                ldsm4(kf[2 * p][0], kf[2 * p][1], kf[2 * p + 1][0], kf[2 * p + 1][1],
                      sK + p * 16 * QK_STR + bOffK + kc * 32);
#pragma unroll
            for (int nt = 0; nt < 8; ++nt)
                mma_f16(sacc[nt], qf[kc], kf[nt]);
        }

        // ---- scale + causal mask + online softmax ----
        const bool diag = (kt == qt);
        float rm0 = -1e30f, rm1 = -1e30f;
#pragma unroll
        for (int nt = 0; nt < 8; ++nt) {
            const int cl0 = nt * 8 + 2 * t;
            float s0v = sacc[nt][0] * scale;
            float s1v = sacc[nt][1] * scale;
            float s2v = sacc[nt][2] * scale;
            float s3v = sacc[nt][3] * scale;
            if (diag) {
                if (cl0 > rl0)     s0v = -1e30f;
                if (cl0 + 1 > rl0) s1v = -1e30f;
                if (cl0 > rl1)     s2v = -1e30f;
                if (cl0 + 1 > rl1) s3v = -1e30f;
            }
            sacc[nt][0] = s0v; sacc[nt][1] = s1v;
            sacc[nt][2] = s2v; sacc[nt][3] = s3v;
            rm0 = fmaxf(rm0, fmaxf(s0v, s1v));
            rm1 = fmaxf(rm1, fmaxf(s2v, s3v));
        }
        rm0 = fmaxf(rm0, __shfl_xor_sync(0xffffffffu, rm0, 1));
        rm0 = fmaxf(rm0, __shfl_xor_sync(0xffffffffu, rm0, 2));
        rm1 = fmaxf(rm1, __shfl_xor_sync(0xffffffffu, rm1, 1));
        rm1 = fmaxf(rm1, __shfl_xor_sync(0xffffffffu, rm1, 2));

        const float mn0 = fmaxf(m0, rm0), mn1 = fmaxf(m1, rm1);
        const float a0 = __expf(m0 - mn0), a1 = __expf(m1 - mn1);
        m0 = mn0; m1 = mn1;

        float rs0 = 0.0f, rs1 = 0.0f;
#pragma unroll
        for (int nt = 0; nt < 8; ++nt) {
            const float p0 = __expf(sacc[nt][0] - mn0);
            const float p1 = __expf(sacc[nt][1] - mn0);
            const float p2 = __expf(sacc[nt][2] - mn1);
            const float p3 = __expf(sacc[nt][3] - mn1);
            sacc[nt][0] = p0; sacc[nt][1] = p1;
            sacc[nt][2] = p2; sacc[nt][3] = p3;
            rs0 += p0 + p1;
            rs1 += p2 + p3;
        }
        rs0 += __shfl_xor_sync(0xffffffffu, rs0, 1);
        rs0 += __shfl_xor_sync(0xffffffffu, rs0, 2);
        rs1 += __shfl_xor_sync(0xffffffffu, rs1, 1);
        rs1 += __shfl_xor_sync(0xffffffffu, rs1, 2);
        l0 = l0 * a0 + rs0;
        l1 = l1 * a1 + rs1;

#pragma unroll
        for (int nt = 0; nt < 16; ++nt) {
            O[nt][0] *= a0; O[nt][1] *= a0;
            O[nt][2] *= a1; O[nt][3] *= a1;
        }

        // ---- pack P into single-fp16 A fragments ----
        uint32_t pf[4][4];
#pragma unroll
        for (int kc = 0; kc < 4; ++kc) {
            const int n0 = 2 * kc, n1 = 2 * kc + 1;
            pf[kc][0] = pack_h2(sacc[n0][0], sacc[n0][1]);
            pf[kc][1] = pack_h2(sacc[n0][2], sacc[n0][3]);
            pf[kc][2] = pack_h2(sacc[n1][0], sacc[n1][1]);
            pf[kc][3] = pack_h2(sacc[n1][2], sacc[n1][3]);
        }

        // ---- O += P16 V16 (kc outer) ----
#pragma unroll
        for (int kc = 0; kc < 4; ++kc) {
#pragma unroll
            for (int p = 0; p < 8; ++p) {
                uint32_t vh[2][2];
                ldsm4(vh[0][0], vh[0][1], vh[1][0], vh[1][1],
                      sV + p * 16 * VT_STR + bOffV + kc * 32);
                mma_f16(O[2 * p],     pf[kc], vh[0]);
                mma_f16(O[2 * p + 1], pf[kc], vh[1]);
            }
        }
        __syncthreads();
    }

    // ---- epilogue ----
    const int b = bh >> 4, h = bh & 15;
    const float i0 = 1.0f / l0, i1 = 1.0f / l1;
    const int row0 = qt * 64 + wq * 16 + g;
#pragma unroll
    for (int nt = 0; nt < 16; ++nt) {
        const int col = h * D_ + nt * 8 + 2 * t;
        const size_t o0 = (size_t)(b * S_ + row0) * E_ + col;
        const size_t o1 = (size_t)(b * S_ + row0 + 8) * E_ + col;
        *reinterpret_cast<uint32_t*>(c16 + o0) = pack_h2(O[nt][0] * i0, O[nt][1] * i0);
        *reinterpret_cast<uint32_t*>(c16 + o1) = pack_h2(O[nt][2] * i1, O[nt][3] * i1);
    }
}

// ---------------------------------------------------------------------------
extern "C" void kernel_launch(void* const* d_in, const int* in_sizes, int n_in,
                              void* d_out, int out_size)
{
    const float* x    = (const float*)d_in[0];
    const float* wqkv = (const float*)d_in[1];
    const float* bqkv = (const float*)d_in[2];
    const float* wout = (const float*)d_in[3];
    const float* bout = (const float*)d_in[4];
    float* out = (float*)d_out;

    float* qkv;
    __half *x16, *wq16, *wo16, *c16;
    __half *Q16, *K16, *Vt16;
    cudaGetSymbolAddress((void**)&qkv, g_qkv);
    cudaGetSymbolAddress((void**)&x16, g_x16);
    cudaGetSymbolAddress((void**)&wq16, g_wq16);
    cudaGetSymbolAddress((void**)&wo16, g_wo16);
    cudaGetSymbolAddress((void**)&c16, g_c16);
    cudaGetSymbolAddress((void**)&Q16, g_Q16);
    cudaGetSymbolAddress((void**)&K16, g_K16);
    cudaGetSymbolAddress((void**)&Vt16, g_Vt16);

    cudaFuncSetAttribute(gemm_hmma_x1,
                         cudaFuncAttributeMaxDynamicSharedMemorySize, GSM_TOTAL);
    cudaFuncSetAttribute(attn_hmma,
                         cudaFuncAttributeMaxDynamicSharedMemorySize, ASM_TOTAL);

    // 0) converts
    {
        int n4;
        n4 = MTOT * E_ / 4;
        to_f16<<<(n4 + 255) / 256, 256>>>(x, x16, n4);
        n4 = N_QKV * E_ / 4;
        to_f16<<<(n4 + 255) / 256, 256>>>(wqkv, wq16, n4);
        n4 = E_ * E_ / 4;
        to_f16<<<(n4 + 255) / 256, 256>>>(wout, wo16, n4);
    }

    // 1) QKV projection
    gemm_hmma_x1<<<dim3(N_QKV / 128, MTOT / 128), 128, GSM_TOTAL>>>(
        x16, wq16, bqkv, qkv, N_QKV, KDIM);

    // 2) rotary + convert Q,K ; transpose V
    qk_rope_cvt<<<(B_ * S_ * H_ * HALF_ + 255) / 256, 256>>>(qkv, Q16, K16);
    v_transpose<<<dim3(S_ / 32, D_ / 32, BH_), dim3(32, 8)>>>(qkv, Vt16);

    // 3) fp16 flash attention -> c16
    attn_hmma<<<dim3(S_ / 64, BH_), 128, ASM_TOTAL>>>(Q16, K16, Vt16, c16);

    // 4) output projection
    gemm_hmma_x1<<<dim3(E_ / 128, MTOT / 128), 128, GSM_TOTAL>>>(
        c16, wo16, bout, out, E_, KDIM);
}